// round 10
// baseline (speedup 1.0000x reference)
#include <cuda_runtime.h>
#include <cuda_fp16.h>
#include <cstdint>
#include <cstddef>

#define D_    1024
#define BATCH 32
#define SEQ   128
#define NQ_   256
#define HID   4096
#define NHEAD 16
#define NEGV  (-10000.0f)
#define NLAYER 6
#define VOCAB 18

// ---------------- portable PTX helpers (compute_103-safe) -------------------
__device__ __forceinline__ uint32_t smem_u32(const void* p) {
    uint32_t a;
    asm("{ .reg .u64 t; cvta.to.shared.u64 t, %1; cvt.u32.u64 %0, t; }"
        : "=r"(a) : "l"(p));
    return a;
}

#define CP16(s, g) \
    asm volatile("cp.async.cg.shared.global [%0], [%1], 16;" :: "r"(s), "l"(g))
#define CP_COMMIT() asm volatile("cp.async.commit_group;" ::: "memory")
#define CP_WAIT1()  asm volatile("cp.async.wait_group 1;" ::: "memory")
#define CP_WAIT0()  asm volatile("cp.async.wait_group 0;" ::: "memory")

#define LDSM_X4(r0, r1, r2, r3, addr) \
    asm volatile("ldmatrix.sync.aligned.m8n8.x4.shared.b16 {%0,%1,%2,%3}, [%4];" \
                 : "=r"(r0), "=r"(r1), "=r"(r2), "=r"(r3) : "r"(addr))

#define MMA16816(c, a0, a1, a2, a3, b0, b1) \
    asm volatile("mma.sync.aligned.m16n8k16.row.col.f32.f16.f16.f32 " \
                 "{%0,%1,%2,%3}, {%4,%5,%6,%7}, {%8,%9}, {%0,%1,%2,%3};" \
                 : "+f"((c)[0]), "+f"((c)[1]), "+f"((c)[2]), "+f"((c)[3]) \
                 : "r"(a0), "r"(a1), "r"(a2), "r"(a3), "r"(b0), "r"(b1))

__device__ __forceinline__ uint32_t cvt2h(float a, float b) {
    __half2 t = __floats2half2_rn(a, b);
    return *(uint32_t*)&t;
}
__device__ __forceinline__ void split2h(float a, float b, uint32_t& h, uint32_t& l) {
    __half ha = __float2half_rn(a);
    __half hb = __float2half_rn(b);
    __half la = __float2half_rn(a - __half2float(ha));
    __half lb = __float2half_rn(b - __half2float(hb));
    __half2 hh; hh.x = ha; hh.y = hb;
    __half2 ll; ll.x = la; ll.y = lb;
    h = *(uint32_t*)&hh;
    l = *(uint32_t*)&ll;
}

// ---------------- scratch (device globals; allocation-free) ----------------
#define WPL 25165824ULL
#define OFF_MOD 0ULL
#define OFF_SAQ 6291456ULL
#define OFF_SAP 9437184ULL
#define OFF_CAQ 10485760ULL
#define OFF_CAK 11534336ULL
#define OFF_CAV 12582912ULL
#define OFF_CAP 13631488ULL
#define OFF_AL  14680064ULL
#define OFF_FC1 16777216ULL
#define OFF_FC2 20971520ULL

__device__ __half g_wth[NLAYER * WPL];
__device__ __half g_wtl[NLAYER * WPL];
__device__ __half g_sc16 [BATCH*SEQ*D_];
__device__ __half g_q16  [BATCH*NQ_*D_];
__device__ __half g_ao16 [BATCH*NQ_*D_];
__device__ __half g_kv16 [2*BATCH*SEQ*D_];
__device__ __half g_cat16[BATCH*NQ_*2*D_];
__device__ __half g_h16  [BATCH*NQ_*HID];

__device__ float g_mod[NLAYER*BATCH*SEQ*6*D_];
__device__ float g_q  [BATCH*NQ_*D_];
__device__ float g_qkv[BATCH*NQ_*3*D_];
__device__ float g_qp [BATCH*NQ_*D_];
__device__ float g_kvp[2*BATCH*SEQ*D_];
__device__ float g_po [BATCH*NQ_*D_];
__device__ float g_q2 [BATCH*NQ_*D_];
__device__ float g_alf[BATCH*NQ_*D_];

// ---------------- weight transpose + fp16 hi/lo split (z-batched) ----------
__global__ __launch_bounds__(256) void transpose_split(const float* __restrict__ W,
                                                       __half* __restrict__ oh,
                                                       __half* __restrict__ ol,
                                                       int K, int N,
                                                       size_t ils, size_t ols)
{
    __shared__ float t[32][33];
    const int z = blockIdx.z;
    W  += (size_t)z * ils;
    oh += (size_t)z * ols;
    ol += (size_t)z * ols;
    const int n0 = blockIdx.x * 32, k0 = blockIdx.y * 32;
    const int tx = threadIdx.x & 31, ty = threadIdx.x >> 5;
#pragma unroll
    for (int r = 0; r < 4; r++)
        t[ty + 8*r][tx] = W[(size_t)(k0 + ty + 8*r) * N + n0 + tx];
    __syncthreads();
#pragma unroll
    for (int s = 0; s < 2; s++) {
        int id = threadIdx.x + s * 256;
        int n  = id >> 4;
        int kp = (id & 15) * 2;
        uint32_t h, l;
        split2h(t[kp][n], t[kp + 1][n], h, l);
        size_t o = (size_t)(n0 + n) * K + k0 + kp;
        *(uint32_t*)(oh + o) = h;
        *(uint32_t*)(ol + o) = l;
    }
}

__global__ void silu_h(const float* __restrict__ x, __half* __restrict__ oh, int n4)
{
    int i = blockIdx.x * blockDim.x + threadIdx.x;
    if (i >= n4) return;
    float4 v = ((const float4*)x)[i];
    float f[4] = {v.x, v.y, v.z, v.w};
#pragma unroll
    for (int j = 0; j < 4; j++) f[j] = f[j] / (1.f + expf(-f[j]));
    uint2 hh; hh.x = cvt2h(f[0], f[1]); hh.y = cvt2h(f[2], f[3]);
    *(uint2*)(oh + 4*(size_t)i) = hh;
}

__global__ void copy_h(const float* __restrict__ x, float* __restrict__ o,
                       __half* __restrict__ oh, int n4)
{
    int i = blockIdx.x * blockDim.x + threadIdx.x;
    if (i >= n4) return;
    float4 v = ((const float4*)x)[i];
    ((float4*)o)[i] = v;
    uint2 hh; hh.x = cvt2h(v.x, v.y); hh.y = cvt2h(v.z, v.w);
    *(uint2*)(oh + 4*(size_t)i) = hh;
}

// ---------------- persistent HMMA GEMM (2-term fp16 split, BK=64) -----------
// OUT: 0 = fp32 only, 1 = fp32 + fp16, 2 = fp16 only
// Persistent tiles: grid = min(ntiles, 296); inter-tile chunk-0 prefetch.
#define AS 72
#define TILE_B (128 * AS * 2)       // 18432 B
#define BUF_B  (3 * TILE_B)         // 55296 B (A, Bh, Bl)
#define GEMM_SMEM (2 * BUF_B)       // 110592 B

template<int ACT, int OUT>
__global__ __launch_bounds__(256) void gemm_mma(const __half* __restrict__ A,
                                                const __half* __restrict__ Bh,
                                                const __half* __restrict__ Bl,
                                                const float* __restrict__ bias,
                                                float* __restrict__ C,
                                                __half* __restrict__ Ch,
                                                int M, int N, int K, int cn,
                                                size_t azs, size_t bzs,
                                                size_t biaszs, size_t czs,
                                                int ntiles)
{
    extern __shared__ __align__(128) char dynsm[];
    const uint32_t sb0 = smem_u32(dynsm);
    const int nx = N >> 7, ny = M >> 7;

    const int tid  = threadIdx.x;
    const int lane = tid & 31;
    const int wid  = tid >> 5;
    const int wm   = wid & 3;
    const int wn   = wid >> 2;

    const int lr  = tid >> 3;
    const int lcs = (tid & 7) * 8;
    const uint32_t so = (uint32_t)(lr * AS + lcs) * 2;
    const uint32_t SOSTEP = 32u * AS * 2;
    const size_t rstep = (size_t)32 * K;
    const int nch = K >> 6;       // always even for our Ks (1024/2048/4096)

    int t = blockIdx.x;           // grid.x = min(ntiles, 296) -> t < ntiles
    int bx = t % nx, rr = t / nx, by = rr % ny, bz = rr / ny;
    const __half* gA  = A  + (size_t)bz * azs + (size_t)(by * 128 + lr) * K + lcs;
    const __half* gBh = Bh + (size_t)bz * bzs + (size_t)(bx * 128 + lr) * K + lcs;
    const __half* gBl = Bl + (size_t)bz * bzs + (size_t)(bx * 128 + lr) * K + lcs;

    // prefetch chunk 0 of first tile
#pragma unroll
    for (int tt = 0; tt < 4; tt++) {
        CP16(sb0 + 0*TILE_B + so + tt*SOSTEP, gA  + tt*rstep);
        CP16(sb0 + 1*TILE_B + so + tt*SOSTEP, gBh + tt*rstep);
        CP16(sb0 + 2*TILE_B + so + tt*SOSTEP, gBl + tt*rstep);
    }
    CP_COMMIT();

    const uint32_t a_row = (uint32_t)(wm * 32 + (lane & 15));
    const uint32_t a_kb  = (uint32_t)((lane >> 4) * 16);
    const uint32_t b_row = (uint32_t)(wn * 64 + (lane & 7) + ((lane >> 4) << 3));
    const uint32_t b_kb  = (uint32_t)(((lane >> 3) & 1) * 16);

    while (true) {
        float acc[2][8][4];
#pragma unroll
        for (int i = 0; i < 2; i++)
#pragma unroll
            for (int n = 0; n < 8; n++)
#pragma unroll
                for (int j = 0; j < 4; j++) acc[i][n][j] = 0.f;

        const int tn = t + gridDim.x;
        const bool has_next = (tn < ntiles);
        int nbx = 0, nby = 0, nbz = 0;
        const __half *nA = nullptr, *nBh = nullptr, *nBl = nullptr;
        if (has_next) {
            nbx = tn % nx; int r2 = tn / nx; nby = r2 % ny; nbz = r2 / ny;
            nA  = A  + (size_t)nbz * azs + (size_t)(nby * 128 + lr) * K + lcs;
            nBh = Bh + (size_t)nbz * bzs + (size_t)(nbx * 128 + lr) * K + lcs;
            nBl = Bl + (size_t)nbz * bzs + (size_t)(nbx * 128 + lr) * K + lcs;
        }

        for (int c = 0; c < nch; c++) {
            if (c + 1 < nch) {
                const int k1 = (c + 1) << 6;
                uint32_t sb = sb0 + ((c + 1) & 1) * BUF_B;
#pragma unroll
                for (int tt = 0; tt < 4; tt++) {
                    CP16(sb + 0*TILE_B + so + tt*SOSTEP, gA  + tt*rstep + k1);
                    CP16(sb + 1*TILE_B + so + tt*SOSTEP, gBh + tt*rstep + k1);
                    CP16(sb + 2*TILE_B + so + tt*SOSTEP, gBl + tt*rstep + k1);
                }
                CP_COMMIT();
                CP_WAIT1();
            } else if (has_next) {
                // prefetch next tile's chunk 0 into buf0 (last chunk computes buf1)
#pragma unroll
                for (int tt = 0; tt < 4; tt++) {
                    CP16(sb0 + 0*TILE_B + so + tt*SOSTEP, nA  + tt*rstep);
                    CP16(sb0 + 1*TILE_B + so + tt*SOSTEP, nBh + tt*rstep);
                    CP16(sb0 + 2*TILE_B + so + tt*SOSTEP, nBl + tt*rstep);
                }
                CP_COMMIT();
                CP_WAIT1();
            } else {
                CP_WAIT0();
            }
            __syncthreads();

            const uint32_t sb  = sb0 + (c & 1) * BUF_B;
            const uint32_t sA  = sb + 0*TILE_B;
            const uint32_t sBh = sb + 1*TILE_B;
            const uint32_t sBl = sb + 2*TILE_B;

#pragma unroll
            for (int ks = 0; ks < 4; ks++) {
                const uint32_t kb = (uint32_t)(ks * 32);
                uint32_t ah[2][4];
#pragma unroll
                for (int i = 0; i < 2; i++) {
                    uint32_t aoff = (a_row + i * 16) * (AS * 2) + kb + a_kb;
                    LDSM_X4(ah[i][0], ah[i][1], ah[i][2], ah[i][3], sA + aoff);
                }
#pragma unroll
                for (int np = 0; np < 4; np++) {
                    uint32_t boff = (b_row + np * 16) * (AS * 2) + kb + b_kb;
                    uint32_t bh0, bh1, bh2, bh3, bl0, bl1, bl2, bl3;
                    LDSM_X4(bh0, bh1, bh2, bh3, sBh + boff);
                    LDSM_X4(bl0, bl1, bl2, bl3, sBl + boff);
                    MMA16816(acc[0][np*2+0], ah[0][0], ah[0][1], ah[0][2], ah[0][3], bh0, bh1);
                    MMA16816(acc[1][np*2+0], ah[1][0], ah[1][1], ah[1][2], ah[1][3], bh0, bh1);
                    MMA16816(acc[0][np*2+1], ah[0][0], ah[0][1], ah[0][2], ah[0][3], bh2, bh3);
                    MMA16816(acc[1][np*2+1], ah[1][0], ah[1][1], ah[1][2], ah[1][3], bh2, bh3);
                    MMA16816(acc[0][np*2+0], ah[0][0], ah[0][1], ah[0][2], ah[0][3], bl0, bl1);
                    MMA16816(acc[1][np*2+0], ah[1][0], ah[1][1], ah[1][2], ah[1][3], bl0, bl1);
                    MMA16816(acc[0][np*2+1], ah[0][0], ah[0][1], ah[0][2], ah[0][3], bl2, bl3);
                    MMA16816(acc[1][np*2+1], ah[1][0], ah[1][1], ah[1][2], ah[1][3], bl2, bl3);
                }
            }
            __syncthreads();
        }

        // epilogue for tile (bx, by, bz); next tile's chunk-0 load is in flight
        {
            const float* biasp = bias ? (bias + (size_t)bz * biaszs) : nullptr;
            float* Cp = C + (size_t)bz * czs;
            __half* Chp = (OUT >= 1) ? (Ch + (size_t)bz * czs) : nullptr;
            const int m0 = by * 128, n0 = bx * 128;
#pragma unroll
            for (int i = 0; i < 2; i++) {
                const int r0 = m0 + wm * 32 + i * 16 + (lane >> 2);
#pragma unroll
                for (int nt = 0; nt < 8; nt++) {
                    const int col = n0 + wn * 64 + nt * 8 + (lane & 3) * 2;
#pragma unroll
                    for (int half = 0; half < 2; half++) {
                        const int r = r0 + half * 8;
                        float v0 = acc[i][nt][half * 2 + 0];
                        float v1 = acc[i][nt][half * 2 + 1];
                        if (biasp) { v0 += biasp[col]; v1 += biasp[col + 1]; }
                        if (ACT == 1) {
                            v0 = 0.5f * v0 * (1.0f + erff(v0 * 0.70710678118654752f));
                            v1 = 0.5f * v1 * (1.0f + erff(v1 * 0.70710678118654752f));
                        }
                        if (OUT != 2) {
                            float2 o; o.x = v0; o.y = v1;
                            *(float2*)(Cp + (size_t)r * N + col) = o;
                        }
                        if (OUT >= 1)
                            *(uint32_t*)(Chp + (size_t)r * cn + col) = cvt2h(v0, v1);
                    }
                }
            }
        }

        if (!has_next) break;
        t = tn; bx = nbx; by = nby; bz = nbz;
        gA = nA; gBh = nBh; gBl = nBl;
    }
}

// ---------------- attention (ILP dot + rare-rescale softmax) ----------------
__global__ __launch_bounds__(256) void attn_kernel(const float* __restrict__ Q,
                                                   const float* __restrict__ Kp,
                                                   const float* __restrict__ Vp,
                                                   const int* __restrict__ pm,
                                                   __half* __restrict__ Oh,
                                                   int NK, int qst, int kvst,
                                                   int rshift, int pmshift, float scale)
{
    __shared__ float Ks[64][64];
    __shared__ float Vs[64][64];

    const int bh = blockIdx.x;
    const int b  = bh >> 4;
    const int h  = bh & 15;
    const float* qb = Q  + (size_t)b * NQ_ * qst  + h * 64;
    const float* kb = Kp + (size_t)b * NK  * kvst + h * 64;
    const float* vb = Vp + (size_t)b * NK  * kvst + h * 64;
    const int r = threadIdx.x;

    float qr[64];
#pragma unroll
    for (int k4 = 0; k4 < 16; k4++) {
        float4 v = *(const float4*)(qb + (size_t)r * qst + k4 * 4);
        qr[k4*4+0] = v.x; qr[k4*4+1] = v.y; qr[k4*4+2] = v.z; qr[k4*4+3] = v.w;
    }

    float m = -1e30f, l = 0.f;
    float o[64];
#pragma unroll
    for (int k = 0; k < 64; k++) o[k] = 0.f;

    const int maxj = r >> rshift;

    for (int c0 = 0; c0 < NK; c0 += 64) {
        __syncthreads();
        for (int t = threadIdx.x; t < 1024; t += 256) {
            int j = t >> 4;
            int c = (t & 15) << 2;
            *(float4*)&Ks[j][c] = *(const float4*)(kb + (size_t)(c0 + j) * kvst + c);
            *(float4*)&Vs[j][c] = *(const float4*)(vb + (size_t)(c0 + j) * kvst + c);
        }
        __syncthreads();

        int jend = maxj - c0;
        if (jend > 63) jend = 63;
        for (int j = 0; j <= jend; j++) {
            float d0 = 0.f, d1 = 0.f, d2 = 0.f, d3 = 0.f;
#pragma unroll
            for (int k = 0; k < 64; k += 4) {
                d0 += qr[k+0] * Ks[j][k+0];
                d1 += qr[k+1] * Ks[j][k+1];
                d2 += qr[k+2] * Ks[j][k+2];
                d3 += qr[k+3] * Ks[j][k+3];
            }
            int gj = c0 + j;
            float sc = ((d0 + d1) + (d2 + d3)) * scale
                     + NEGV * (float)pm[b * SEQ + (gj >> pmshift)];
            if (sc > m) {
                float corr = expf(m - sc);
                l = l * corr + 1.f;
#pragma unroll
                for (int k = 0; k < 64; k++) o[k] = o[k] * corr + Vs[j][k];
                m = sc;
            } else {
                float p = expf(sc - m);
                l += p;
#pragma unroll
                for (int k = 0; k < 64; k++) o[k] += p * Vs[j][k];
            }
        }
    }

    float inv = 1.f / l;
    const size_t obase = ((size_t)b * NQ_ + r) * D_ + h * 64;
#pragma unroll
    for (int k2 = 0; k2 < 32; k2++)
        *(uint32_t*)(Oh + obase + k2*2) = cvt2h(o[k2*2] * inv, o[k2*2+1] * inv);
}

// ---------------- LN helpers ----------------
__device__ __forceinline__ void block_reduce2(float& a, float& b)
{
    __shared__ float sa[8], sb[8];
    const unsigned full = 0xffffffffu;
#pragma unroll
    for (int o = 16; o > 0; o >>= 1) {
        a += __shfl_down_sync(full, a, o);
        b += __shfl_down_sync(full, b, o);
    }
    int w = threadIdx.x >> 5, lane = threadIdx.x & 31;
    if (lane == 0) { sa[w] = a; sb[w] = b; }
    __syncthreads();
    float ta = 0.f, tb = 0.f;
#pragma unroll
    for (int i = 0; i < 8; i++) { ta += sa[i]; tb += sb[i]; }
    a = ta; b = tb;
}

__device__ __forceinline__ void block_reduce4(float& a, float& b, float& c, float& d)
{
    __shared__ float s4[8][4];
    const unsigned full = 0xffffffffu;
#pragma unroll
    for (int o = 16; o > 0; o >>= 1) {
        a += __shfl_down_sync(full, a, o);
        b += __shfl_down_sync(full, b, o);
        c += __shfl_down_sync(full, c, o);
        d += __shfl_down_sync(full, d, o);
    }
    int w = threadIdx.x >> 5, lane = threadIdx.x & 31;
    if (lane == 0) { s4[w][0] = a; s4[w][1] = b; s4[w][2] = c; s4[w][3] = d; }
    __syncthreads();
    float ta = 0.f, tb = 0.f, tc = 0.f, td = 0.f;
#pragma unroll
    for (int i = 0; i < 8; i++) {
        ta += s4[i][0]; tb += s4[i][1]; tc += s4[i][2]; td += s4[i][3];
    }
    a = ta; b = tb; c = tc; d = td;
}

// q = LN(q + add) * (1+s) + sh ; fp16 mirror (+ optional concat copy)
__global__ __launch_bounds__(256) void ln_mod_resid(float* __restrict__ q,
                                                    __half* __restrict__ qh,
                                                    __half* __restrict__ qcat,
                                                    const float* __restrict__ add,
                                                    const float* __restrict__ mod,
                                                    int off)
{
    const int row = blockIdx.x;
    const int b = row >> 8, n = row & 255;
    const float* mp = mod + ((size_t)(b * SEQ + (n >> 1))) * (6 * D_) + off;
    const size_t base = (size_t)row * D_;
    const int d = threadIdx.x * 4;

    float4 xv = *(const float4*)(q + base + d);
    float4 av = *(const float4*)(add + base + d);
    float x[4] = {xv.x + av.x, xv.y + av.y, xv.z + av.z, xv.w + av.w};

    float s  = x[0] + x[1] + x[2] + x[3];
    float ss = x[0]*x[0] + x[1]*x[1] + x[2]*x[2] + x[3]*x[3];
    block_reduce2(s, ss);
    float mean = s * (1.f / D_);
    float var  = ss * (1.f / D_) - mean * mean;
    float inv  = rsqrtf(var + 1e-6f);

    float4 sv  = *(const float4*)(mp + d);
    float4 shv = *(const float4*)(mp + D_ + d);
    float y0 = (x[0]-mean)*inv*(1.f+sv.x)+shv.x;
    float y1 = (x[1]-mean)*inv*(1.f+sv.y)+shv.y;
    float y2 = (x[2]-mean)*inv*(1.f+sv.z)+shv.z;
    float y3 = (x[3]-mean)*inv*(1.f+sv.w)+shv.w;
    float4 o; o.x = y0; o.y = y1; o.z = y2; o.w = y3;
    *(float4*)(q + base + d) = o;
    uint2 hh; hh.x = cvt2h(y0, y1); hh.y = cvt2h(y2, y3);
    *(uint2*)(qh + base + d) = hh;
    if (qcat)
        *(uint2*)(qcat + (size_t)row * (2*D_) + D_ + d) = hh;
}

// q = LN((1+al)*q2 + q) * (1+s) + sh ; fp16 mirror
__global__ __launch_bounds__(256) void alpha_ln_mod(float* __restrict__ q,
                                                    __half* __restrict__ qh,
                                                    const float* __restrict__ q2,
                                                    const float* __restrict__ al,
                                                    const float* __restrict__ mod,
                                                    int off)
{
    const int row = blockIdx.x;
    const int b = row >> 8, n = row & 255;
    const float* mp = mod + ((size_t)(b * SEQ + (n >> 1))) * (6 * D_) + off;
    const size_t base = (size_t)row * D_;
    const int d = threadIdx.x * 4;

    float4 qv  = *(const float4*)(q  + base + d);
    float4 q2v = *(const float4*)(q2 + base + d);
    float4 alv = *(const float4*)(al + base + d);
    float x[4];
    x[0] = (1.f+alv.x)*q2v.x + qv.x;
    x[1] = (1.f+alv.y)*q2v.y + qv.y;
    x[2] = (1.f+alv.z)*q2v.z + qv.z;
    x[3] = (1.f+alv.w)*q2v.w + qv.w;

    float s  = x[0] + x[1] + x[2] + x[3];
    float ss = x[0]*x[0] + x[1]*x[1] + x[2]*x[2] + x[3]*x[3];
    block_reduce2(s, ss);
    float mean = s * (1.f / D_);
    float var  = ss * (1.f / D_) - mean * mean;
    float inv  = rsqrtf(var + 1e-6f);

    float4 sv  = *(const float4*)(mp + d);
    float4 shv = *(const float4*)(mp + D_ + d);
    float y0 = (x[0]-mean)*inv*(1.f+sv.x)+shv.x;
    float y1 = (x[1]-mean)*inv*(1.f+sv.y)+shv.y;
    float y2 = (x[2]-mean)*inv*(1.f+sv.z)+shv.z;
    float y3 = (x[3]-mean)*inv*(1.f+sv.w)+shv.w;
    float4 o; o.x = y0; o.y = y1; o.z = y2; o.w = y3;
    *(float4*)(q + base + d) = o;
    uint2 hh; hh.x = cvt2h(y0, y1); hh.y = cvt2h(y2, y3);
    *(uint2*)(qh + base + d) = hh;
}

// fused: kin = fp16(LN(c+pe)*g1+b1), vin = fp16(LN(c)*g2+b2), eps=1e-5
__global__ __launch_bounds__(256) void ln_gamma2(__half* __restrict__ kin,
                                                 __half* __restrict__ vin,
                                                 const float* __restrict__ c,
                                                 const float* __restrict__ pe,
                                                 const float* __restrict__ g1,
                                                 const float* __restrict__ b1,
                                                 const float* __restrict__ g2,
                                                 const float* __restrict__ b2)
{
    const int row = blockIdx.x;
    const size_t base = (size_t)row * D_;
    const int d = threadIdx.x * 4;

    float4 cv = *(const float4*)(c  + base + d);
    float4 pv = *(const float4*)(pe + base + d);
    float xk[4] = {cv.x + pv.x, cv.y + pv.y, cv.z + pv.z, cv.w + pv.w};
    float xv[4] = {cv.x, cv.y, cv.z, cv.w};

    float sk = xk[0]+xk[1]+xk[2]+xk[3];
    float ssk = xk[0]*xk[0]+xk[1]*xk[1]+xk[2]*xk[2]+xk[3]*xk[3];
    float sv = xv[0]+xv[1]+xv[2]+xv[3];
    float ssv = xv[0]*xv[0]+xv[1]*xv[1]+xv[2]*xv[2]+xv[3]*xv[3];
    block_reduce4(sk, ssk, sv, ssv);

    float mk = sk * (1.f / D_);
    float ik = rsqrtf(ssk * (1.f / D_) - mk*mk + 1e-5f);
    float mv = sv * (1.f / D_);
    float iv = rsqrtf(ssv * (1.f / D_) - mv*mv + 1e-5f);

    float4 g1v = *(const float4*)(g1 + d);
    float4 b1v = *(const float4*)(b1 + d);
    float4 g2v = *(const float4*)(g2 + d);
    float4 b2v = *(const float4*)(b2 + d);

    float k0 = (xk[0]-mk)*ik*g1v.x+b1v.x;
    float k1 = (xk[1]-mk)*ik*g1v.y+b1v.y;
    float k2 = (xk[2]-mk)*ik*g1v.z+b1v.z;
    float k3 = (xk[3]-mk)*ik*g1v.w+b1v.w;
    uint2 hk; hk.x = cvt2h(k0, k1); hk.y = cvt2h(k2, k3);
    *(uint2*)(kin + base + d) = hk;

    float v0 = (xv[0]-mv)*iv*g2v.x+b2v.x;
    float v1 = (xv[1]-mv)*iv*g2v.y+b2v.y;
    float v2 = (xv[2]-mv)*iv*g2v.z+b2v.z;
    float v3 = (xv[3]-mv)*iv*g2v.w+b2v.w;
    uint2 hv; hv.x = cvt2h(v0, v1); hv.y = cvt2h(v2, v3);
    *(uint2*)(vin + base + d) = hv;
}

__global__ __launch_bounds__(256) void head_kernel(const float* __restrict__ X,
                                                   const float* __restrict__ W,
                                                   const float* __restrict__ bias,
                                                   float* __restrict__ out)
{
    __shared__ float xs[D_];
    const int row = blockIdx.x;
    const size_t base = (size_t)row * D_;
    for (int t = threadIdx.x; t < D_ / 4; t += 256)
        *(float4*)&xs[t * 4] = *(const float4*)(X + base + t * 4);
    __syncthreads();

    int w = threadIdx.x >> 5, lane = threadIdx.x & 31;
    for (int col = w; col < VOCAB; col += 8) {
        float s = 0.f;
        for (int k = lane; k < D_; k += 32) s += xs[k] * W[(size_t)k * VOCAB + col];
#pragma unroll
        for (int o = 16; o > 0; o >>= 1) s += __shfl_down_sync(0xffffffffu, s, o);
        if (lane == 0) out[(size_t)row * VOCAB + col] = s + bias[col];
    }
}

// ---------------- host orchestration ----------------
static float* symaddr_f(const void* s)
{
    void* p = nullptr;
    cudaGetSymbolAddress(&p, s);
    return (float*)p;
}
static __half* symaddr_h(const void* s)
{
    void* p = nullptr;
    cudaGetSymbolAddress(&p, s);
    return (__half*)p;
}
static inline int pgrid(int nt) { return nt < 296 ? nt : 296; }

extern "C" void kernel_launch(void* const* d_in, const int* in_sizes, int n_in,
                              void* d_out, int out_size)
{
    const float* q_in   = (const float*)d_in[0];
    const float* c_in   = (const float*)d_in[1];
    const float* pe_in  = (const float*)d_in[2];
    const float* mod_w  = (const float*)d_in[3];
    const float* mod_b  = (const float*)d_in[4];
    const float* sa_qw  = (const float*)d_in[5];
    const float* sa_kw  = (const float*)d_in[6];
    const float* sa_vw  = (const float*)d_in[7];
    const float* sa_pw  = (const float*)d_in[8];
    const float* sa_pb  = (const float*)d_in[9];
    const float* ca_qw  = (const float*)d_in[10];
    const float* ca_kw  = (const float*)d_in[11];
    const float* ca_vw  = (const float*)d_in[12];
    const float* ca_pw  = (const float*)d_in[13];
    const float* ca_pb  = (const float*)d_in[14];
    const float* nk_g   = (const float*)d_in[15];
    const float* nk_b   = (const float*)d_in[16];
    const float* nv_g   = (const float*)d_in[17];
    const float* nv_b   = (const float*)d_in[18];
    const float* al_w   = (const float*)d_in[19];
    const float* al_b   = (const float*)d_in[20];
    const float* fc1_w  = (const float*)d_in[21];
    const float* fc1_b  = (const float*)d_in[22];
    const float* fc2_w  = (const float*)d_in[23];
    const float* fc2_b  = (const float*)d_in[24];
    const float* head_w = (const float*)d_in[25];
    const float* head_b = (const float*)d_in[26];
    const int*   pm     = (const int*)  d_in[27];
    float* out = (float*)d_out;

    __half* wth   = symaddr_h(g_wth);
    __half* wtl   = symaddr_h(g_wtl);
    __half* sc16  = symaddr_h(g_sc16);
    __half* q16   = symaddr_h(g_q16);
    __half* ao16  = symaddr_h(g_ao16);
    __half* kv16  = symaddr_h(g_kv16);
    __half* cat16 = symaddr_h(g_cat16);
    __half* h16   = symaddr_h(g_h16);

    float* mod  = symaddr_f(g_mod);
    float* qbuf = symaddr_f(g_q);
    float* qkv  = symaddr_f(g_qkv);
    float* qp   = symaddr_f(g_qp);
    float* kvp  = symaddr_f(g_kvp);
    float* po   = symaddr_f(g_po);
    float* q2   = symaddr_f(g_q2);
    float* alf  = symaddr_f(g_alf);

    cudaFuncSetAttribute(gemm_mma<0,0>, cudaFuncAttributeMaxDynamicSharedMemorySize, GEMM_SMEM);
    cudaFuncSetAttribute(gemm_mma<0,1>, cudaFuncAttributeMaxDynamicSharedMemorySize, GEMM_SMEM);
    cudaFuncSetAttribute(gemm_mma<1,2>, cudaFuncAttributeMaxDynamicSharedMemorySize, GEMM_SMEM);

    const int MQ = BATCH * NQ_;   // 8192
    const int MC = BATCH * SEQ;   // 4096
    const float scale = 0.125f;
    const size_t MODL = (size_t)MC * 6 * D_;
    const size_t DD   = (size_t)D_ * D_;
    const size_t MCD  = (size_t)MC * D_;

    const int ntQ   = (D_/128) * (MQ/128);        // 512
    const int ntQKV = (3*D_/128) * (MQ/128);      // 1536
    const int ntFc1 = (HID/128) * (MQ/128);       // 2048
    const int ntMod = (6*D_/128) * (MC/128) * 2;  // 3072
    const int ntKV  = (D_/128) * (MC/128) * 2;    // 512

    // #1-#3: prerequisites
    silu_h<<<(MC * D_ / 4 + 255) / 256, 256>>>(c_in, sc16, MC * D_ / 4);
    transpose_split<<<dim3(6*D_/32, D_/32, NLAYER), 256>>>(mod_w, wth + OFF_MOD, wtl + OFF_MOD, D_, 6*D_, (size_t)D_*6*D_, WPL);
    copy_h<<<(MQ * D_ / 4 + 255) / 256, 256>>>(q_in, qbuf, q16, MQ * D_ / 4);
    // #4-#6: all-layer mod GEMMs
    for (int ck = 0; ck < 3; ck++) {
        gemm_mma<0,0><<<pgrid(ntMod), 256, GEMM_SMEM>>>(
            sc16, wth + OFF_MOD + (size_t)(2*ck)*WPL, wtl + OFF_MOD + (size_t)(2*ck)*WPL,
            mod_b + (size_t)(2*ck)*6*D_, mod + (size_t)(2*ck)*MODL, nullptr,
            MC, 6*D_, D_, 6*D_, 0, WPL, (size_t)6*D_, MODL, ntMod);
    }

    // remaining weight transposes (z-batched over layers)
    transpose_split<<<dim3(32, 32, NLAYER), 256>>>(sa_qw, wth + OFF_SAQ,           wtl + OFF_SAQ,           D_, D_, DD, WPL);
    transpose_split<<<dim3(32, 32, NLAYER), 256>>>(sa_kw, wth + OFF_SAQ + 1048576, wtl + OFF_SAQ + 1048576, D_, D_, DD, WPL);
    transpose_split<<<dim3(32, 32, NLAYER), 256>>>(sa_vw, wth + OFF_SAQ + 2097152, wtl + OFF_SAQ + 2097152, D_, D_, DD, WPL);
    transpose_split<<<dim3(32, 32, NLAYER), 256>>>(sa_pw, wth + OFF_SAP, wtl + OFF_SAP, D_, D_, DD, WPL);
    transpose_split<<<dim3(32, 32, NLAYER), 256>>>(ca_qw, wth + OFF_CAQ, wtl + OFF_CAQ, D_, D_, DD, WPL);
    transpose_split<<<dim3(32, 32, NLAYER), 256>>>(ca_kw, wth + OFF_CAK, wtl + OFF_CAK, D_, D_, DD, WPL);
    transpose_split<<<dim3(32, 32, NLAYER), 256>>>(ca_vw, wth + OFF_CAV, wtl + OFF_CAV, D_, D_, DD, WPL);
    transpose_split<<<dim3(32, 32, NLAYER), 256>>>(ca_pw, wth + OFF_CAP, wtl + OFF_CAP, D_, D_, DD, WPL);
    transpose_split<<<dim3(32, 64, NLAYER), 256>>>(al_w, wth + OFF_AL, wtl + OFF_AL, 2*D_, D_, 2*DD, WPL);
    transpose_split<<<dim3(HID/32, 32, NLAYER), 256>>>(fc1_w, wth + OFF_FC1, wtl + OFF_FC1, D_, HID, (size_t)D_*HID, WPL);
    transpose_split<<<dim3(32, HID/32, NLAYER), 256>>>(fc2_w, wth + OFF_FC2, wtl + OFF_FC2, HID, D_, (size_t)HID*D_, WPL);

    for (int i = 0; i < NLAYER; i++) {
        size_t wb = (size_t)i * WPL;
        const float* modL = mod + (size_t)i * MODL;
        const float* spb = sa_pb + (size_t)i * D_;
        const float* cpb = ca_pb + (size_t)i * D_;
        const float* alb = al_b  + (size_t)i * D_;
        const float* f1b = fc1_b + (size_t)i * HID;
        const float* f2b = fc2_b + (size_t)i * D_;

        // ---- self-attention (fused QKV) ----
        gemm_mma<0,0><<<pgrid(ntQKV), 256, GEMM_SMEM>>>(q16, wth + wb + OFF_SAQ, wtl + wb + OFF_SAQ, nullptr, qkv, nullptr, MQ, 3*D_, D_, 3*D_, 0, 0, 0, 0, ntQKV);
        attn_kernel<<<BATCH*NHEAD, 256>>>(qkv, qkv + D_, qkv + 2*D_, pm, ao16, NQ_, 3*D_, 3*D_, 0, 1, scale);
        gemm_mma<0,0><<<pgrid(ntQ), 256, GEMM_SMEM>>>(ao16, wth + wb + OFF_SAP, wtl + wb + OFF_SAP, spb, po, nullptr, MQ, D_, D_, D_, 0, 0, 0, 0, ntQ);
        ln_mod_resid<<<MQ, 256>>>(qbuf, q16, cat16, po, modL, 0);

        // ---- cross attention ----
        ln_gamma2<<<MC, 256>>>(kv16, kv16 + MCD, c_in, pe_in,
                               nk_g + (size_t)i*D_, nk_b + (size_t)i*D_,
                               nv_g + (size_t)i*D_, nv_b + (size_t)i*D_);
        gemm_mma<0,0><<<pgrid(ntKV), 256, GEMM_SMEM>>>(
            kv16, wth + wb + OFF_CAK, wtl + wb + OFF_CAK, nullptr, kvp, nullptr,
            MC, D_, D_, D_, MCD, DD, 0, MCD, ntKV);
        gemm_mma<0,0><<<pgrid(ntQ), 256, GEMM_SMEM>>>(q16, wth + wb + OFF_CAQ, wtl + wb + OFF_CAQ, nullptr, qp, nullptr, MQ, D_, D_, D_, 0, 0, 0, 0, ntQ);
        attn_kernel<<<BATCH*NHEAD, 256>>>(qp, kvp, kvp + MCD, pm, ao16, SEQ, D_, D_, 1, 0, scale);
        gemm_mma<0,1><<<pgrid(ntQ), 256, GEMM_SMEM>>>(ao16, wth + wb + OFF_CAP, wtl + wb + OFF_CAP, cpb, q2, cat16, MQ, D_, D_, 2*D_, 0, 0, 0, 0, ntQ);

        // alpha = [q2, q] @ al_w + al_b  (single K=2048 GEMM)
        gemm_mma<0,0><<<pgrid(ntQ), 256, GEMM_SMEM>>>(cat16, wth + wb + OFF_AL, wtl + wb + OFF_AL, alb, alf, nullptr, MQ, D_, 2*D_, D_, 0, 0, 0, 0, ntQ);
        alpha_ln_mod<<<MQ, 256>>>(qbuf, q16, q2, alf, modL, 2*D_);

        // ---- MLP ----
        gemm_mma<1,2><<<pgrid(ntFc1), 256, GEMM_SMEM>>>(q16, wth + wb + OFF_FC1, wtl + wb + OFF_FC1, f1b, po, h16, MQ, HID, D_, HID, 0, 0, 0, 0, ntFc1);
        gemm_mma<0,0><<<pgrid(ntQ), 256, GEMM_SMEM>>>(h16, wth + wb + OFF_FC2, wtl + wb + OFF_FC2, f2b, po, nullptr, MQ, D_, HID, D_, 0, 0, 0, 0, ntQ);
        ln_mod_resid<<<MQ, 256>>>(qbuf, q16, nullptr, po, modL, 4*D_);
    }

    head_kernel<<<MQ, 256>>>(qbuf, head_w, head_b, out);
}

// round 11
// speedup vs baseline: 1.0534x; 1.0534x over previous
#include <cuda_runtime.h>
#include <cuda_fp16.h>
#include <cstdint>
#include <cstddef>

#define D_    1024
#define BATCH 32
#define SEQ   128
#define NQ_   256
#define HID   4096
#define NHEAD 16
#define NEGV  (-10000.0f)
#define NLAYER 6
#define VOCAB 18

// ---------------- portable PTX helpers (compute_103-safe) -------------------
__device__ __forceinline__ uint32_t smem_u32(const void* p) {
    uint32_t a;
    asm("{ .reg .u64 t; cvta.to.shared.u64 t, %1; cvt.u32.u64 %0, t; }"
        : "=r"(a) : "l"(p));
    return a;
}

#define CP16(s, g) \
    asm volatile("cp.async.cg.shared.global [%0], [%1], 16;" :: "r"(s), "l"(g))
#define CP_COMMIT() asm volatile("cp.async.commit_group;" ::: "memory")
#define CP_WAIT1()  asm volatile("cp.async.wait_group 1;" ::: "memory")
#define CP_WAIT0()  asm volatile("cp.async.wait_group 0;" ::: "memory")

#define LDSM_X4(r0, r1, r2, r3, addr) \
    asm volatile("ldmatrix.sync.aligned.m8n8.x4.shared.b16 {%0,%1,%2,%3}, [%4];" \
                 : "=r"(r0), "=r"(r1), "=r"(r2), "=r"(r3) : "r"(addr))

#define MMA16816(c, a0, a1, a2, a3, b0, b1) \
    asm volatile("mma.sync.aligned.m16n8k16.row.col.f32.f16.f16.f32 " \
                 "{%0,%1,%2,%3}, {%4,%5,%6,%7}, {%8,%9}, {%0,%1,%2,%3};" \
                 : "+f"((c)[0]), "+f"((c)[1]), "+f"((c)[2]), "+f"((c)[3]) \
                 : "r"(a0), "r"(a1), "r"(a2), "r"(a3), "r"(b0), "r"(b1))

__device__ __forceinline__ uint32_t cvt2h(float a, float b) {
    __half2 t = __floats2half2_rn(a, b);
    return *(uint32_t*)&t;
}
__device__ __forceinline__ void split2h(float a, float b, uint32_t& h, uint32_t& l) {
    __half ha = __float2half_rn(a);
    __half hb = __float2half_rn(b);
    __half la = __float2half_rn(a - __half2float(ha));
    __half lb = __float2half_rn(b - __half2float(hb));
    __half2 hh; hh.x = ha; hh.y = hb;
    __half2 ll; ll.x = la; ll.y = lb;
    h = *(uint32_t*)&hh;
    l = *(uint32_t*)&ll;
}

// ---------------- scratch (device globals; allocation-free) ----------------
#define WPL 25165824ULL
#define OFF_MOD 0ULL
#define OFF_SAQ 6291456ULL
#define OFF_SAP 9437184ULL
#define OFF_CAQ 10485760ULL
#define OFF_CAK 11534336ULL
#define OFF_CAV 12582912ULL
#define OFF_CAP 13631488ULL
#define OFF_AL  14680064ULL
#define OFF_FC1 16777216ULL
#define OFF_FC2 20971520ULL

__device__ __half g_wth[NLAYER * WPL];
__device__ __half g_wtl[NLAYER * WPL];
__device__ __half g_sc16 [BATCH*SEQ*D_];
__device__ __half g_q16  [BATCH*NQ_*D_];
__device__ __half g_ao16 [BATCH*NQ_*D_];
__device__ __half g_kv16 [2*BATCH*SEQ*D_];
__device__ __half g_cat16[BATCH*NQ_*2*D_];
__device__ __half g_h16  [BATCH*NQ_*HID];

__device__ float g_mod[NLAYER*BATCH*SEQ*6*D_];
__device__ float g_q  [BATCH*NQ_*D_];
__device__ float g_qkv[BATCH*NQ_*3*D_];
__device__ float g_qp [BATCH*NQ_*D_];
__device__ float g_kvp[2*BATCH*SEQ*D_];
__device__ float g_po [BATCH*NQ_*D_];
__device__ float g_q2 [BATCH*NQ_*D_];
__device__ float g_alf[BATCH*NQ_*D_];

// ---------------- weight transpose + fp16 hi/lo split (z-batched) ----------
__global__ __launch_bounds__(256) void transpose_split(const float* __restrict__ W,
                                                       __half* __restrict__ oh,
                                                       __half* __restrict__ ol,
                                                       int K, int N,
                                                       size_t ils, size_t ols)
{
    __shared__ float t[32][33];
    const int z = blockIdx.z;
    W  += (size_t)z * ils;
    oh += (size_t)z * ols;
    ol += (size_t)z * ols;
    const int n0 = blockIdx.x * 32, k0 = blockIdx.y * 32;
    const int tx = threadIdx.x & 31, ty = threadIdx.x >> 5;
#pragma unroll
    for (int r = 0; r < 4; r++)
        t[ty + 8*r][tx] = W[(size_t)(k0 + ty + 8*r) * N + n0 + tx];
    __syncthreads();
#pragma unroll
    for (int s = 0; s < 2; s++) {
        int id = threadIdx.x + s * 256;
        int n  = id >> 4;
        int kp = (id & 15) * 2;
        uint32_t h, l;
        split2h(t[kp][n], t[kp + 1][n], h, l);
        size_t o = (size_t)(n0 + n) * K + k0 + kp;
        *(uint32_t*)(oh + o) = h;
        *(uint32_t*)(ol + o) = l;
    }
}

__global__ void silu_h(const float* __restrict__ x, __half* __restrict__ oh, int n4)
{
    int i = blockIdx.x * blockDim.x + threadIdx.x;
    if (i >= n4) return;
    float4 v = ((const float4*)x)[i];
    float f[4] = {v.x, v.y, v.z, v.w};
#pragma unroll
    for (int j = 0; j < 4; j++) f[j] = f[j] / (1.f + expf(-f[j]));
    uint2 hh; hh.x = cvt2h(f[0], f[1]); hh.y = cvt2h(f[2], f[3]);
    *(uint2*)(oh + 4*(size_t)i) = hh;
}

__global__ void copy_h(const float* __restrict__ x, float* __restrict__ o,
                       __half* __restrict__ oh, int n4)
{
    int i = blockIdx.x * blockDim.x + threadIdx.x;
    if (i >= n4) return;
    float4 v = ((const float4*)x)[i];
    ((float4*)o)[i] = v;
    uint2 hh; hh.x = cvt2h(v.x, v.y); hh.y = cvt2h(v.z, v.w);
    *(uint2*)(oh + 4*(size_t)i) = hh;
}

// ---------------- persistent HMMA GEMM (2-term fp16 split, BK=64) -----------
// OUT: 0 = fp32 only, 1 = fp32 + fp16, 2 = fp16 only
// __launch_bounds__(256, 2): cap regs at 128 so 2 CTAs/SM stay resident.
// Next-tile state lives only inside the last-chunk branch (minimal regs).
#define AS 72
#define TILE_B (128 * AS * 2)       // 18432 B
#define BUF_B  (3 * TILE_B)         // 55296 B (A, Bh, Bl)
#define GEMM_SMEM (2 * BUF_B)       // 110592 B

template<int ACT, int OUT>
__global__ __launch_bounds__(256, 2) void gemm_mma(const __half* __restrict__ A,
                                                   const __half* __restrict__ Bh,
                                                   const __half* __restrict__ Bl,
                                                   const float* __restrict__ bias,
                                                   float* __restrict__ C,
                                                   __half* __restrict__ Ch,
                                                   int M, int N, int K, int cn,
                                                   size_t azs, size_t bzs,
                                                   size_t biaszs, size_t czs,
                                                   int ntiles)
{
    extern __shared__ __align__(128) char dynsm[];
    const uint32_t sb0 = smem_u32(dynsm);
    const int nx = N >> 7, ny = M >> 7;

    const int tid  = threadIdx.x;
    const int lane = tid & 31;
    const int wid  = tid >> 5;
    const int wm   = wid & 3;
    const int wn   = wid >> 2;

    const int lr  = tid >> 3;
    const int lcs = (tid & 7) * 8;
    const uint32_t so = (uint32_t)(lr * AS + lcs) * 2;
    const uint32_t SOSTEP = 32u * AS * 2;
    const size_t rstep = (size_t)32 * K;
    const int nch = K >> 6;       // even for all our Ks (1024/2048/4096)

    int t = blockIdx.x;
    int bx = t % nx, rr = t / nx, by = rr % ny, bz = rr / ny;
    const __half* gA  = A  + (size_t)bz * azs + (size_t)(by * 128 + lr) * K + lcs;
    const __half* gBh = Bh + (size_t)bz * bzs + (size_t)(bx * 128 + lr) * K + lcs;
    const __half* gBl = Bl + (size_t)bz * bzs + (size_t)(bx * 128 + lr) * K + lcs;

    // prefetch chunk 0 of first tile
#pragma unroll
    for (int tt = 0; tt < 4; tt++) {
        CP16(sb0 + 0*TILE_B + so + tt*SOSTEP, gA  + tt*rstep);
        CP16(sb0 + 1*TILE_B + so + tt*SOSTEP, gBh + tt*rstep);
        CP16(sb0 + 2*TILE_B + so + tt*SOSTEP, gBl + tt*rstep);
    }
    CP_COMMIT();

    const uint32_t a_row = (uint32_t)(wm * 32 + (lane & 15));
    const uint32_t a_kb  = (uint32_t)((lane >> 4) * 16);
    const uint32_t b_row = (uint32_t)(wn * 64 + (lane & 7) + ((lane >> 4) << 3));
    const uint32_t b_kb  = (uint32_t)(((lane >> 3) & 1) * 16);

    while (true) {
        float acc[2][8][4];
#pragma unroll
        for (int i = 0; i < 2; i++)
#pragma unroll
            for (int n = 0; n < 8; n++)
#pragma unroll
                for (int j = 0; j < 4; j++) acc[i][n][j] = 0.f;

        const bool has_next = (t + (int)gridDim.x < ntiles);

        for (int c = 0; c < nch; c++) {
            if (c + 1 < nch) {
                const int k1 = (c + 1) << 6;
                uint32_t sb = sb0 + ((c + 1) & 1) * BUF_B;
#pragma unroll
                for (int tt = 0; tt < 4; tt++) {
                    CP16(sb + 0*TILE_B + so + tt*SOSTEP, gA  + tt*rstep + k1);
                    CP16(sb + 1*TILE_B + so + tt*SOSTEP, gBh + tt*rstep + k1);
                    CP16(sb + 2*TILE_B + so + tt*SOSTEP, gBl + tt*rstep + k1);
                }
                CP_COMMIT();
                CP_WAIT1();
            } else if (has_next) {
                // compute next-tile pointers HERE (short lifetime, low reg pressure)
                const int tn = t + gridDim.x;
                const int nbx = tn % nx; int r2 = tn / nx;
                const int nby = r2 % ny, nbz = r2 / ny;
                const __half* nA  = A  + (size_t)nbz * azs + (size_t)(nby * 128 + lr) * K + lcs;
                const __half* nBh = Bh + (size_t)nbz * bzs + (size_t)(nbx * 128 + lr) * K + lcs;
                const __half* nBl = Bl + (size_t)nbz * bzs + (size_t)(nbx * 128 + lr) * K + lcs;
                // last chunk computes from buf1; buf0 reads already fenced by prior barrier
#pragma unroll
                for (int tt = 0; tt < 4; tt++) {
                    CP16(sb0 + 0*TILE_B + so + tt*SOSTEP, nA  + tt*rstep);
                    CP16(sb0 + 1*TILE_B + so + tt*SOSTEP, nBh + tt*rstep);
                    CP16(sb0 + 2*TILE_B + so + tt*SOSTEP, nBl + tt*rstep);
                }
                CP_COMMIT();
                CP_WAIT1();
            } else {
                CP_WAIT0();
            }
            __syncthreads();

            const uint32_t sb  = sb0 + (c & 1) * BUF_B;
            const uint32_t sA  = sb + 0*TILE_B;
            const uint32_t sBh = sb + 1*TILE_B;
            const uint32_t sBl = sb + 2*TILE_B;

#pragma unroll
            for (int ks = 0; ks < 4; ks++) {
                const uint32_t kb = (uint32_t)(ks * 32);
                uint32_t ah[2][4];
#pragma unroll
                for (int i = 0; i < 2; i++) {
                    uint32_t aoff = (a_row + i * 16) * (AS * 2) + kb + a_kb;
                    LDSM_X4(ah[i][0], ah[i][1], ah[i][2], ah[i][3], sA + aoff);
                }
#pragma unroll
                for (int np = 0; np < 4; np++) {
                    uint32_t boff = (b_row + np * 16) * (AS * 2) + kb + b_kb;
                    uint32_t bh0, bh1, bh2, bh3, bl0, bl1, bl2, bl3;
                    LDSM_X4(bh0, bh1, bh2, bh3, sBh + boff);
                    LDSM_X4(bl0, bl1, bl2, bl3, sBl + boff);
                    MMA16816(acc[0][np*2+0], ah[0][0], ah[0][1], ah[0][2], ah[0][3], bh0, bh1);
                    MMA16816(acc[1][np*2+0], ah[1][0], ah[1][1], ah[1][2], ah[1][3], bh0, bh1);
                    MMA16816(acc[0][np*2+1], ah[0][0], ah[0][1], ah[0][2], ah[0][3], bh2, bh3);
                    MMA16816(acc[1][np*2+1], ah[1][0], ah[1][1], ah[1][2], ah[1][3], bh2, bh3);
                    MMA16816(acc[0][np*2+0], ah[0][0], ah[0][1], ah[0][2], ah[0][3], bl0, bl1);
                    MMA16816(acc[1][np*2+0], ah[1][0], ah[1][1], ah[1][2], ah[1][3], bl0, bl1);
                    MMA16816(acc[0][np*2+1], ah[0][0], ah[0][1], ah[0][2], ah[0][3], bl2, bl3);
                    MMA16816(acc[1][np*2+1], ah[1][0], ah[1][1], ah[1][2], ah[1][3], bl2, bl3);
                }
            }
            __syncthreads();
        }

        // epilogue for tile (bx, by, bz); next tile's chunk-0 load in flight
        {
            const float* biasp = bias ? (bias + (size_t)bz * biaszs) : nullptr;
            float* Cp = C + (size_t)bz * czs;
            __half* Chp = (OUT >= 1) ? (Ch + (size_t)bz * czs) : nullptr;
            const int m0 = by * 128, n0 = bx * 128;
#pragma unroll
            for (int i = 0; i < 2; i++) {
                const int r0 = m0 + wm * 32 + i * 16 + (lane >> 2);
#pragma unroll
                for (int nt = 0; nt < 8; nt++) {
                    const int col = n0 + wn * 64 + nt * 8 + (lane & 3) * 2;
#pragma unroll
                    for (int half = 0; half < 2; half++) {
                        const int r = r0 + half * 8;
                        float v0 = acc[i][nt][half * 2 + 0];
                        float v1 = acc[i][nt][half * 2 + 1];
                        if (biasp) { v0 += biasp[col]; v1 += biasp[col + 1]; }
                        if (ACT == 1) {
                            v0 = 0.5f * v0 * (1.0f + erff(v0 * 0.70710678118654752f));
                            v1 = 0.5f * v1 * (1.0f + erff(v1 * 0.70710678118654752f));
                        }
                        if (OUT != 2) {
                            float2 o; o.x = v0; o.y = v1;
                            *(float2*)(Cp + (size_t)r * N + col) = o;
                        }
                        if (OUT >= 1)
                            *(uint32_t*)(Chp + (size_t)r * cn + col) = cvt2h(v0, v1);
                    }
                }
            }
        }

        if (!has_next) break;
        // recompute current-tile state from t (cheap; keeps loop-carried regs minimal)
        t += gridDim.x;
        bx = t % nx; rr = t / nx; by = rr % ny; bz = rr / ny;
        gA  = A  + (size_t)bz * azs + (size_t)(by * 128 + lr) * K + lcs;
        gBh = Bh + (size_t)bz * bzs + (size_t)(bx * 128 + lr) * K + lcs;
        gBl = Bl + (size_t)bz * bzs + (size_t)(bx * 128 + lr) * K + lcs;
    }
}

// ---------------- attention (ILP dot + rare-rescale softmax) ----------------
__global__ __launch_bounds__(256) void attn_kernel(const float* __restrict__ Q,
                                                   const float* __restrict__ Kp,
                                                   const float* __restrict__ Vp,
                                                   const int* __restrict__ pm,
                                                   __half* __restrict__ Oh,
                                                   int NK, int qst, int kvst,
                                                   int rshift, int pmshift, float scale)
{
    __shared__ float Ks[64][64];
    __shared__ float Vs[64][64];

    const int bh = blockIdx.x;
    const int b  = bh >> 4;
    const int h  = bh & 15;
    const float* qb = Q  + (size_t)b * NQ_ * qst  + h * 64;
    const float* kb = Kp + (size_t)b * NK  * kvst + h * 64;
    const float* vb = Vp + (size_t)b * NK  * kvst + h * 64;
    const int r = threadIdx.x;

    float qr[64];
#pragma unroll
    for (int k4 = 0; k4 < 16; k4++) {
        float4 v = *(const float4*)(qb + (size_t)r * qst + k4 * 4);
        qr[k4*4+0] = v.x; qr[k4*4+1] = v.y; qr[k4*4+2] = v.z; qr[k4*4+3] = v.w;
    }

    float m = -1e30f, l = 0.f;
    float o[64];
#pragma unroll
    for (int k = 0; k < 64; k++) o[k] = 0.f;

    const int maxj = r >> rshift;

    for (int c0 = 0; c0 < NK; c0 += 64) {
        __syncthreads();
        for (int t = threadIdx.x; t < 1024; t += 256) {
            int j = t >> 4;
            int c = (t & 15) << 2;
            *(float4*)&Ks[j][c] = *(const float4*)(kb + (size_t)(c0 + j) * kvst + c);
            *(float4*)&Vs[j][c] = *(const float4*)(vb + (size_t)(c0 + j) * kvst + c);
        }
        __syncthreads();

        int jend = maxj - c0;
        if (jend > 63) jend = 63;
        for (int j = 0; j <= jend; j++) {
            float d0 = 0.f, d1 = 0.f, d2 = 0.f, d3 = 0.f;
#pragma unroll
            for (int k = 0; k < 64; k += 4) {
                d0 += qr[k+0] * Ks[j][k+0];
                d1 += qr[k+1] * Ks[j][k+1];
                d2 += qr[k+2] * Ks[j][k+2];
                d3 += qr[k+3] * Ks[j][k+3];
            }
            int gj = c0 + j;
            float sc = ((d0 + d1) + (d2 + d3)) * scale
                     + NEGV * (float)pm[b * SEQ + (gj >> pmshift)];
            if (sc > m) {
                float corr = expf(m - sc);
                l = l * corr + 1.f;
#pragma unroll
                for (int k = 0; k < 64; k++) o[k] = o[k] * corr + Vs[j][k];
                m = sc;
            } else {
                float p = expf(sc - m);
                l += p;
#pragma unroll
                for (int k = 0; k < 64; k++) o[k] += p * Vs[j][k];
            }
        }
    }

    float inv = 1.f / l;
    const size_t obase = ((size_t)b * NQ_ + r) * D_ + h * 64;
#pragma unroll
    for (int k2 = 0; k2 < 32; k2++)
        *(uint32_t*)(Oh + obase + k2*2) = cvt2h(o[k2*2] * inv, o[k2*2+1] * inv);
}

// ---------------- LN helpers ----------------
__device__ __forceinline__ void block_reduce2(float& a, float& b)
{
    __shared__ float sa[8], sb[8];
    const unsigned full = 0xffffffffu;
#pragma unroll
    for (int o = 16; o > 0; o >>= 1) {
        a += __shfl_down_sync(full, a, o);
        b += __shfl_down_sync(full, b, o);
    }
    int w = threadIdx.x >> 5, lane = threadIdx.x & 31;
    if (lane == 0) { sa[w] = a; sb[w] = b; }
    __syncthreads();
    float ta = 0.f, tb = 0.f;
#pragma unroll
    for (int i = 0; i < 8; i++) { ta += sa[i]; tb += sb[i]; }
    a = ta; b = tb;
}

__device__ __forceinline__ void block_reduce4(float& a, float& b, float& c, float& d)
{
    __shared__ float s4[8][4];
    const unsigned full = 0xffffffffu;
#pragma unroll
    for (int o = 16; o > 0; o >>= 1) {
        a += __shfl_down_sync(full, a, o);
        b += __shfl_down_sync(full, b, o);
        c += __shfl_down_sync(full, c, o);
        d += __shfl_down_sync(full, d, o);
    }
    int w = threadIdx.x >> 5, lane = threadIdx.x & 31;
    if (lane == 0) { s4[w][0] = a; s4[w][1] = b; s4[w][2] = c; s4[w][3] = d; }
    __syncthreads();
    float ta = 0.f, tb = 0.f, tc = 0.f, td = 0.f;
#pragma unroll
    for (int i = 0; i < 8; i++) {
        ta += s4[i][0]; tb += s4[i][1]; tc += s4[i][2]; td += s4[i][3];
    }
    a = ta; b = tb; c = tc; d = td;
}

// q = LN(q + add) * (1+s) + sh ; fp16 mirror (+ optional concat copy)
__global__ __launch_bounds__(256) void ln_mod_resid(float* __restrict__ q,
                                                    __half* __restrict__ qh,
                                                    __half* __restrict__ qcat,
                                                    const float* __restrict__ add,
                                                    const float* __restrict__ mod,
                                                    int off)
{
    const int row = blockIdx.x;
    const int b = row >> 8, n = row & 255;
    const float* mp = mod + ((size_t)(b * SEQ + (n >> 1))) * (6 * D_) + off;
    const size_t base = (size_t)row * D_;
    const int d = threadIdx.x * 4;

    float4 xv = *(const float4*)(q + base + d);
    float4 av = *(const float4*)(add + base + d);
    float x[4] = {xv.x + av.x, xv.y + av.y, xv.z + av.z, xv.w + av.w};

    float s  = x[0] + x[1] + x[2] + x[3];
    float ss = x[0]*x[0] + x[1]*x[1] + x[2]*x[2] + x[3]*x[3];
    block_reduce2(s, ss);
    float mean = s * (1.f / D_);
    float var  = ss * (1.f / D_) - mean * mean;
    float inv  = rsqrtf(var + 1e-6f);

    float4 sv  = *(const float4*)(mp + d);
    float4 shv = *(const float4*)(mp + D_ + d);
    float y0 = (x[0]-mean)*inv*(1.f+sv.x)+shv.x;
    float y1 = (x[1]-mean)*inv*(1.f+sv.y)+shv.y;
    float y2 = (x[2]-mean)*inv*(1.f+sv.z)+shv.z;
    float y3 = (x[3]-mean)*inv*(1.f+sv.w)+shv.w;
    float4 o; o.x = y0; o.y = y1; o.z = y2; o.w = y3;
    *(float4*)(q + base + d) = o;
    uint2 hh; hh.x = cvt2h(y0, y1); hh.y = cvt2h(y2, y3);
    *(uint2*)(qh + base + d) = hh;
    if (qcat)
        *(uint2*)(qcat + (size_t)row * (2*D_) + D_ + d) = hh;
}

// q = LN((1+al)*q2 + q) * (1+s) + sh ; fp16 mirror
__global__ __launch_bounds__(256) void alpha_ln_mod(float* __restrict__ q,
                                                    __half* __restrict__ qh,
                                                    const float* __restrict__ q2,
                                                    const float* __restrict__ al,
                                                    const float* __restrict__ mod,
                                                    int off)
{
    const int row = blockIdx.x;
    const int b = row >> 8, n = row & 255;
    const float* mp = mod + ((size_t)(b * SEQ + (n >> 1))) * (6 * D_) + off;
    const size_t base = (size_t)row * D_;
    const int d = threadIdx.x * 4;

    float4 qv  = *(const float4*)(q  + base + d);
    float4 q2v = *(const float4*)(q2 + base + d);
    float4 alv = *(const float4*)(al + base + d);
    float x[4];
    x[0] = (1.f+alv.x)*q2v.x + qv.x;
    x[1] = (1.f+alv.y)*q2v.y + qv.y;
    x[2] = (1.f+alv.z)*q2v.z + qv.z;
    x[3] = (1.f+alv.w)*q2v.w + qv.w;

    float s  = x[0] + x[1] + x[2] + x[3];
    float ss = x[0]*x[0] + x[1]*x[1] + x[2]*x[2] + x[3]*x[3];
    block_reduce2(s, ss);
    float mean = s * (1.f / D_);
    float var  = ss * (1.f / D_) - mean * mean;
    float inv  = rsqrtf(var + 1e-6f);

    float4 sv  = *(const float4*)(mp + d);
    float4 shv = *(const float4*)(mp + D_ + d);
    float y0 = (x[0]-mean)*inv*(1.f+sv.x)+shv.x;
    float y1 = (x[1]-mean)*inv*(1.f+sv.y)+shv.y;
    float y2 = (x[2]-mean)*inv*(1.f+sv.z)+shv.z;
    float y3 = (x[3]-mean)*inv*(1.f+sv.w)+shv.w;
    float4 o; o.x = y0; o.y = y1; o.z = y2; o.w = y3;
    *(float4*)(q + base + d) = o;
    uint2 hh; hh.x = cvt2h(y0, y1); hh.y = cvt2h(y2, y3);
    *(uint2*)(qh + base + d) = hh;
}

// fused: kin = fp16(LN(c+pe)*g1+b1), vin = fp16(LN(c)*g2+b2), eps=1e-5
__global__ __launch_bounds__(256) void ln_gamma2(__half* __restrict__ kin,
                                                 __half* __restrict__ vin,
                                                 const float* __restrict__ c,
                                                 const float* __restrict__ pe,
                                                 const float* __restrict__ g1,
                                                 const float* __restrict__ b1,
                                                 const float* __restrict__ g2,
                                                 const float* __restrict__ b2)
{
    const int row = blockIdx.x;
    const size_t base = (size_t)row * D_;
    const int d = threadIdx.x * 4;

    float4 cv = *(const float4*)(c  + base + d);
    float4 pv = *(const float4*)(pe + base + d);
    float xk[4] = {cv.x + pv.x, cv.y + pv.y, cv.z + pv.z, cv.w + pv.w};
    float xv[4] = {cv.x, cv.y, cv.z, cv.w};

    float sk = xk[0]+xk[1]+xk[2]+xk[3];
    float ssk = xk[0]*xk[0]+xk[1]*xk[1]+xk[2]*xk[2]+xk[3]*xk[3];
    float sv = xv[0]+xv[1]+xv[2]+xv[3];
    float ssv = xv[0]*xv[0]+xv[1]*xv[1]+xv[2]*xv[2]+xv[3]*xv[3];
    block_reduce4(sk, ssk, sv, ssv);

    float mk = sk * (1.f / D_);
    float ik = rsqrtf(ssk * (1.f / D_) - mk*mk + 1e-5f);
    float mv = sv * (1.f / D_);
    float iv = rsqrtf(ssv * (1.f / D_) - mv*mv + 1e-5f);

    float4 g1v = *(const float4*)(g1 + d);
    float4 b1v = *(const float4*)(b1 + d);
    float4 g2v = *(const float4*)(g2 + d);
    float4 b2v = *(const float4*)(b2 + d);

    float k0 = (xk[0]-mk)*ik*g1v.x+b1v.x;
    float k1 = (xk[1]-mk)*ik*g1v.y+b1v.y;
    float k2 = (xk[2]-mk)*ik*g1v.z+b1v.z;
    float k3 = (xk[3]-mk)*ik*g1v.w+b1v.w;
    uint2 hk; hk.x = cvt2h(k0, k1); hk.y = cvt2h(k2, k3);
    *(uint2*)(kin + base + d) = hk;

    float v0 = (xv[0]-mv)*iv*g2v.x+b2v.x;
    float v1 = (xv[1]-mv)*iv*g2v.y+b2v.y;
    float v2 = (xv[2]-mv)*iv*g2v.z+b2v.z;
    float v3 = (xv[3]-mv)*iv*g2v.w+b2v.w;
    uint2 hv; hv.x = cvt2h(v0, v1); hv.y = cvt2h(v2, v3);
    *(uint2*)(vin + base + d) = hv;
}

__global__ __launch_bounds__(256) void head_kernel(const float* __restrict__ X,
                                                   const float* __restrict__ W,
                                                   const float* __restrict__ bias,
                                                   float* __restrict__ out)
{
    __shared__ float xs[D_];
    const int row = blockIdx.x;
    const size_t base = (size_t)row * D_;
    for (int t = threadIdx.x; t < D_ / 4; t += 256)
        *(float4*)&xs[t * 4] = *(const float4*)(X + base + t * 4);
    __syncthreads();

    int w = threadIdx.x >> 5, lane = threadIdx.x & 31;
    for (int col = w; col < VOCAB; col += 8) {
        float s = 0.f;
        for (int k = lane; k < D_; k += 32) s += xs[k] * W[(size_t)k * VOCAB + col];
#pragma unroll
        for (int o = 16; o > 0; o >>= 1) s += __shfl_down_sync(0xffffffffu, s, o);
        if (lane == 0) out[(size_t)row * VOCAB + col] = s + bias[col];
    }
}

// ---------------- host orchestration ----------------
static float* symaddr_f(const void* s)
{
    void* p = nullptr;
    cudaGetSymbolAddress(&p, s);
    return (float*)p;
}
static __half* symaddr_h(const void* s)
{
    void* p = nullptr;
    cudaGetSymbolAddress(&p, s);
    return (__half*)p;
}
static inline int pgrid(int nt) { return nt < 296 ? nt : 296; }

extern "C" void kernel_launch(void* const* d_in, const int* in_sizes, int n_in,
                              void* d_out, int out_size)
{
    const float* q_in   = (const float*)d_in[0];
    const float* c_in   = (const float*)d_in[1];
    const float* pe_in  = (const float*)d_in[2];
    const float* mod_w  = (const float*)d_in[3];
    const float* mod_b  = (const float*)d_in[4];
    const float* sa_qw  = (const float*)d_in[5];
    const float* sa_kw  = (const float*)d_in[6];
    const float* sa_vw  = (const float*)d_in[7];
    const float* sa_pw  = (const float*)d_in[8];
    const float* sa_pb  = (const float*)d_in[9];
    const float* ca_qw  = (const float*)d_in[10];
    const float* ca_kw  = (const float*)d_in[11];
    const float* ca_vw  = (const float*)d_in[12];
    const float* ca_pw  = (const float*)d_in[13];
    const float* ca_pb  = (const float*)d_in[14];
    const float* nk_g   = (const float*)d_in[15];
    const float* nk_b   = (const float*)d_in[16];
    const float* nv_g   = (const float*)d_in[17];
    const float* nv_b   = (const float*)d_in[18];
    const float* al_w   = (const float*)d_in[19];
    const float* al_b   = (const float*)d_in[20];
    const float* fc1_w  = (const float*)d_in[21];
    const float* fc1_b  = (const float*)d_in[22];
    const float* fc2_w  = (const float*)d_in[23];
    const float* fc2_b  = (const float*)d_in[24];
    const float* head_w = (const float*)d_in[25];
    const float* head_b = (const float*)d_in[26];
    const int*   pm     = (const int*)  d_in[27];
    float* out = (float*)d_out;

    __half* wth   = symaddr_h(g_wth);
    __half* wtl   = symaddr_h(g_wtl);
    __half* sc16  = symaddr_h(g_sc16);
    __half* q16   = symaddr_h(g_q16);
    __half* ao16  = symaddr_h(g_ao16);
    __half* kv16  = symaddr_h(g_kv16);
    __half* cat16 = symaddr_h(g_cat16);
    __half* h16   = symaddr_h(g_h16);

    float* mod  = symaddr_f(g_mod);
    float* qbuf = symaddr_f(g_q);
    float* qkv  = symaddr_f(g_qkv);
    float* qp   = symaddr_f(g_qp);
    float* kvp  = symaddr_f(g_kvp);
    float* po   = symaddr_f(g_po);
    float* q2   = symaddr_f(g_q2);
    float* alf  = symaddr_f(g_alf);

    cudaFuncSetAttribute(gemm_mma<0,0>, cudaFuncAttributeMaxDynamicSharedMemorySize, GEMM_SMEM);
    cudaFuncSetAttribute(gemm_mma<0,1>, cudaFuncAttributeMaxDynamicSharedMemorySize, GEMM_SMEM);
    cudaFuncSetAttribute(gemm_mma<1,2>, cudaFuncAttributeMaxDynamicSharedMemorySize, GEMM_SMEM);

    const int MQ = BATCH * NQ_;   // 8192
    const int MC = BATCH * SEQ;   // 4096
    const float scale = 0.125f;
    const size_t MODL = (size_t)MC * 6 * D_;
    const size_t DD   = (size_t)D_ * D_;
    const size_t MCD  = (size_t)MC * D_;

    const int ntQ   = (D_/128) * (MQ/128);        // 512
    const int ntQKV = (3*D_/128) * (MQ/128);      // 1536
    const int ntFc1 = (HID/128) * (MQ/128);       // 2048
    const int ntMod = (6*D_/128) * (MC/128) * 2;  // 3072
    const int ntKV  = (D_/128) * (MC/128) * 2;    // 512

    // #1-#3: prerequisites
    silu_h<<<(MC * D_ / 4 + 255) / 256, 256>>>(c_in, sc16, MC * D_ / 4);
    transpose_split<<<dim3(6*D_/32, D_/32, NLAYER), 256>>>(mod_w, wth + OFF_MOD, wtl + OFF_MOD, D_, 6*D_, (size_t)D_*6*D_, WPL);
    copy_h<<<(MQ * D_ / 4 + 255) / 256, 256>>>(q_in, qbuf, q16, MQ * D_ / 4);
    // #4-#6: all-layer mod GEMMs
    for (int ck = 0; ck < 3; ck++) {
        gemm_mma<0,0><<<pgrid(ntMod), 256, GEMM_SMEM>>>(
            sc16, wth + OFF_MOD + (size_t)(2*ck)*WPL, wtl + OFF_MOD + (size_t)(2*ck)*WPL,
            mod_b + (size_t)(2*ck)*6*D_, mod + (size_t)(2*ck)*MODL, nullptr,
            MC, 6*D_, D_, 6*D_, 0, WPL, (size_t)6*D_, MODL, ntMod);
    }

    // remaining weight transposes (z-batched over layers)
    transpose_split<<<dim3(32, 32, NLAYER), 256>>>(sa_qw, wth + OFF_SAQ,           wtl + OFF_SAQ,           D_, D_, DD, WPL);
    transpose_split<<<dim3(32, 32, NLAYER), 256>>>(sa_kw, wth + OFF_SAQ + 1048576, wtl + OFF_SAQ + 1048576, D_, D_, DD, WPL);
    transpose_split<<<dim3(32, 32, NLAYER), 256>>>(sa_vw, wth + OFF_SAQ + 2097152, wtl + OFF_SAQ + 2097152, D_, D_, DD, WPL);
    transpose_split<<<dim3(32, 32, NLAYER), 256>>>(sa_pw, wth + OFF_SAP, wtl + OFF_SAP, D_, D_, DD, WPL);
    transpose_split<<<dim3(32, 32, NLAYER), 256>>>(ca_qw, wth + OFF_CAQ, wtl + OFF_CAQ, D_, D_, DD, WPL);
    transpose_split<<<dim3(32, 32, NLAYER), 256>>>(ca_kw, wth + OFF_CAK, wtl + OFF_CAK, D_, D_, DD, WPL);
    transpose_split<<<dim3(32, 32, NLAYER), 256>>>(ca_vw, wth + OFF_CAV, wtl + OFF_CAV, D_, D_, DD, WPL);
    transpose_split<<<dim3(32, 32, NLAYER), 256>>>(ca_pw, wth + OFF_CAP, wtl + OFF_CAP, D_, D_, DD, WPL);
    transpose_split<<<dim3(32, 64, NLAYER), 256>>>(al_w, wth + OFF_AL, wtl + OFF_AL, 2*D_, D_, 2*DD, WPL);
    transpose_split<<<dim3(HID/32, 32, NLAYER), 256>>>(fc1_w, wth + OFF_FC1, wtl + OFF_FC1, D_, HID, (size_t)D_*HID, WPL);
    transpose_split<<<dim3(32, HID/32, NLAYER), 256>>>(fc2_w, wth + OFF_FC2, wtl + OFF_FC2, HID, D_, (size_t)HID*D_, WPL);

    for (int i = 0; i < NLAYER; i++) {
        size_t wb = (size_t)i * WPL;
        const float* modL = mod + (size_t)i * MODL;
        const float* spb = sa_pb + (size_t)i * D_;
        const float* cpb = ca_pb + (size_t)i * D_;
        const float* alb = al_b  + (size_t)i * D_;
        const float* f1b = fc1_b + (size_t)i * HID;
        const float* f2b = fc2_b + (size_t)i * D_;

        // ---- self-attention (fused QKV) ----
        gemm_mma<0,0><<<pgrid(ntQKV), 256, GEMM_SMEM>>>(q16, wth + wb + OFF_SAQ, wtl + wb + OFF_SAQ, nullptr, qkv, nullptr, MQ, 3*D_, D_, 3*D_, 0, 0, 0, 0, ntQKV);
        attn_kernel<<<BATCH*NHEAD, 256>>>(qkv, qkv + D_, qkv + 2*D_, pm, ao16, NQ_, 3*D_, 3*D_, 0, 1, scale);
        gemm_mma<0,0><<<pgrid(ntQ), 256, GEMM_SMEM>>>(ao16, wth + wb + OFF_SAP, wtl + wb + OFF_SAP, spb, po, nullptr, MQ, D_, D_, D_, 0, 0, 0, 0, ntQ);
        ln_mod_resid<<<MQ, 256>>>(qbuf, q16, cat16, po, modL, 0);

        // ---- cross attention ----
        ln_gamma2<<<MC, 256>>>(kv16, kv16 + MCD, c_in, pe_in,
                               nk_g + (size_t)i*D_, nk_b + (size_t)i*D_,
                               nv_g + (size_t)i*D_, nv_b + (size_t)i*D_);
        gemm_mma<0,0><<<pgrid(ntKV), 256, GEMM_SMEM>>>(
            kv16, wth + wb + OFF_CAK, wtl + wb + OFF_CAK, nullptr, kvp, nullptr,
            MC, D_, D_, D_, MCD, DD, 0, MCD, ntKV);
        gemm_mma<0,0><<<pgrid(ntQ), 256, GEMM_SMEM>>>(q16, wth + wb + OFF_CAQ, wtl + wb + OFF_CAQ, nullptr, qp, nullptr, MQ, D_, D_, D_, 0, 0, 0, 0, ntQ);
        attn_kernel<<<BATCH*NHEAD, 256>>>(qp, kvp, kvp + MCD, pm, ao16, SEQ, D_, D_, 1, 0, scale);
        gemm_mma<0,1><<<pgrid(ntQ), 256, GEMM_SMEM>>>(ao16, wth + wb + OFF_CAP, wtl + wb + OFF_CAP, cpb, q2, cat16, MQ, D_, D_, 2*D_, 0, 0, 0, 0, ntQ);

        // alpha = [q2, q] @ al_w + al_b  (single K=2048 GEMM)
        gemm_mma<0,0><<<pgrid(ntQ), 256, GEMM_SMEM>>>(cat16, wth + wb + OFF_AL, wtl + wb + OFF_AL, alb, alf, nullptr, MQ, D_, 2*D_, D_, 0, 0, 0, 0, ntQ);
        alpha_ln_mod<<<MQ, 256>>>(qbuf, q16, q2, alf, modL, 2*D_);

        // ---- MLP ----
        gemm_mma<1,2><<<pgrid(ntFc1), 256, GEMM_SMEM>>>(q16, wth + wb + OFF_FC1, wtl + wb + OFF_FC1, f1b, po, h16, MQ, HID, D_, HID, 0, 0, 0, 0, ntFc1);
        gemm_mma<0,0><<<pgrid(ntQ), 256, GEMM_SMEM>>>(h16, wth + wb + OFF_FC2, wtl + wb + OFF_FC2, f2b, po, nullptr, MQ, D_, HID, D_, 0, 0, 0, 0, ntQ);
        ln_mod_resid<<<MQ, 256>>>(qbuf, q16, nullptr, po, modL, 4*D_);
    }

    head_kernel<<<MQ, 256>>>(qbuf, head_w, head_b, out);
}

// round 13
// speedup vs baseline: 1.0752x; 1.0207x over previous
#include <cuda_runtime.h>
#include <cuda_fp16.h>
#include <cstdint>
#include <cstddef>

#define D_    1024
#define BATCH 32
#define SEQ   128
#define NQ_   256
#define HID   4096
#define NHEAD 16
#define NEGV  (-10000.0f)
#define NLAYER 6
#define VOCAB 18

// ---------------- portable PTX helpers (compute_103-safe) -------------------
__device__ __forceinline__ uint32_t smem_u32(const void* p) {
    uint32_t a;
    asm("{ .reg .u64 t; cvta.to.shared.u64 t, %1; cvt.u32.u64 %0, t; }"
        : "=r"(a) : "l"(p));
    return a;
}

#define CP16(s, g) \
    asm volatile("cp.async.cg.shared.global [%0], [%1], 16;" :: "r"(s), "l"(g))
#define CP_COMMIT() asm volatile("cp.async.commit_group;" ::: "memory")
#define CP_WAIT1()  asm volatile("cp.async.wait_group 1;" ::: "memory")
#define CP_WAIT0()  asm volatile("cp.async.wait_group 0;" ::: "memory")

#define LDSM_X4(r0, r1, r2, r3, addr) \
    asm volatile("ldmatrix.sync.aligned.m8n8.x4.shared.b16 {%0,%1,%2,%3}, [%4];" \
                 : "=r"(r0), "=r"(r1), "=r"(r2), "=r"(r3) : "r"(addr))

#define MMA16816(c, a0, a1, a2, a3, b0, b1) \
    asm volatile("mma.sync.aligned.m16n8k16.row.col.f32.f16.f16.f32 " \
                 "{%0,%1,%2,%3}, {%4,%5,%6,%7}, {%8,%9}, {%0,%1,%2,%3};" \
                 : "+f"((c)[0]), "+f"((c)[1]), "+f"((c)[2]), "+f"((c)[3]) \
                 : "r"(a0), "r"(a1), "r"(a2), "r"(a3), "r"(b0), "r"(b1))

__device__ __forceinline__ uint32_t cvt2h(float a, float b) {
    __half2 t = __floats2half2_rn(a, b);
    return *(uint32_t*)&t;
}
__device__ __forceinline__ void split2h(float a, float b, uint32_t& h, uint32_t& l) {
    __half ha = __float2half_rn(a);
    __half hb = __float2half_rn(b);
    __half la = __float2half_rn(a - __half2float(ha));
    __half lb = __float2half_rn(b - __half2float(hb));
    __half2 hh; hh.x = ha; hh.y = hb;
    __half2 ll; ll.x = la; ll.y = lb;
    h = *(uint32_t*)&hh;
    l = *(uint32_t*)&ll;
}

// ---------------- scratch (device globals; allocation-free) ----------------
#define WPL 25165824ULL
#define OFF_MOD 0ULL
#define OFF_SAQ 6291456ULL
#define OFF_SAP 9437184ULL
#define OFF_CAQ 10485760ULL
#define OFF_CAK 11534336ULL
#define OFF_CAV 12582912ULL
#define OFF_CAP 13631488ULL
#define OFF_AL  14680064ULL
#define OFF_FC1 16777216ULL
#define OFF_FC2 20971520ULL

__device__ __half g_wth[NLAYER * WPL];
__device__ __half g_wtl[NLAYER * WPL];
__device__ __half g_sc16 [BATCH*SEQ*D_];
__device__ __half g_q16  [BATCH*NQ_*D_];
__device__ __half g_ao16 [BATCH*NQ_*D_];
__device__ __half g_kv16 [2*BATCH*SEQ*D_];
__device__ __half g_cat16[BATCH*NQ_*2*D_];
__device__ __half g_h16  [BATCH*NQ_*HID];

__device__ float g_mod[NLAYER*BATCH*SEQ*6*D_];
__device__ float g_q  [BATCH*NQ_*D_];
__device__ float g_qkv[BATCH*NQ_*3*D_];
__device__ float g_qp [BATCH*NQ_*D_];
__device__ float g_kvp[2*BATCH*SEQ*D_];
__device__ float g_po [BATCH*NQ_*D_];
__device__ float g_q2 [BATCH*NQ_*D_];
__device__ float g_alf[BATCH*NQ_*D_];

// ---------------- weight transpose + fp16 hi/lo split (z-batched) ----------
__global__ __launch_bounds__(256) void transpose_split(const float* __restrict__ W,
                                                       __half* __restrict__ oh,
                                                       __half* __restrict__ ol,
                                                       int K, int N,
                                                       size_t ils, size_t ols)
{
    __shared__ float t[32][33];
    const int z = blockIdx.z;
    W  += (size_t)z * ils;
    oh += (size_t)z * ols;
    ol += (size_t)z * ols;
    const int n0 = blockIdx.x * 32, k0 = blockIdx.y * 32;
    const int tx = threadIdx.x & 31, ty = threadIdx.x >> 5;
#pragma unroll
    for (int r = 0; r < 4; r++)
        t[ty + 8*r][tx] = W[(size_t)(k0 + ty + 8*r) * N + n0 + tx];
    __syncthreads();
#pragma unroll
    for (int s = 0; s < 2; s++) {
        int id = threadIdx.x + s * 256;
        int n  = id >> 4;
        int kp = (id & 15) * 2;
        uint32_t h, l;
        split2h(t[kp][n], t[kp + 1][n], h, l);
        size_t o = (size_t)(n0 + n) * K + k0 + kp;
        *(uint32_t*)(oh + o) = h;
        *(uint32_t*)(ol + o) = l;
    }
}

__global__ void silu_h(const float* __restrict__ x, __half* __restrict__ oh, int n4)
{
    int i = blockIdx.x * blockDim.x + threadIdx.x;
    if (i >= n4) return;
    float4 v = ((const float4*)x)[i];
    float f[4] = {v.x, v.y, v.z, v.w};
#pragma unroll
    for (int j = 0; j < 4; j++) f[j] = f[j] / (1.f + expf(-f[j]));
    uint2 hh; hh.x = cvt2h(f[0], f[1]); hh.y = cvt2h(f[2], f[3]);
    *(uint2*)(oh + 4*(size_t)i) = hh;
}

__global__ void copy_h(const float* __restrict__ x, float* __restrict__ o,
                       __half* __restrict__ oh, int n4)
{
    int i = blockIdx.x * blockDim.x + threadIdx.x;
    if (i >= n4) return;
    float4 v = ((const float4*)x)[i];
    ((float4*)o)[i] = v;
    uint2 hh; hh.x = cvt2h(v.x, v.y); hh.y = cvt2h(v.z, v.w);
    *(uint2*)(oh + 4*(size_t)i) = hh;
}

// ---------------- persistent HMMA GEMM (2-term fp16 split, BK=64) -----------
// Warp tile 64Mx32N (warps 2x4): 8 LDSM_X4 per K16-step instead of 10
// (-20% smem read traffic). B (h+l) held per-step; A streams per-fragment.
// OUT: 0 = fp32 only, 1 = fp32 + fp16, 2 = fp16 only
#define AS 72
#define TILE_B (128 * AS * 2)       // 18432 B
#define BUF_B  (3 * TILE_B)         // 55296 B (A, Bh, Bl)
#define GEMM_SMEM (2 * BUF_B)       // 110592 B

template<int ACT, int OUT>
__global__ __launch_bounds__(256, 2) void gemm_mma(const __half* __restrict__ A,
                                                   const __half* __restrict__ Bh,
                                                   const __half* __restrict__ Bl,
                                                   const float* __restrict__ bias,
                                                   float* __restrict__ C,
                                                   __half* __restrict__ Ch,
                                                   int M, int N, int K, int cn,
                                                   size_t azs, size_t bzs,
                                                   size_t biaszs, size_t czs,
                                                   int ntiles)
{
    extern __shared__ __align__(128) char dynsm[];
    const uint32_t sb0 = smem_u32(dynsm);
    const int nx = N >> 7, ny = M >> 7;

    const int tid  = threadIdx.x;
    const int lane = tid & 31;
    const int wid  = tid >> 5;
    const int wm   = wid & 1;      // 2 strips of 64 rows
    const int wn   = wid >> 1;     // 4 strips of 32 cols

    const int lr  = tid >> 3;
    const int lcs = (tid & 7) * 8;
    const uint32_t so = (uint32_t)(lr * AS + lcs) * 2;
    const uint32_t SOSTEP = 32u * AS * 2;
    const size_t rstep = (size_t)32 * K;
    const int nch = K >> 6;       // even for all our Ks (1024/2048/4096)

    int t = blockIdx.x;
    int bx = t % nx, rr = t / nx, by = rr % ny, bz = rr / ny;
    const __half* gA  = A  + (size_t)bz * azs + (size_t)(by * 128 + lr) * K + lcs;
    const __half* gBh = Bh + (size_t)bz * bzs + (size_t)(bx * 128 + lr) * K + lcs;
    const __half* gBl = Bl + (size_t)bz * bzs + (size_t)(bx * 128 + lr) * K + lcs;

    // prefetch chunk 0 of first tile
#pragma unroll
    for (int tt = 0; tt < 4; tt++) {
        CP16(sb0 + 0*TILE_B + so + tt*SOSTEP, gA  + tt*rstep);
        CP16(sb0 + 1*TILE_B + so + tt*SOSTEP, gBh + tt*rstep);
        CP16(sb0 + 2*TILE_B + so + tt*SOSTEP, gBl + tt*rstep);
    }
    CP_COMMIT();

    // ldmatrix lane addressing
    const uint32_t a_row = (uint32_t)(wm * 64 + (lane & 15));            // + i*16
    const uint32_t a_kb  = (uint32_t)((lane >> 4) * 16);
    const uint32_t b_row = (uint32_t)(wn * 32 + (lane & 7) + ((lane >> 4) << 3)); // + np*16
    const uint32_t b_kb  = (uint32_t)(((lane >> 3) & 1) * 16);

    while (true) {
        float acc[4][4][4];
#pragma unroll
        for (int i = 0; i < 4; i++)
#pragma unroll
            for (int n = 0; n < 4; n++)
#pragma unroll
                for (int j = 0; j < 4; j++) acc[i][n][j] = 0.f;

        const bool has_next = (t + (int)gridDim.x < ntiles);

        for (int c = 0; c < nch; c++) {
            if (c + 1 < nch) {
                const int k1 = (c + 1) << 6;
                uint32_t sb = sb0 + ((c + 1) & 1) * BUF_B;
#pragma unroll
                for (int tt = 0; tt < 4; tt++) {
                    CP16(sb + 0*TILE_B + so + tt*SOSTEP, gA  + tt*rstep + k1);
                    CP16(sb + 1*TILE_B + so + tt*SOSTEP, gBh + tt*rstep + k1);
                    CP16(sb + 2*TILE_B + so + tt*SOSTEP, gBl + tt*rstep + k1);
                }
                CP_COMMIT();
                CP_WAIT1();
            } else if (has_next) {
                const int tn = t + gridDim.x;
                const int nbx = tn % nx; int r2 = tn / nx;
                const int nby = r2 % ny, nbz = r2 / ny;
                const __half* nA  = A  + (size_t)nbz * azs + (size_t)(nby * 128 + lr) * K + lcs;
                const __half* nBh = Bh + (size_t)nbz * bzs + (size_t)(nbx * 128 + lr) * K + lcs;
                const __half* nBl = Bl + (size_t)nbz * bzs + (size_t)(nbx * 128 + lr) * K + lcs;
#pragma unroll
                for (int tt = 0; tt < 4; tt++) {
                    CP16(sb0 + 0*TILE_B + so + tt*SOSTEP, nA  + tt*rstep);
                    CP16(sb0 + 1*TILE_B + so + tt*SOSTEP, nBh + tt*rstep);
                    CP16(sb0 + 2*TILE_B + so + tt*SOSTEP, nBl + tt*rstep);
                }
                CP_COMMIT();
                CP_WAIT1();
            } else {
                CP_WAIT0();
            }
            __syncthreads();

            const uint32_t sb  = sb0 + (c & 1) * BUF_B;
            const uint32_t sA  = sb + 0*TILE_B;
            const uint32_t sBh = sb + 1*TILE_B;
            const uint32_t sBl = sb + 2*TILE_B;

#pragma unroll
            for (int ks = 0; ks < 4; ks++) {
                const uint32_t kb = (uint32_t)(ks * 32);
                // hold B fragments (h+l, 2 np slices) for this K16 step
                uint32_t bh[2][4], bl[2][4];
#pragma unroll
                for (int np = 0; np < 2; np++) {
                    uint32_t boff = (b_row + np * 16) * (AS * 2) + kb + b_kb;
                    LDSM_X4(bh[np][0], bh[np][1], bh[np][2], bh[np][3], sBh + boff);
                    LDSM_X4(bl[np][0], bl[np][1], bl[np][2], bl[np][3], sBl + boff);
                }
                // stream A fragments
#pragma unroll
                for (int i = 0; i < 4; i++) {
                    uint32_t a0, a1, a2, a3;
                    uint32_t aoff = (a_row + i * 16) * (AS * 2) + kb + a_kb;
                    LDSM_X4(a0, a1, a2, a3, sA + aoff);
                    MMA16816(acc[i][0], a0, a1, a2, a3, bh[0][0], bh[0][1]);
                    MMA16816(acc[i][1], a0, a1, a2, a3, bh[0][2], bh[0][3]);
                    MMA16816(acc[i][2], a0, a1, a2, a3, bh[1][0], bh[1][1]);
                    MMA16816(acc[i][3], a0, a1, a2, a3, bh[1][2], bh[1][3]);
                    MMA16816(acc[i][0], a0, a1, a2, a3, bl[0][0], bl[0][1]);
                    MMA16816(acc[i][1], a0, a1, a2, a3, bl[0][2], bl[0][3]);
                    MMA16816(acc[i][2], a0, a1, a2, a3, bl[1][0], bl[1][1]);
                    MMA16816(acc[i][3], a0, a1, a2, a3, bl[1][2], bl[1][3]);
                }
            }
            __syncthreads();
        }

        // epilogue for tile (bx, by, bz); next tile's chunk-0 load in flight
        {
            const float* biasp = bias ? (bias + (size_t)bz * biaszs) : nullptr;
            float* Cp = C + (size_t)bz * czs;
            __half* Chp = (OUT >= 1) ? (Ch + (size_t)bz * czs) : nullptr;
            const int m0 = by * 128, n0 = bx * 128;
#pragma unroll
            for (int i = 0; i < 4; i++) {
                const int r0 = m0 + wm * 64 + i * 16 + (lane >> 2);
#pragma unroll
                for (int nt = 0; nt < 4; nt++) {
                    const int col = n0 + wn * 32 + nt * 8 + (lane & 3) * 2;
#pragma unroll
                    for (int half = 0; half < 2; half++) {
                        const int r = r0 + half * 8;
                        float v0 = acc[i][nt][half * 2 + 0];
                        float v1 = acc[i][nt][half * 2 + 1];
                        if (biasp) { v0 += biasp[col]; v1 += biasp[col + 1]; }
                        if (ACT == 1) {
                            v0 = 0.5f * v0 * (1.0f + erff(v0 * 0.70710678118654752f));
                            v1 = 0.5f * v1 * (1.0f + erff(v1 * 0.70710678118654752f));
                        }
                        if (OUT != 2) {
                            float2 o; o.x = v0; o.y = v1;
                            *(float2*)(Cp + (size_t)r * N + col) = o;
                        }
                        if (OUT >= 1)
                            *(uint32_t*)(Chp + (size_t)r * cn + col) = cvt2h(v0, v1);
                    }
                }
            }
        }

        if (!has_next) break;
        t += gridDim.x;
        bx = t % nx; rr = t / nx; by = rr % ny; bz = rr / ny;
        gA  = A  + (size_t)bz * azs + (size_t)(by * 128 + lr) * K + lcs;
        gBh = Bh + (size_t)bz * bzs + (size_t)(bx * 128 + lr) * K + lcs;
        gBl = Bl + (size_t)bz * bzs + (size_t)(bx * 128 + lr) * K + lcs;
    }
}

// ---------------- attention (ILP dot + rare-rescale softmax) ----------------
__global__ __launch_bounds__(256) void attn_kernel(const float* __restrict__ Q,
                                                   const float* __restrict__ Kp,
                                                   const float* __restrict__ Vp,
                                                   const int* __restrict__ pm,
                                                   __half* __restrict__ Oh,
                                                   int NK, int qst, int kvst,
                                                   int rshift, int pmshift, float scale)
{
    __shared__ float Ks[64][64];
    __shared__ float Vs[64][64];

    const int bh = blockIdx.x;
    const int b  = bh >> 4;
    const int h  = bh & 15;
    const float* qb = Q  + (size_t)b * NQ_ * qst  + h * 64;
    const float* kb = Kp + (size_t)b * NK  * kvst + h * 64;
    const float* vb = Vp + (size_t)b * NK  * kvst + h * 64;
    const int r = threadIdx.x;

    float qr[64];
#pragma unroll
    for (int k4 = 0; k4 < 16; k4++) {
        float4 v = *(const float4*)(qb + (size_t)r * qst + k4 * 4);
        qr[k4*4+0] = v.x; qr[k4*4+1] = v.y; qr[k4*4+2] = v.z; qr[k4*4+3] = v.w;
    }

    float m = -1e30f, l = 0.f;
    float o[64];
#pragma unroll
    for (int k = 0; k < 64; k++) o[k] = 0.f;

    const int maxj = r >> rshift;

    for (int c0 = 0; c0 < NK; c0 += 64) {
        __syncthreads();
        for (int t = threadIdx.x; t < 1024; t += 256) {
            int j = t >> 4;
            int c = (t & 15) << 2;
            *(float4*)&Ks[j][c] = *(const float4*)(kb + (size_t)(c0 + j) * kvst + c);
            *(float4*)&Vs[j][c] = *(const float4*)(vb + (size_t)(c0 + j) * kvst + c);
        }
        __syncthreads();

        int jend = maxj - c0;
        if (jend > 63) jend = 63;
        for (int j = 0; j <= jend; j++) {
            float d0 = 0.f, d1 = 0.f, d2 = 0.f, d3 = 0.f;
#pragma unroll
            for (int k = 0; k < 64; k += 4) {
                d0 += qr[k+0] * Ks[j][k+0];
                d1 += qr[k+1] * Ks[j][k+1];
                d2 += qr[k+2] * Ks[j][k+2];
                d3 += qr[k+3] * Ks[j][k+3];
            }
            int gj = c0 + j;
            float sc = ((d0 + d1) + (d2 + d3)) * scale
                     + NEGV * (float)pm[b * SEQ + (gj >> pmshift)];
            if (sc > m) {
                float corr = expf(m - sc);
                l = l * corr + 1.f;
#pragma unroll
                for (int k = 0; k < 64; k++) o[k] = o[k] * corr + Vs[j][k];
                m = sc;
            } else {
                float p = expf(sc - m);
                l += p;
#pragma unroll
                for (int k = 0; k < 64; k++) o[k] += p * Vs[j][k];
            }
        }
    }

    float inv = 1.f / l;
    const size_t obase = ((size_t)b * NQ_ + r) * D_ + h * 64;
#pragma unroll
    for (int k2 = 0; k2 < 32; k2++)
        *(uint32_t*)(Oh + obase + k2*2) = cvt2h(o[k2*2] * inv, o[k2*2+1] * inv);
}

// ---------------- LN helpers ----------------
__device__ __forceinline__ void block_reduce2(float& a, float& b)
{
    __shared__ float sa[8], sb[8];
    const unsigned full = 0xffffffffu;
#pragma unroll
    for (int o = 16; o > 0; o >>= 1) {
        a += __shfl_down_sync(full, a, o);
        b += __shfl_down_sync(full, b, o);
    }
    int w = threadIdx.x >> 5, lane = threadIdx.x & 31;
    if (lane == 0) { sa[w] = a; sb[w] = b; }
    __syncthreads();
    float ta = 0.f, tb = 0.f;
#pragma unroll
    for (int i = 0; i < 8; i++) { ta += sa[i]; tb += sb[i]; }
    a = ta; b = tb;
}

__device__ __forceinline__ void block_reduce4(float& a, float& b, float& c, float& d)
{
    __shared__ float s4[8][4];
    const unsigned full = 0xffffffffu;
#pragma unroll
    for (int o = 16; o > 0; o >>= 1) {
        a += __shfl_down_sync(full, a, o);
        b += __shfl_down_sync(full, b, o);
        c += __shfl_down_sync(full, c, o);
        d += __shfl_down_sync(full, d, o);
    }
    int w = threadIdx.x >> 5, lane = threadIdx.x & 31;
    if (lane == 0) { s4[w][0] = a; s4[w][1] = b; s4[w][2] = c; s4[w][3] = d; }
    __syncthreads();
    float ta = 0.f, tb = 0.f, tc = 0.f, td = 0.f;
#pragma unroll
    for (int i = 0; i < 8; i++) {
        ta += s4[i][0]; tb += s4[i][1]; tc += s4[i][2]; td += s4[i][3];
    }
    a = ta; b = tb; c = tc; d = td;
}

// q = LN(q + add) * (1+s) + sh ; fp16 mirror (+ optional concat copy)
__global__ __launch_bounds__(256) void ln_mod_resid(float* __restrict__ q,
                                                    __half* __restrict__ qh,
                                                    __half* __restrict__ qcat,
                                                    const float* __restrict__ add,
                                                    const float* __restrict__ mod,
                                                    int off)
{
    const int row = blockIdx.x;
    const int b = row >> 8, n = row & 255;
    const float* mp = mod + ((size_t)(b * SEQ + (n >> 1))) * (6 * D_) + off;
    const size_t base = (size_t)row * D_;
    const int d = threadIdx.x * 4;

    float4 xv = *(const float4*)(q + base + d);
    float4 av = *(const float4*)(add + base + d);
    float x[4] = {xv.x + av.x, xv.y + av.y, xv.z + av.z, xv.w + av.w};

    float s  = x[0] + x[1] + x[2] + x[3];
    float ss = x[0]*x[0] + x[1]*x[1] + x[2]*x[2] + x[3]*x[3];
    block_reduce2(s, ss);
    float mean = s * (1.f / D_);
    float var  = ss * (1.f / D_) - mean * mean;
    float inv  = rsqrtf(var + 1e-6f);

    float4 sv  = *(const float4*)(mp + d);
    float4 shv = *(const float4*)(mp + D_ + d);
    float y0 = (x[0]-mean)*inv*(1.f+sv.x)+shv.x;
    float y1 = (x[1]-mean)*inv*(1.f+sv.y)+shv.y;
    float y2 = (x[2]-mean)*inv*(1.f+sv.z)+shv.z;
    float y3 = (x[3]-mean)*inv*(1.f+sv.w)+shv.w;
    float4 o; o.x = y0; o.y = y1; o.z = y2; o.w = y3;
    *(float4*)(q + base + d) = o;
    uint2 hh; hh.x = cvt2h(y0, y1); hh.y = cvt2h(y2, y3);
    *(uint2*)(qh + base + d) = hh;
    if (qcat)
        *(uint2*)(qcat + (size_t)row * (2*D_) + D_ + d) = hh;
}

// q = LN((1+al)*q2 + q) * (1+s) + sh ; fp16 mirror
__global__ __launch_bounds__(256) void alpha_ln_mod(float* __restrict__ q,
                                                    __half* __restrict__ qh,
                                                    const float* __restrict__ q2,
                                                    const float* __restrict__ al,
                                                    const float* __restrict__ mod,
                                                    int off)
{
    const int row = blockIdx.x;
    const int b = row >> 8, n = row & 255;
    const float* mp = mod + ((size_t)(b * SEQ + (n >> 1))) * (6 * D_) + off;
    const size_t base = (size_t)row * D_;
    const int d = threadIdx.x * 4;

    float4 qv  = *(const float4*)(q  + base + d);
    float4 q2v = *(const float4*)(q2 + base + d);
    float4 alv = *(const float4*)(al + base + d);
    float x[4];
    x[0] = (1.f+alv.x)*q2v.x + qv.x;
    x[1] = (1.f+alv.y)*q2v.y + qv.y;
    x[2] = (1.f+alv.z)*q2v.z + qv.z;
    x[3] = (1.f+alv.w)*q2v.w + qv.w;

    float s  = x[0] + x[1] + x[2] + x[3];
    float ss = x[0]*x[0] + x[1]*x[1] + x[2]*x[2] + x[3]*x[3];
    block_reduce2(s, ss);
    float mean = s * (1.f / D_);
    float var  = ss * (1.f / D_) - mean * mean;
    float inv  = rsqrtf(var + 1e-6f);

    float4 sv  = *(const float4*)(mp + d);
    float4 shv = *(const float4*)(mp + D_ + d);
    float y0 = (x[0]-mean)*inv*(1.f+sv.x)+shv.x;
    float y1 = (x[1]-mean)*inv*(1.f+sv.y)+shv.y;
    float y2 = (x[2]-mean)*inv*(1.f+sv.z)+shv.z;
    float y3 = (x[3]-mean)*inv*(1.f+sv.w)+shv.w;
    float4 o; o.x = y0; o.y = y1; o.z = y2; o.w = y3;
    *(float4*)(q + base + d) = o;
    uint2 hh; hh.x = cvt2h(y0, y1); hh.y = cvt2h(y2, y3);
    *(uint2*)(qh + base + d) = hh;
}

// fused: kin = fp16(LN(c+pe)*g1+b1), vin = fp16(LN(c)*g2+b2), eps=1e-5
__global__ __launch_bounds__(256) void ln_gamma2(__half* __restrict__ kin,
                                                 __half* __restrict__ vin,
                                                 const float* __restrict__ c,
                                                 const float* __restrict__ pe,
                                                 const float* __restrict__ g1,
                                                 const float* __restrict__ b1,
                                                 const float* __restrict__ g2,
                                                 const float* __restrict__ b2)
{
    const int row = blockIdx.x;
    const size_t base = (size_t)row * D_;
    const int d = threadIdx.x * 4;

    float4 cv = *(const float4*)(c  + base + d);
    float4 pv = *(const float4*)(pe + base + d);
    float xk[4] = {cv.x + pv.x, cv.y + pv.y, cv.z + pv.z, cv.w + pv.w};
    float xv[4] = {cv.x, cv.y, cv.z, cv.w};

    float sk = xk[0]+xk[1]+xk[2]+xk[3];
    float ssk = xk[0]*xk[0]+xk[1]*xk[1]+xk[2]*xk[2]+xk[3]*xk[3];
    float sv = xv[0]+xv[1]+xv[2]+xv[3];
    float ssv = xv[0]*xv[0]+xv[1]*xv[1]+xv[2]*xv[2]+xv[3]*xv[3];
    block_reduce4(sk, ssk, sv, ssv);

    float mk = sk * (1.f / D_);
    float ik = rsqrtf(ssk * (1.f / D_) - mk*mk + 1e-5f);
    float mv = sv * (1.f / D_);
    float iv = rsqrtf(ssv * (1.f / D_) - mv*mv + 1e-5f);

    float4 g1v = *(const float4*)(g1 + d);
    float4 b1v = *(const float4*)(b1 + d);
    float4 g2v = *(const float4*)(g2 + d);
    float4 b2v = *(const float4*)(b2 + d);

    float k0 = (xk[0]-mk)*ik*g1v.x+b1v.x;
    float k1 = (xk[1]-mk)*ik*g1v.y+b1v.y;
    float k2 = (xk[2]-mk)*ik*g1v.z+b1v.z;
    float k3 = (xk[3]-mk)*ik*g1v.w+b1v.w;
    uint2 hk; hk.x = cvt2h(k0, k1); hk.y = cvt2h(k2, k3);
    *(uint2*)(kin + base + d) = hk;

    float v0 = (xv[0]-mv)*iv*g2v.x+b2v.x;
    float v1 = (xv[1]-mv)*iv*g2v.y+b2v.y;
    float v2 = (xv[2]-mv)*iv*g2v.z+b2v.z;
    float v3 = (xv[3]-mv)*iv*g2v.w+b2v.w;
    uint2 hv; hv.x = cvt2h(v0, v1); hv.y = cvt2h(v2, v3);
    *(uint2*)(vin + base + d) = hv;
}

__global__ __launch_bounds__(256) void head_kernel(const float* __restrict__ X,
                                                   const float* __restrict__ W,
                                                   const float* __restrict__ bias,
                                                   float* __restrict__ out)
{
    __shared__ float xs[D_];
    const int row = blockIdx.x;
    const size_t base = (size_t)row * D_;
    for (int t = threadIdx.x; t < D_ / 4; t += 256)
        *(float4*)&xs[t * 4] = *(const float4*)(X + base + t * 4);
    __syncthreads();

    int w = threadIdx.x >> 5, lane = threadIdx.x & 31;
    for (int col = w; col < VOCAB; col += 8) {
        float s = 0.f;
        for (int k = lane; k < D_; k += 32) s += xs[k] * W[(size_t)k * VOCAB + col];
#pragma unroll
        for (int o = 16; o > 0; o >>= 1) s += __shfl_down_sync(0xffffffffu, s, o);
        if (lane == 0) out[(size_t)row * VOCAB + col] = s + bias[col];
    }
}

// ---------------- host orchestration ----------------
static float* symaddr_f(const void* s)
{
    void* p = nullptr;
    cudaGetSymbolAddress(&p, s);
    return (float*)p;
}
static __half* symaddr_h(const void* s)
{
    void* p = nullptr;
    cudaGetSymbolAddress(&p, s);
    return (__half*)p;
}
static inline int pgrid(int nt) { return nt < 296 ? nt : 296; }

extern "C" void kernel_launch(void* const* d_in, const int* in_sizes, int n_in,
                              void* d_out, int out_size)
{
    const float* q_in   = (const float*)d_in[0];
    const float* c_in   = (const float*)d_in[1];
    const float* pe_in  = (const float*)d_in[2];
    const float* mod_w  = (const float*)d_in[3];
    const float* mod_b  = (const float*)d_in[4];
    const float* sa_qw  = (const float*)d_in[5];
    const float* sa_kw  = (const float*)d_in[6];
    const float* sa_vw  = (const float*)d_in[7];
    const float* sa_pw  = (const float*)d_in[8];
    const float* sa_pb  = (const float*)d_in[9];
    const float* ca_qw  = (const float*)d_in[10];
    const float* ca_kw  = (const float*)d_in[11];
    const float* ca_vw  = (const float*)d_in[12];
    const float* ca_pw  = (const float*)d_in[13];
    const float* ca_pb  = (const float*)d_in[14];
    const float* nk_g   = (const float*)d_in[15];
    const float* nk_b   = (const float*)d_in[16];
    const float* nv_g   = (const float*)d_in[17];
    const float* nv_b   = (const float*)d_in[18];
    const float* al_w   = (const float*)d_in[19];
    const float* al_b   = (const float*)d_in[20];
    const float* fc1_w  = (const float*)d_in[21];
    const float* fc1_b  = (const float*)d_in[22];
    const float* fc2_w  = (const float*)d_in[23];
    const float* fc2_b  = (const float*)d_in[24];
    const float* head_w = (const float*)d_in[25];
    const float* head_b = (const float*)d_in[26];
    const int*   pm     = (const int*)  d_in[27];
    float* out = (float*)d_out;

    __half* wth   = symaddr_h(g_wth);
    __half* wtl   = symaddr_h(g_wtl);
    __half* sc16  = symaddr_h(g_sc16);
    __half* q16   = symaddr_h(g_q16);
    __half* ao16  = symaddr_h(g_ao16);
    __half* kv16  = symaddr_h(g_kv16);
    __half* cat16 = symaddr_h(g_cat16);
    __half* h16   = symaddr_h(g_h16);

    float* mod  = symaddr_f(g_mod);
    float* qbuf = symaddr_f(g_q);
    float* qkv  = symaddr_f(g_qkv);
    float* qp   = symaddr_f(g_qp);
    float* kvp  = symaddr_f(g_kvp);
    float* po   = symaddr_f(g_po);
    float* q2   = symaddr_f(g_q2);
    float* alf  = symaddr_f(g_alf);

    cudaFuncSetAttribute(gemm_mma<0,0>, cudaFuncAttributeMaxDynamicSharedMemorySize, GEMM_SMEM);
    cudaFuncSetAttribute(gemm_mma<0,1>, cudaFuncAttributeMaxDynamicSharedMemorySize, GEMM_SMEM);
    cudaFuncSetAttribute(gemm_mma<1,2>, cudaFuncAttributeMaxDynamicSharedMemorySize, GEMM_SMEM);

    const int MQ = BATCH * NQ_;   // 8192
    const int MC = BATCH * SEQ;   // 4096
    const float scale = 0.125f;
    const size_t MODL = (size_t)MC * 6 * D_;
    const size_t DD   = (size_t)D_ * D_;
    const size_t MCD  = (size_t)MC * D_;

    const int ntQ   = (D_/128) * (MQ/128);        // 512
    const int ntQKV = (3*D_/128) * (MQ/128);      // 1536
    const int ntFc1 = (HID/128) * (MQ/128);       // 2048
    const int ntMod = (6*D_/128) * (MC/128) * 2;  // 3072
    const int ntKV  = (D_/128) * (MC/128) * 2;    // 512

    // #1-#3: prerequisites
    silu_h<<<(MC * D_ / 4 + 255) / 256, 256>>>(c_in, sc16, MC * D_ / 4);
    transpose_split<<<dim3(6*D_/32, D_/32, NLAYER), 256>>>(mod_w, wth + OFF_MOD, wtl + OFF_MOD, D_, 6*D_, (size_t)D_*6*D_, WPL);
    copy_h<<<(MQ * D_ / 4 + 255) / 256, 256>>>(q_in, qbuf, q16, MQ * D_ / 4);
    // #4-#6: all-layer mod GEMMs
    for (int ck = 0; ck < 3; ck++) {
        gemm_mma<0,0><<<pgrid(ntMod), 256, GEMM_SMEM>>>(
            sc16, wth + OFF_MOD + (size_t)(2*ck)*WPL, wtl + OFF_MOD + (size_t)(2*ck)*WPL,
            mod_b + (size_t)(2*ck)*6*D_, mod + (size_t)(2*ck)*MODL, nullptr,
            MC, 6*D_, D_, 6*D_, 0, WPL, (size_t)6*D_, MODL, ntMod);
    }

    // remaining weight transposes (z-batched over layers)
    transpose_split<<<dim3(32, 32, NLAYER), 256>>>(sa_qw, wth + OFF_SAQ,           wtl + OFF_SAQ,           D_, D_, DD, WPL);
    transpose_split<<<dim3(32, 32, NLAYER), 256>>>(sa_kw, wth + OFF_SAQ + 1048576, wtl + OFF_SAQ + 1048576, D_, D_, DD, WPL);
    transpose_split<<<dim3(32, 32, NLAYER), 256>>>(sa_vw, wth + OFF_SAQ + 2097152, wtl + OFF_SAQ + 2097152, D_, D_, DD, WPL);
    transpose_split<<<dim3(32, 32, NLAYER), 256>>>(sa_pw, wth + OFF_SAP, wtl + OFF_SAP, D_, D_, DD, WPL);
    transpose_split<<<dim3(32, 32, NLAYER), 256>>>(ca_qw, wth + OFF_CAQ, wtl + OFF_CAQ, D_, D_, DD, WPL);
    transpose_split<<<dim3(32, 32, NLAYER), 256>>>(ca_kw, wth + OFF_CAK, wtl + OFF_CAK, D_, D_, DD, WPL);
    transpose_split<<<dim3(32, 32, NLAYER), 256>>>(ca_vw, wth + OFF_CAV, wtl + OFF_CAV, D_, D_, DD, WPL);
    transpose_split<<<dim3(32, 32, NLAYER), 256>>>(ca_pw, wth + OFF_CAP, wtl + OFF_CAP, D_, D_, DD, WPL);
    transpose_split<<<dim3(32, 64, NLAYER), 256>>>(al_w, wth + OFF_AL, wtl + OFF_AL, 2*D_, D_, 2*DD, WPL);
    transpose_split<<<dim3(HID/32, 32, NLAYER), 256>>>(fc1_w, wth + OFF_FC1, wtl + OFF_FC1, D_, HID, (size_t)D_*HID, WPL);
    transpose_split<<<dim3(32, HID/32, NLAYER), 256>>>(fc2_w, wth + OFF_FC2, wtl + OFF_FC2, HID, D_, (size_t)HID*D_, WPL);

    for (int i = 0; i < NLAYER; i++) {
        size_t wb = (size_t)i * WPL;
        const float* modL = mod + (size_t)i * MODL;
        const float* spb = sa_pb + (size_t)i * D_;
        const float* cpb = ca_pb + (size_t)i * D_;
        const float* alb = al_b  + (size_t)i * D_;
        const float* f1b = fc1_b + (size_t)i * HID;
        const float* f2b = fc2_b + (size_t)i * D_;

        // ---- self-attention (fused QKV) ----
        gemm_mma<0,0><<<pgrid(ntQKV), 256, GEMM_SMEM>>>(q16, wth + wb + OFF_SAQ, wtl + wb + OFF_SAQ, nullptr, qkv, nullptr, MQ, 3*D_, D_, 3*D_, 0, 0, 0, 0, ntQKV);
        attn_kernel<<<BATCH*NHEAD, 256>>>(qkv, qkv + D_, qkv + 2*D_, pm, ao16, NQ_, 3*D_, 3*D_, 0, 1, scale);
        gemm_mma<0,0><<<pgrid(ntQ), 256, GEMM_SMEM>>>(ao16, wth + wb + OFF_SAP, wtl + wb + OFF_SAP, spb, po, nullptr, MQ, D_, D_, D_, 0, 0, 0, 0, ntQ);
        ln_mod_resid<<<MQ, 256>>>(qbuf, q16, cat16, po, modL, 0);

        // ---- cross attention ----
        ln_gamma2<<<MC, 256>>>(kv16, kv16 + MCD, c_in, pe_in,
                               nk_g + (size_t)i*D_, nk_b + (size_t)i*D_,
                               nv_g + (size_t)i*D_, nv_b + (size_t)i*D_);
        gemm_mma<0,0><<<pgrid(ntKV), 256, GEMM_SMEM>>>(
            kv16, wth + wb + OFF_CAK, wtl + wb + OFF_CAK, nullptr, kvp, nullptr,
            MC, D_, D_, D_, MCD, DD, 0, MCD, ntKV);
        gemm_mma<0,0><<<pgrid(ntQ), 256, GEMM_SMEM>>>(q16, wth + wb + OFF_CAQ, wtl + wb + OFF_CAQ, nullptr, qp, nullptr, MQ, D_, D_, D_, 0, 0, 0, 0, ntQ);
        attn_kernel<<<BATCH*NHEAD, 256>>>(qp, kvp, kvp + MCD, pm, ao16, SEQ, D_, D_, 1, 0, scale);
        gemm_mma<0,1><<<pgrid(ntQ), 256, GEMM_SMEM>>>(ao16, wth + wb + OFF_CAP, wtl + wb + OFF_CAP, cpb, q2, cat16, MQ, D_, D_, 2*D_, 0, 0, 0, 0, ntQ);

        // alpha = [q2, q] @ al_w + al_b  (single K=2048 GEMM)
        gemm_mma<0,0><<<pgrid(ntQ), 256, GEMM_SMEM>>>(cat16, wth + wb + OFF_AL, wtl + wb + OFF_AL, alb, alf, nullptr, MQ, D_, 2*D_, D_, 0, 0, 0, 0, ntQ);
        alpha_ln_mod<<<MQ, 256>>>(qbuf, q16, q2, alf, modL, 2*D_);

        // ---- MLP ----
        gemm_mma<1,2><<<pgrid(ntFc1), 256, GEMM_SMEM>>>(q16, wth + wb + OFF_FC1, wtl + wb + OFF_FC1, f1b, po, h16, MQ, HID, D_, HID, 0, 0, 0, 0, ntFc1);
        gemm_mma<0,0><<<pgrid(ntQ), 256, GEMM_SMEM>>>(h16, wth + wb + OFF_FC2, wtl + wb + OFF_FC2, f2b, po, nullptr, MQ, D_, HID, D_, 0, 0, 0, 0, ntQ);
        ln_mod_resid<<<MQ, 256>>>(qbuf, q16, nullptr, po, modL, 4*D_);
    }

    head_kernel<<<MQ, 256>>>(qbuf, head_w, head_b, out);
}

// round 14
// speedup vs baseline: 1.1764x; 1.0941x over previous
#include <cuda_runtime.h>
#include <cuda_fp16.h>
#include <cstdint>
#include <cstddef>

#define D_    1024
#define BATCH 32
#define SEQ   128
#define NQ_   256
#define HID   4096
#define NHEAD 16
#define NEGV  (-10000.0f)
#define NLAYER 6
#define VOCAB 18

// ---------------- portable PTX helpers (compute_103-safe) -------------------
__device__ __forceinline__ uint32_t smem_u32(const void* p) {
    uint32_t a;
    asm("{ .reg .u64 t; cvta.to.shared.u64 t, %1; cvt.u32.u64 %0, t; }"
        : "=r"(a) : "l"(p));
    return a;
}

#define CP16(s, g) \
    asm volatile("cp.async.cg.shared.global [%0], [%1], 16;" :: "r"(s), "l"(g))
#define CP_COMMIT() asm volatile("cp.async.commit_group;" ::: "memory")
#define CP_WAIT1()  asm volatile("cp.async.wait_group 1;" ::: "memory")
#define CP_WAIT0()  asm volatile("cp.async.wait_group 0;" ::: "memory")

#define LDSM_X4(r0, r1, r2, r3, addr) \
    asm volatile("ldmatrix.sync.aligned.m8n8.x4.shared.b16 {%0,%1,%2,%3}, [%4];" \
                 : "=r"(r0), "=r"(r1), "=r"(r2), "=r"(r3) : "r"(addr))

#define MMA16816(c, a0, a1, a2, a3, b0, b1) \
    asm volatile("mma.sync.aligned.m16n8k16.row.col.f32.f16.f16.f32 " \
                 "{%0,%1,%2,%3}, {%4,%5,%6,%7}, {%8,%9}, {%0,%1,%2,%3};" \
                 : "+f"((c)[0]), "+f"((c)[1]), "+f"((c)[2]), "+f"((c)[3]) \
                 : "r"(a0), "r"(a1), "r"(a2), "r"(a3), "r"(b0), "r"(b1))

__device__ __forceinline__ uint32_t cvt2h(float a, float b) {
    __half2 t = __floats2half2_rn(a, b);
    return *(uint32_t*)&t;
}
__device__ __forceinline__ void split2h(float a, float b, uint32_t& h, uint32_t& l) {
    __half ha = __float2half_rn(a);
    __half hb = __float2half_rn(b);
    __half la = __float2half_rn(a - __half2float(ha));
    __half lb = __float2half_rn(b - __half2float(hb));
    __half2 hh; hh.x = ha; hh.y = hb;
    __half2 ll; ll.x = la; ll.y = lb;
    h = *(uint32_t*)&hh;
    l = *(uint32_t*)&ll;
}

// ---------------- scratch (device globals; allocation-free) ----------------
#define WPL 25165824ULL
#define OFF_MOD 0ULL
#define OFF_SAQ 6291456ULL
#define OFF_SAP 9437184ULL
#define OFF_CAQ 10485760ULL
#define OFF_CAP 13631488ULL
#define OFF_AL  14680064ULL
#define OFF_FC1 16777216ULL
#define OFF_FC2 20971520ULL

#define MCD_ ((size_t)BATCH * SEQ * D_)

__device__ __half g_wth[NLAYER * WPL];
__device__ __half g_wtl[NLAYER * WPL];
__device__ __half g_wkvh[NLAYER * 2 * D_ * D_];   // CAK/CAV, uniform stride DD
__device__ __half g_wkvl[NLAYER * 2 * D_ * D_];
__device__ __half g_sc16 [BATCH*SEQ*D_];
__device__ __half g_q16  [BATCH*NQ_*D_];
__device__ __half g_ao16 [BATCH*NQ_*D_];
__device__ __half g_kv16 [NLAYER*2*BATCH*SEQ*D_];  // all layers kin|vin
__device__ __half g_cat16[BATCH*NQ_*2*D_];
__device__ __half g_h16  [BATCH*NQ_*HID];

__device__ float g_mod[NLAYER*BATCH*SEQ*6*D_];
__device__ float g_q  [BATCH*NQ_*D_];
__device__ float g_qkv[BATCH*NQ_*3*D_];
__device__ float g_qp [BATCH*NQ_*D_];
__device__ float g_kvp[NLAYER*2*BATCH*SEQ*D_];     // all layers kp|vp
__device__ float g_po [BATCH*NQ_*D_];
__device__ float g_q2 [BATCH*NQ_*D_];
__device__ float g_alf[BATCH*NQ_*D_];

// ---------------- weight transpose + fp16 hi/lo split (z-batched) ----------
__global__ __launch_bounds__(256) void transpose_split(const float* __restrict__ W,
                                                       __half* __restrict__ oh,
                                                       __half* __restrict__ ol,
                                                       int K, int N,
                                                       size_t ils, size_t ols)
{
    __shared__ float t[32][33];
    const int z = blockIdx.z;
    W  += (size_t)z * ils;
    oh += (size_t)z * ols;
    ol += (size_t)z * ols;
    const int n0 = blockIdx.x * 32, k0 = blockIdx.y * 32;
    const int tx = threadIdx.x & 31, ty = threadIdx.x >> 5;
#pragma unroll
    for (int r = 0; r < 4; r++)
        t[ty + 8*r][tx] = W[(size_t)(k0 + ty + 8*r) * N + n0 + tx];
    __syncthreads();
#pragma unroll
    for (int s = 0; s < 2; s++) {
        int id = threadIdx.x + s * 256;
        int n  = id >> 4;
        int kp = (id & 15) * 2;
        uint32_t h, l;
        split2h(t[kp][n], t[kp + 1][n], h, l);
        size_t o = (size_t)(n0 + n) * K + k0 + kp;
        *(uint32_t*)(oh + o) = h;
        *(uint32_t*)(ol + o) = l;
    }
}

__global__ void silu_h(const float* __restrict__ x, __half* __restrict__ oh, int n4)
{
    int i = blockIdx.x * blockDim.x + threadIdx.x;
    if (i >= n4) return;
    float4 v = ((const float4*)x)[i];
    float f[4] = {v.x, v.y, v.z, v.w};
#pragma unroll
    for (int j = 0; j < 4; j++) f[j] = f[j] / (1.f + expf(-f[j]));
    uint2 hh; hh.x = cvt2h(f[0], f[1]); hh.y = cvt2h(f[2], f[3]);
    *(uint2*)(oh + 4*(size_t)i) = hh;
}

__global__ void copy_h(const float* __restrict__ x, float* __restrict__ o,
                       __half* __restrict__ oh, int n4)
{
    int i = blockIdx.x * blockDim.x + threadIdx.x;
    if (i >= n4) return;
    float4 v = ((const float4*)x)[i];
    ((float4*)o)[i] = v;
    uint2 hh; hh.x = cvt2h(v.x, v.y); hh.y = cvt2h(v.z, v.w);
    *(uint2*)(oh + 4*(size_t)i) = hh;
}

// ---------------- persistent HMMA GEMM (2-term fp16 split, BK=64) -----------
// Warp tile 64Mx32N (warps 2x4). OUT: 0 fp32, 1 fp32+fp16, 2 fp16 only.
#define AS 72
#define TILE_B (128 * AS * 2)
#define BUF_B  (3 * TILE_B)
#define GEMM_SMEM (2 * BUF_B)

template<int ACT, int OUT>
__global__ __launch_bounds__(256, 2) void gemm_mma(const __half* __restrict__ A,
                                                   const __half* __restrict__ Bh,
                                                   const __half* __restrict__ Bl,
                                                   const float* __restrict__ bias,
                                                   float* __restrict__ C,
                                                   __half* __restrict__ Ch,
                                                   int M, int N, int K, int cn,
                                                   size_t azs, size_t bzs,
                                                   size_t biaszs, size_t czs,
                                                   int ntiles)
{
    extern __shared__ __align__(128) char dynsm[];
    const uint32_t sb0 = smem_u32(dynsm);
    const int nx = N >> 7, ny = M >> 7;

    const int tid  = threadIdx.x;
    const int lane = tid & 31;
    const int wid  = tid >> 5;
    const int wm   = wid & 1;
    const int wn   = wid >> 1;

    const int lr  = tid >> 3;
    const int lcs = (tid & 7) * 8;
    const uint32_t so = (uint32_t)(lr * AS + lcs) * 2;
    const uint32_t SOSTEP = 32u * AS * 2;
    const size_t rstep = (size_t)32 * K;
    const int nch = K >> 6;

    int t = blockIdx.x;
    int bx = t % nx, rr = t / nx, by = rr % ny, bz = rr / ny;
    const __half* gA  = A  + (size_t)bz * azs + (size_t)(by * 128 + lr) * K + lcs;
    const __half* gBh = Bh + (size_t)bz * bzs + (size_t)(bx * 128 + lr) * K + lcs;
    const __half* gBl = Bl + (size_t)bz * bzs + (size_t)(bx * 128 + lr) * K + lcs;

#pragma unroll
    for (int tt = 0; tt < 4; tt++) {
        CP16(sb0 + 0*TILE_B + so + tt*SOSTEP, gA  + tt*rstep);
        CP16(sb0 + 1*TILE_B + so + tt*SOSTEP, gBh + tt*rstep);
        CP16(sb0 + 2*TILE_B + so + tt*SOSTEP, gBl + tt*rstep);
    }
    CP_COMMIT();

    const uint32_t a_row = (uint32_t)(wm * 64 + (lane & 15));
    const uint32_t a_kb  = (uint32_t)((lane >> 4) * 16);
    const uint32_t b_row = (uint32_t)(wn * 32 + (lane & 7) + ((lane >> 4) << 3));
    const uint32_t b_kb  = (uint32_t)(((lane >> 3) & 1) * 16);

    while (true) {
        float acc[4][4][4];
#pragma unroll
        for (int i = 0; i < 4; i++)
#pragma unroll
            for (int n = 0; n < 4; n++)
#pragma unroll
                for (int j = 0; j < 4; j++) acc[i][n][j] = 0.f;

        const bool has_next = (t + (int)gridDim.x < ntiles);

        for (int c = 0; c < nch; c++) {
            if (c + 1 < nch) {
                const int k1 = (c + 1) << 6;
                uint32_t sb = sb0 + ((c + 1) & 1) * BUF_B;
#pragma unroll
                for (int tt = 0; tt < 4; tt++) {
                    CP16(sb + 0*TILE_B + so + tt*SOSTEP, gA  + tt*rstep + k1);
                    CP16(sb + 1*TILE_B + so + tt*SOSTEP, gBh + tt*rstep + k1);
                    CP16(sb + 2*TILE_B + so + tt*SOSTEP, gBl + tt*rstep + k1);
                }
                CP_COMMIT();
                CP_WAIT1();
            } else if (has_next) {
                const int tn = t + gridDim.x;
                const int nbx = tn % nx; int r2 = tn / nx;
                const int nby = r2 % ny, nbz = r2 / ny;
                const __half* nA  = A  + (size_t)nbz * azs + (size_t)(nby * 128 + lr) * K + lcs;
                const __half* nBh = Bh + (size_t)nbz * bzs + (size_t)(nbx * 128 + lr) * K + lcs;
                const __half* nBl = Bl + (size_t)nbz * bzs + (size_t)(nbx * 128 + lr) * K + lcs;
#pragma unroll
                for (int tt = 0; tt < 4; tt++) {
                    CP16(sb0 + 0*TILE_B + so + tt*SOSTEP, nA  + tt*rstep);
                    CP16(sb0 + 1*TILE_B + so + tt*SOSTEP, nBh + tt*rstep);
                    CP16(sb0 + 2*TILE_B + so + tt*SOSTEP, nBl + tt*rstep);
                }
                CP_COMMIT();
                CP_WAIT1();
            } else {
                CP_WAIT0();
            }
            __syncthreads();

            const uint32_t sb  = sb0 + (c & 1) * BUF_B;
            const uint32_t sA  = sb + 0*TILE_B;
            const uint32_t sBh = sb + 1*TILE_B;
            const uint32_t sBl = sb + 2*TILE_B;

#pragma unroll
            for (int ks = 0; ks < 4; ks++) {
                const uint32_t kb = (uint32_t)(ks * 32);
                uint32_t bh[2][4], bl[2][4];
#pragma unroll
                for (int np = 0; np < 2; np++) {
                    uint32_t boff = (b_row + np * 16) * (AS * 2) + kb + b_kb;
                    LDSM_X4(bh[np][0], bh[np][1], bh[np][2], bh[np][3], sBh + boff);
                    LDSM_X4(bl[np][0], bl[np][1], bl[np][2], bl[np][3], sBl + boff);
                }
#pragma unroll
                for (int i = 0; i < 4; i++) {
                    uint32_t a0, a1, a2, a3;
                    uint32_t aoff = (a_row + i * 16) * (AS * 2) + kb + a_kb;
                    LDSM_X4(a0, a1, a2, a3, sA + aoff);
                    MMA16816(acc[i][0], a0, a1, a2, a3, bh[0][0], bh[0][1]);
                    MMA16816(acc[i][1], a0, a1, a2, a3, bh[0][2], bh[0][3]);
                    MMA16816(acc[i][2], a0, a1, a2, a3, bh[1][0], bh[1][1]);
                    MMA16816(acc[i][3], a0, a1, a2, a3, bh[1][2], bh[1][3]);
                    MMA16816(acc[i][0], a0, a1, a2, a3, bl[0][0], bl[0][1]);
                    MMA16816(acc[i][1], a0, a1, a2, a3, bl[0][2], bl[0][3]);
                    MMA16816(acc[i][2], a0, a1, a2, a3, bl[1][0], bl[1][1]);
                    MMA16816(acc[i][3], a0, a1, a2, a3, bl[1][2], bl[1][3]);
                }
            }
            __syncthreads();
        }

        {
            const float* biasp = bias ? (bias + (size_t)bz * biaszs) : nullptr;
            float* Cp = C + (size_t)bz * czs;
            __half* Chp = (OUT >= 1) ? (Ch + (size_t)bz * czs) : nullptr;
            const int m0 = by * 128, n0 = bx * 128;
#pragma unroll
            for (int i = 0; i < 4; i++) {
                const int r0 = m0 + wm * 64 + i * 16 + (lane >> 2);
#pragma unroll
                for (int nt = 0; nt < 4; nt++) {
                    const int col = n0 + wn * 32 + nt * 8 + (lane & 3) * 2;
#pragma unroll
                    for (int half = 0; half < 2; half++) {
                        const int r = r0 + half * 8;
                        float v0 = acc[i][nt][half * 2 + 0];
                        float v1 = acc[i][nt][half * 2 + 1];
                        if (biasp) { v0 += biasp[col]; v1 += biasp[col + 1]; }
                        if (ACT == 1) {
                            v0 = 0.5f * v0 * (1.0f + erff(v0 * 0.70710678118654752f));
                            v1 = 0.5f * v1 * (1.0f + erff(v1 * 0.70710678118654752f));
                        }
                        if (OUT != 2) {
                            float2 o; o.x = v0; o.y = v1;
                            *(float2*)(Cp + (size_t)r * N + col) = o;
                        }
                        if (OUT >= 1)
                            *(uint32_t*)(Chp + (size_t)r * cn + col) = cvt2h(v0, v1);
                    }
                }
            }
        }

        if (!has_next) break;
        t += gridDim.x;
        bx = t % nx; rr = t / nx; by = rr % ny; bz = rr / ny;
        gA  = A  + (size_t)bz * azs + (size_t)(by * 128 + lr) * K + lcs;
        gBh = Bh + (size_t)bz * bzs + (size_t)(bx * 128 + lr) * K + lcs;
        gBl = Bl + (size_t)bz * bzs + (size_t)(bx * 128 + lr) * K + lcs;
    }
}

// ---------------- attention: 128 threads, 2 CTAs/(b,h), causal early-exit ---
__global__ __launch_bounds__(128) void attn_kernel(const float* __restrict__ Q,
                                                   const float* __restrict__ Kp,
                                                   const float* __restrict__ Vp,
                                                   const int* __restrict__ pm,
                                                   __half* __restrict__ Oh,
                                                   int NK, int qst, int kvst,
                                                   int rshift, int pmshift, float scale)
{
    __shared__ float Ks[64][64];
    __shared__ float Vs[64][64];
    __shared__ float bias_s[64];

    const int bh = blockIdx.x >> 1;
    const int hf = blockIdx.x & 1;
    const int b  = bh >> 4;
    const int h  = bh & 15;
    const float* qb = Q  + (size_t)b * NQ_ * qst  + h * 64;
    const float* kb = Kp + (size_t)b * NK  * kvst + h * 64;
    const float* vb = Vp + (size_t)b * NK  * kvst + h * 64;
    const int r = hf * 128 + threadIdx.x;

    float qr[64];
#pragma unroll
    for (int k4 = 0; k4 < 16; k4++) {
        float4 v = *(const float4*)(qb + (size_t)r * qst + k4 * 4);
        qr[k4*4+0] = v.x; qr[k4*4+1] = v.y; qr[k4*4+2] = v.z; qr[k4*4+3] = v.w;
    }

    float m = -1e30f, l = 0.f;
    float o[64];
#pragma unroll
    for (int k = 0; k < 64; k++) o[k] = 0.f;

    const int maxj = r >> rshift;
    // block-uniform chunk bound (last row of this half decides)
    int kend = ((hf * 128 + 127) >> rshift) + 1;
    if (kend > NK) kend = NK;

    for (int c0 = 0; c0 < kend; c0 += 64) {
        __syncthreads();
        for (int t = threadIdx.x; t < 1024; t += 128) {
            int j = t >> 4;
            int c = (t & 15) << 2;
            *(float4*)&Ks[j][c] = *(const float4*)(kb + (size_t)(c0 + j) * kvst + c);
            *(float4*)&Vs[j][c] = *(const float4*)(vb + (size_t)(c0 + j) * kvst + c);
        }
        if (threadIdx.x < 64)
            bias_s[threadIdx.x] =
                NEGV * (float)pm[b * SEQ + ((c0 + threadIdx.x) >> pmshift)];
        __syncthreads();

        int jend = maxj - c0;
        if (jend > 63) jend = 63;
        for (int j = 0; j <= jend; j++) {
            float d0 = 0.f, d1 = 0.f, d2 = 0.f, d3 = 0.f;
#pragma unroll
            for (int k = 0; k < 64; k += 4) {
                d0 += qr[k+0] * Ks[j][k+0];
                d1 += qr[k+1] * Ks[j][k+1];
                d2 += qr[k+2] * Ks[j][k+2];
                d3 += qr[k+3] * Ks[j][k+3];
            }
            float sc = ((d0 + d1) + (d2 + d3)) * scale + bias_s[j];
            if (sc > m) {
                float corr = expf(m - sc);
                l = l * corr + 1.f;
#pragma unroll
                for (int k = 0; k < 64; k++) o[k] = o[k] * corr + Vs[j][k];
                m = sc;
            } else {
                float p = expf(sc - m);
                l += p;
#pragma unroll
                for (int k = 0; k < 64; k++) o[k] += p * Vs[j][k];
            }
        }
    }

    float inv = 1.f / l;
    const size_t obase = ((size_t)b * NQ_ + r) * D_ + h * 64;
#pragma unroll
    for (int k2 = 0; k2 < 32; k2++)
        *(uint32_t*)(Oh + obase + k2*2) = cvt2h(o[k2*2] * inv, o[k2*2+1] * inv);
}

// ---------------- LN helpers ----------------
__device__ __forceinline__ void block_reduce2(float& a, float& b)
{
    __shared__ float sa[8], sb[8];
    const unsigned full = 0xffffffffu;
#pragma unroll
    for (int o = 16; o > 0; o >>= 1) {
        a += __shfl_down_sync(full, a, o);
        b += __shfl_down_sync(full, b, o);
    }
    int w = threadIdx.x >> 5, lane = threadIdx.x & 31;
    if (lane == 0) { sa[w] = a; sb[w] = b; }
    __syncthreads();
    float ta = 0.f, tb = 0.f;
#pragma unroll
    for (int i = 0; i < 8; i++) { ta += sa[i]; tb += sb[i]; }
    a = ta; b = tb;
}

__device__ __forceinline__ void block_reduce4(float& a, float& b, float& c, float& d)
{
    __shared__ float s4[8][4];
    const unsigned full = 0xffffffffu;
#pragma unroll
    for (int o = 16; o > 0; o >>= 1) {
        a += __shfl_down_sync(full, a, o);
        b += __shfl_down_sync(full, b, o);
        c += __shfl_down_sync(full, c, o);
        d += __shfl_down_sync(full, d, o);
    }
    int w = threadIdx.x >> 5, lane = threadIdx.x & 31;
    if (lane == 0) { s4[w][0] = a; s4[w][1] = b; s4[w][2] = c; s4[w][3] = d; }
    __syncthreads();
    float ta = 0.f, tb = 0.f, tc = 0.f, td = 0.f;
#pragma unroll
    for (int i = 0; i < 8; i++) {
        ta += s4[i][0]; tb += s4[i][1]; tc += s4[i][2]; td += s4[i][3];
    }
    a = ta; b = tb; c = tc; d = td;
}

// q = LN(q + add) * (1+s) + sh ; fp16 mirror (+ optional concat copy)
__global__ __launch_bounds__(256) void ln_mod_resid(float* __restrict__ q,
                                                    __half* __restrict__ qh,
                                                    __half* __restrict__ qcat,
                                                    const float* __restrict__ add,
                                                    const float* __restrict__ mod,
                                                    int off)
{
    const int row = blockIdx.x;
    const int b = row >> 8, n = row & 255;
    const float* mp = mod + ((size_t)(b * SEQ + (n >> 1))) * (6 * D_) + off;
    const size_t base = (size_t)row * D_;
    const int d = threadIdx.x * 4;

    float4 xv = *(const float4*)(q + base + d);
    float4 av = *(const float4*)(add + base + d);
    float x[4] = {xv.x + av.x, xv.y + av.y, xv.z + av.z, xv.w + av.w};

    float s  = x[0] + x[1] + x[2] + x[3];
    float ss = x[0]*x[0] + x[1]*x[1] + x[2]*x[2] + x[3]*x[3];
    block_reduce2(s, ss);
    float mean = s * (1.f / D_);
    float var  = ss * (1.f / D_) - mean * mean;
    float inv  = rsqrtf(var + 1e-6f);

    float4 sv  = *(const float4*)(mp + d);
    float4 shv = *(const float4*)(mp + D_ + d);
    float y0 = (x[0]-mean)*inv*(1.f+sv.x)+shv.x;
    float y1 = (x[1]-mean)*inv*(1.f+sv.y)+shv.y;
    float y2 = (x[2]-mean)*inv*(1.f+sv.z)+shv.z;
    float y3 = (x[3]-mean)*inv*(1.f+sv.w)+shv.w;
    float4 o; o.x = y0; o.y = y1; o.z = y2; o.w = y3;
    *(float4*)(q + base + d) = o;
    uint2 hh; hh.x = cvt2h(y0, y1); hh.y = cvt2h(y2, y3);
    *(uint2*)(qh + base + d) = hh;
    if (qcat)
        *(uint2*)(qcat + (size_t)row * (2*D_) + D_ + d) = hh;
}

// q = LN((1+al)*q2 + q) * (1+s) + sh ; fp16 mirror
__global__ __launch_bounds__(256) void alpha_ln_mod(float* __restrict__ q,
                                                    __half* __restrict__ qh,
                                                    const float* __restrict__ q2,
                                                    const float* __restrict__ al,
                                                    const float* __restrict__ mod,
                                                    int off)
{
    const int row = blockIdx.x;
    const int b = row >> 8, n = row & 255;
    const float* mp = mod + ((size_t)(b * SEQ + (n >> 1))) * (6 * D_) + off;
    const size_t base = (size_t)row * D_;
    const int d = threadIdx.x * 4;

    float4 qv  = *(const float4*)(q  + base + d);
    float4 q2v = *(const float4*)(q2 + base + d);
    float4 alv = *(const float4*)(al + base + d);
    float x[4];
    x[0] = (1.f+alv.x)*q2v.x + qv.x;
    x[1] = (1.f+alv.y)*q2v.y + qv.y;
    x[2] = (1.f+alv.z)*q2v.z + qv.z;
    x[3] = (1.f+alv.w)*q2v.w + qv.w;

    float s  = x[0] + x[1] + x[2] + x[3];
    float ss = x[0]*x[0] + x[1]*x[1] + x[2]*x[2] + x[3]*x[3];
    block_reduce2(s, ss);
    float mean = s * (1.f / D_);
    float var  = ss * (1.f / D_) - mean * mean;
    float inv  = rsqrtf(var + 1e-6f);

    float4 sv  = *(const float4*)(mp + d);
    float4 shv = *(const float4*)(mp + D_ + d);
    float y0 = (x[0]-mean)*inv*(1.f+sv.x)+shv.x;
    float y1 = (x[1]-mean)*inv*(1.f+sv.y)+shv.y;
    float y2 = (x[2]-mean)*inv*(1.f+sv.z)+shv.z;
    float y3 = (x[3]-mean)*inv*(1.f+sv.w)+shv.w;
    float4 o; o.x = y0; o.y = y1; o.z = y2; o.w = y3;
    *(float4*)(q + base + d) = o;
    uint2 hh; hh.x = cvt2h(y0, y1); hh.y = cvt2h(y2, y3);
    *(uint2*)(qh + base + d) = hh;
}

// all-layer fused CA input LNs: blockIdx.y = layer
__global__ __launch_bounds__(256) void ln_gamma2(__half* __restrict__ kv,
                                                 const float* __restrict__ c,
                                                 const float* __restrict__ pe,
                                                 const float* __restrict__ nk_g,
                                                 const float* __restrict__ nk_b,
                                                 const float* __restrict__ nv_g,
                                                 const float* __restrict__ nv_b)
{
    const int ly = blockIdx.y;
    const float* g1 = nk_g + (size_t)ly * D_;
    const float* b1 = nk_b + (size_t)ly * D_;
    const float* g2 = nv_g + (size_t)ly * D_;
    const float* b2 = nv_b + (size_t)ly * D_;
    __half* kin = kv + (size_t)ly * 2 * MCD_;
    __half* vin = kin + MCD_;

    const int row = blockIdx.x;
    const size_t base = (size_t)row * D_;
    const int d = threadIdx.x * 4;

    float4 cv = *(const float4*)(c  + base + d);
    float4 pv = *(const float4*)(pe + base + d);
    float xk[4] = {cv.x + pv.x, cv.y + pv.y, cv.z + pv.z, cv.w + pv.w};
    float xv[4] = {cv.x, cv.y, cv.z, cv.w};

    float sk = xk[0]+xk[1]+xk[2]+xk[3];
    float ssk = xk[0]*xk[0]+xk[1]*xk[1]+xk[2]*xk[2]+xk[3]*xk[3];
    float sv = xv[0]+xv[1]+xv[2]+xv[3];
    float ssv = xv[0]*xv[0]+xv[1]*xv[1]+xv[2]*xv[2]+xv[3]*xv[3];
    block_reduce4(sk, ssk, sv, ssv);

    float mk = sk * (1.f / D_);
    float ik = rsqrtf(ssk * (1.f / D_) - mk*mk + 1e-5f);
    float mv = sv * (1.f / D_);
    float iv = rsqrtf(ssv * (1.f / D_) - mv*mv + 1e-5f);

    float4 g1v = *(const float4*)(g1 + d);
    float4 b1v = *(const float4*)(b1 + d);
    float4 g2v = *(const float4*)(g2 + d);
    float4 b2v = *(const float4*)(b2 + d);

    float k0 = (xk[0]-mk)*ik*g1v.x+b1v.x;
    float k1 = (xk[1]-mk)*ik*g1v.y+b1v.y;
    float k2 = (xk[2]-mk)*ik*g1v.z+b1v.z;
    float k3 = (xk[3]-mk)*ik*g1v.w+b1v.w;
    uint2 hk; hk.x = cvt2h(k0, k1); hk.y = cvt2h(k2, k3);
    *(uint2*)(kin + base + d) = hk;

    float v0 = (xv[0]-mv)*iv*g2v.x+b2v.x;
    float v1 = (xv[1]-mv)*iv*g2v.y+b2v.y;
    float v2 = (xv[2]-mv)*iv*g2v.z+b2v.z;
    float v3 = (xv[3]-mv)*iv*g2v.w+b2v.w;
    uint2 hv; hv.x = cvt2h(v0, v1); hv.y = cvt2h(v2, v3);
    *(uint2*)(vin + base + d) = hv;
}

__global__ __launch_bounds__(256) void head_kernel(const float* __restrict__ X,
                                                   const float* __restrict__ W,
                                                   const float* __restrict__ bias,
                                                   float* __restrict__ out)
{
    __shared__ float xs[D_];
    const int row = blockIdx.x;
    const size_t base = (size_t)row * D_;
    for (int t = threadIdx.x; t < D_ / 4; t += 256)
        *(float4*)&xs[t * 4] = *(const float4*)(X + base + t * 4);
    __syncthreads();

    int w = threadIdx.x >> 5, lane = threadIdx.x & 31;
    for (int col = w; col < VOCAB; col += 8) {
        float s = 0.f;
        for (int k = lane; k < D_; k += 32) s += xs[k] * W[(size_t)k * VOCAB + col];
#pragma unroll
        for (int o = 16; o > 0; o >>= 1) s += __shfl_down_sync(0xffffffffu, s, o);
        if (lane == 0) out[(size_t)row * VOCAB + col] = s + bias[col];
    }
}

// ---------------- host orchestration ----------------
static float* symaddr_f(const void* s)
{
    void* p = nullptr;
    cudaGetSymbolAddress(&p, s);
    return (float*)p;
}
static __half* symaddr_h(const void* s)
{
    void* p = nullptr;
    cudaGetSymbolAddress(&p, s);
    return (__half*)p;
}
static inline int pgrid(int nt) { return nt < 296 ? nt : 296; }

extern "C" void kernel_launch(void* const* d_in, const int* in_sizes, int n_in,
                              void* d_out, int out_size)
{
    const float* q_in   = (const float*)d_in[0];
    const float* c_in   = (const float*)d_in[1];
    const float* pe_in  = (const float*)d_in[2];
    const float* mod_w  = (const float*)d_in[3];
    const float* mod_b  = (const float*)d_in[4];
    const float* sa_qw  = (const float*)d_in[5];
    const float* sa_kw  = (const float*)d_in[6];
    const float* sa_vw  = (const float*)d_in[7];
    const float* sa_pw  = (const float*)d_in[8];
    const float* sa_pb  = (const float*)d_in[9];
    const float* ca_qw  = (const float*)d_in[10];
    const float* ca_kw  = (const float*)d_in[11];
    const float* ca_vw  = (const float*)d_in[12];
    const float* ca_pw  = (const float*)d_in[13];
    const float* ca_pb  = (const float*)d_in[14];
    const float* nk_g   = (const float*)d_in[15];
    const float* nk_b   = (const float*)d_in[16];
    const float* nv_g   = (const float*)d_in[17];
    const float* nv_b   = (const float*)d_in[18];
    const float* al_w   = (const float*)d_in[19];
    const float* al_b   = (const float*)d_in[20];
    const float* fc1_w  = (const float*)d_in[21];
    const float* fc1_b  = (const float*)d_in[22];
    const float* fc2_w  = (const float*)d_in[23];
    const float* fc2_b  = (const float*)d_in[24];
    const float* head_w = (const float*)d_in[25];
    const float* head_b = (const float*)d_in[26];
    const int*   pm     = (const int*)  d_in[27];
    float* out = (float*)d_out;

    __half* wth   = symaddr_h(g_wth);
    __half* wtl   = symaddr_h(g_wtl);
    __half* wkvh  = symaddr_h(g_wkvh);
    __half* wkvl  = symaddr_h(g_wkvl);
    __half* sc16  = symaddr_h(g_sc16);
    __half* q16   = symaddr_h(g_q16);
    __half* ao16  = symaddr_h(g_ao16);
    __half* kv16  = symaddr_h(g_kv16);
    __half* cat16 = symaddr_h(g_cat16);
    __half* h16   = symaddr_h(g_h16);

    float* mod  = symaddr_f(g_mod);
    float* qbuf = symaddr_f(g_q);
    float* qkv  = symaddr_f(g_qkv);
    float* qp   = symaddr_f(g_qp);
    float* kvp  = symaddr_f(g_kvp);
    float* po   = symaddr_f(g_po);
    float* q2   = symaddr_f(g_q2);
    float* alf  = symaddr_f(g_alf);

    cudaFuncSetAttribute(gemm_mma<0,0>, cudaFuncAttributeMaxDynamicSharedMemorySize, GEMM_SMEM);
    cudaFuncSetAttribute(gemm_mma<0,1>, cudaFuncAttributeMaxDynamicSharedMemorySize, GEMM_SMEM);
    cudaFuncSetAttribute(gemm_mma<1,2>, cudaFuncAttributeMaxDynamicSharedMemorySize, GEMM_SMEM);

    const int MQ = BATCH * NQ_;   // 8192
    const int MC = BATCH * SEQ;   // 4096
    const float scale = 0.125f;
    const size_t MODL = (size_t)MC * 6 * D_;
    const size_t DD   = (size_t)D_ * D_;

    const int ntQ    = (D_/128) * (MQ/128);             // 512
    const int ntQKV  = (3*D_/128) * (MQ/128);           // 1536
    const int ntFc1  = (HID/128) * (MQ/128);            // 2048
    const int ntModA = (6*D_/128) * (MC/128) * NLAYER;  // 9216
    const int ntKVA  = (D_/128) * (MC/128) * 2 * NLAYER; // 3072

    // #1-#5: prerequisites; #6 is a GEMM (ncu -s 5 -c 1)
    silu_h<<<(MC * D_ / 4 + 255) / 256, 256>>>(c_in, sc16, MC * D_ / 4);               // 1
    copy_h<<<(MQ * D_ / 4 + 255) / 256, 256>>>(q_in, qbuf, q16, MQ * D_ / 4);          // 2
    transpose_split<<<dim3(6*D_/32, D_/32, NLAYER), 256>>>(mod_w, wth + OFF_MOD, wtl + OFF_MOD, D_, 6*D_, (size_t)D_*6*D_, WPL); // 3
    transpose_split<<<dim3(32, 32, NLAYER), 256>>>(ca_kw, wkvh,      wkvl,      D_, D_, DD, 2*DD); // 4
    transpose_split<<<dim3(32, 32, NLAYER), 256>>>(ca_vw, wkvh + DD, wkvl + DD, D_, D_, DD, 2*DD); // 5
    // 6: all-layer mod GEMM (single launch, z=6)
    gemm_mma<0,0><<<pgrid(ntModA), 256, GEMM_SMEM>>>(
        sc16, wth + OFF_MOD, wtl + OFF_MOD, mod_b, mod, nullptr,
        MC, 6*D_, D_, 6*D_, 0, WPL, (size_t)6*D_, MODL, ntModA);

    // all-layer CA input LNs + K/V projections (hoisted out of the loop)
    ln_gamma2<<<dim3(MC, NLAYER), 256>>>(kv16, c_in, pe_in, nk_g, nk_b, nv_g, nv_b);
    gemm_mma<0,0><<<pgrid(ntKVA), 256, GEMM_SMEM>>>(
        kv16, wkvh, wkvl, nullptr, kvp, nullptr,
        MC, D_, D_, D_, MCD_, DD, 0, MCD_, ntKVA);

    // remaining weight transposes (z-batched over layers)
    transpose_split<<<dim3(32, 32, NLAYER), 256>>>(sa_qw, wth + OFF_SAQ,           wtl + OFF_SAQ,           D_, D_, DD, WPL);
    transpose_split<<<dim3(32, 32, NLAYER), 256>>>(sa_kw, wth + OFF_SAQ + 1048576, wtl + OFF_SAQ + 1048576, D_, D_, DD, WPL);
    transpose_split<<<dim3(32, 32, NLAYER), 256>>>(sa_vw, wth + OFF_SAQ + 2097152, wtl + OFF_SAQ + 2097152, D_, D_, DD, WPL);
    transpose_split<<<dim3(32, 32, NLAYER), 256>>>(sa_pw, wth + OFF_SAP, wtl + OFF_SAP, D_, D_, DD, WPL);
    transpose_split<<<dim3(32, 32, NLAYER), 256>>>(ca_qw, wth + OFF_CAQ, wtl + OFF_CAQ, D_, D_, DD, WPL);
    transpose_split<<<dim3(32, 32, NLAYER), 256>>>(ca_pw, wth + OFF_CAP, wtl + OFF_CAP, D_, D_, DD, WPL);
    transpose_split<<<dim3(32, 64, NLAYER), 256>>>(al_w, wth + OFF_AL, wtl + OFF_AL, 2*D_, D_, 2*DD, WPL);
    transpose_split<<<dim3(HID/32, 32, NLAYER), 256>>>(fc1_w, wth + OFF_FC1, wtl + OFF_FC1, D_, HID, (size_t)D_*HID, WPL);
    transpose_split<<<dim3(32, HID/32, NLAYER), 256>>>(fc2_w, wth + OFF_FC2, wtl + OFF_FC2, HID, D_, (size_t)HID*D_, WPL);

    for (int i = 0; i < NLAYER; i++) {
        size_t wb = (size_t)i * WPL;
        const float* modL = mod + (size_t)i * MODL;
        float* kvpL = kvp + (size_t)i * 2 * MCD_;
        const float* spb = sa_pb + (size_t)i * D_;
        const float* cpb = ca_pb + (size_t)i * D_;
        const float* alb = al_b  + (size_t)i * D_;
        const float* f1b = fc1_b + (size_t)i * HID;
        const float* f2b = fc2_b + (size_t)i * D_;

        // ---- self-attention (fused QKV) ----
        gemm_mma<0,0><<<pgrid(ntQKV), 256, GEMM_SMEM>>>(q16, wth + wb + OFF_SAQ, wtl + wb + OFF_SAQ, nullptr, qkv, nullptr, MQ, 3*D_, D_, 3*D_, 0, 0, 0, 0, ntQKV);
        attn_kernel<<<BATCH*NHEAD*2, 128>>>(qkv, qkv + D_, qkv + 2*D_, pm, ao16, NQ_, 3*D_, 3*D_, 0, 1, scale);
        gemm_mma<0,0><<<pgrid(ntQ), 256, GEMM_SMEM>>>(ao16, wth + wb + OFF_SAP, wtl + wb + OFF_SAP, spb, po, nullptr, MQ, D_, D_, D_, 0, 0, 0, 0, ntQ);
        ln_mod_resid<<<MQ, 256>>>(qbuf, q16, cat16, po, modL, 0);

        // ---- cross attention (K/V precomputed) ----
        gemm_mma<0,0><<<pgrid(ntQ), 256, GEMM_SMEM>>>(q16, wth + wb + OFF_CAQ, wtl + wb + OFF_CAQ, nullptr, qp, nullptr, MQ, D_, D_, D_, 0, 0, 0, 0, ntQ);
        attn_kernel<<<BATCH*NHEAD*2, 128>>>(qp, kvpL, kvpL + MCD_, pm, ao16, SEQ, D_, D_, 1, 0, scale);
        gemm_mma<0,1><<<pgrid(ntQ), 256, GEMM_SMEM>>>(ao16, wth + wb + OFF_CAP, wtl + wb + OFF_CAP, cpb, q2, cat16, MQ, D_, D_, 2*D_, 0, 0, 0, 0, ntQ);

        // alpha = [q2, q] @ al_w + al_b  (single K=2048 GEMM)
        gemm_mma<0,0><<<pgrid(ntQ), 256, GEMM_SMEM>>>(cat16, wth + wb + OFF_AL, wtl + wb + OFF_AL, alb, alf, nullptr, MQ, D_, 2*D_, D_, 0, 0, 0, 0, ntQ);
        alpha_ln_mod<<<MQ, 256>>>(qbuf, q16, q2, alf, modL, 2*D_);

        // ---- MLP ----
        gemm_mma<1,2><<<pgrid(ntFc1), 256, GEMM_SMEM>>>(q16, wth + wb + OFF_FC1, wtl + wb + OFF_FC1, f1b, po, h16, MQ, HID, D_, HID, 0, 0, 0, 0, ntFc1);
        gemm_mma<0,0><<<pgrid(ntQ), 256, GEMM_SMEM>>>(h16, wth + wb + OFF_FC2, wtl + wb + OFF_FC2, f2b, po, nullptr, MQ, D_, HID, D_, 0, 0, 0, 0, ntQ);
        ln_mod_resid<<<MQ, 256>>>(qbuf, q16, nullptr, po, modL, 4*D_);
    }

    head_kernel<<<MQ, 256>>>(qbuf, head_w, head_b, out);
}

// round 15
// speedup vs baseline: 1.7134x; 1.4565x over previous
#include <cuda_runtime.h>
#include <cuda_fp16.h>
#include <cstdint>
#include <cstddef>

#define D_    1024
#define BATCH 32
#define SEQ   128
#define NQ_   256
#define HID   4096
#define NHEAD 16
#define NEGV  (-10000.0f)
#define NLAYER 6
#define VOCAB 18

// ---------------- portable PTX helpers (compute_103-safe) -------------------
__device__ __forceinline__ uint32_t smem_u32(const void* p) {
    uint32_t a;
    asm("{ .reg .u64 t; cvta.to.shared.u64 t, %1; cvt.u32.u64 %0, t; }"
        : "=r"(a) : "l"(p));
    return a;
}

#define CP16(s, g) \
    asm volatile("cp.async.cg.shared.global [%0], [%1], 16;" :: "r"(s), "l"(g))
#define CP_COMMIT() asm volatile("cp.async.commit_group;" ::: "memory")
#define CP_WAIT1()  asm volatile("cp.async.wait_group 1;" ::: "memory")
#define CP_WAIT0()  asm volatile("cp.async.wait_group 0;" ::: "memory")

#define LDSM_X4(r0, r1, r2, r3, addr) \
    asm volatile("ldmatrix.sync.aligned.m8n8.x4.shared.b16 {%0,%1,%2,%3}, [%4];" \
                 : "=r"(r0), "=r"(r1), "=r"(r2), "=r"(r3) : "r"(addr))

#define MMA16816(c, a0, a1, a2, a3, b0, b1) \
    asm volatile("mma.sync.aligned.m16n8k16.row.col.f32.f16.f16.f32 " \
                 "{%0,%1,%2,%3}, {%4,%5,%6,%7}, {%8,%9}, {%0,%1,%2,%3};" \
                 : "+f"((c)[0]), "+f"((c)[1]), "+f"((c)[2]), "+f"((c)[3]) \
                 : "r"(a0), "r"(a1), "r"(a2), "r"(a3), "r"(b0), "r"(b1))

__device__ __forceinline__ uint32_t cvt2h(float a, float b) {
    __half2 t = __floats2half2_rn(a, b);
    return *(uint32_t*)&t;
}

// ---------------- scratch (device globals; allocation-free) ----------------
#define WPL 25165824ULL
#define OFF_MOD 0ULL
#define OFF_SAQ 6291456ULL
#define OFF_SAP 9437184ULL
#define OFF_CAQ 10485760ULL
#define OFF_CAP 13631488ULL
#define OFF_AL  14680064ULL
#define OFF_FC1 16777216ULL
#define OFF_FC2 20971520ULL

#define MCD_ ((size_t)BATCH * SEQ * D_)

__device__ __half g_wth[NLAYER * WPL];            // transposed fp16 weights
__device__ __half g_wkvh[NLAYER * 2 * D_ * D_];   // CAK/CAV, uniform stride DD
__device__ __half g_sc16 [BATCH*SEQ*D_];
__device__ __half g_q16  [BATCH*NQ_*D_];
__device__ __half g_ao16 [BATCH*NQ_*D_];
__device__ __half g_kv16 [NLAYER*2*BATCH*SEQ*D_];
__device__ __half g_cat16[BATCH*NQ_*2*D_];
__device__ __half g_h16  [BATCH*NQ_*HID];

__device__ float g_mod[NLAYER*BATCH*SEQ*6*D_];
__device__ float g_q  [BATCH*NQ_*D_];
__device__ float g_qkv[BATCH*NQ_*3*D_];
__device__ float g_qp [BATCH*NQ_*D_];
__device__ float g_kvp[NLAYER*2*BATCH*SEQ*D_];
__device__ float g_po [BATCH*NQ_*D_];
__device__ float g_q2 [BATCH*NQ_*D_];
__device__ float g_alf[BATCH*NQ_*D_];

// ---------------- weight transpose to fp16 (hi only, z-batched) -------------
__global__ __launch_bounds__(256) void transpose_h(const float* __restrict__ W,
                                                   __half* __restrict__ oh,
                                                   int K, int N,
                                                   size_t ils, size_t ols)
{
    __shared__ float t[32][33];
    const int z = blockIdx.z;
    W  += (size_t)z * ils;
    oh += (size_t)z * ols;
    const int n0 = blockIdx.x * 32, k0 = blockIdx.y * 32;
    const int tx = threadIdx.x & 31, ty = threadIdx.x >> 5;
#pragma unroll
    for (int r = 0; r < 4; r++)
        t[ty + 8*r][tx] = W[(size_t)(k0 + ty + 8*r) * N + n0 + tx];
    __syncthreads();
#pragma unroll
    for (int s = 0; s < 2; s++) {
        int id = threadIdx.x + s * 256;
        int n  = id >> 4;
        int kp = (id & 15) * 2;
        *(uint32_t*)(oh + (size_t)(n0 + n) * K + k0 + kp) =
            cvt2h(t[kp][n], t[kp + 1][n]);
    }
}

__global__ void silu_h(const float* __restrict__ x, __half* __restrict__ oh, int n4)
{
    int i = blockIdx.x * blockDim.x + threadIdx.x;
    if (i >= n4) return;
    float4 v = ((const float4*)x)[i];
    float f[4] = {v.x, v.y, v.z, v.w};
#pragma unroll
    for (int j = 0; j < 4; j++) f[j] = f[j] / (1.f + expf(-f[j]));
    uint2 hh; hh.x = cvt2h(f[0], f[1]); hh.y = cvt2h(f[2], f[3]);
    *(uint2*)(oh + 4*(size_t)i) = hh;
}

__global__ void copy_h(const float* __restrict__ x, float* __restrict__ o,
                       __half* __restrict__ oh, int n4)
{
    int i = blockIdx.x * blockDim.x + threadIdx.x;
    if (i >= n4) return;
    float4 v = ((const float4*)x)[i];
    ((float4*)o)[i] = v;
    uint2 hh; hh.x = cvt2h(v.x, v.y); hh.y = cvt2h(v.z, v.w);
    *(uint2*)(oh + 4*(size_t)i) = hh;
}

// ---------------- persistent HMMA GEMM (1-term fp16, BK=64) -----------------
// Warp tile 64Mx32N (warps 2x4). OUT: 0 fp32, 1 fp32+fp16, 2 fp16 only.
#define AS 72
#define TILE_B (128 * AS * 2)       // 18432 B
#define BUF_B  (2 * TILE_B)         // 36864 B (A, B)
#define GEMM_SMEM (2 * BUF_B)       // 73728 B

template<int ACT, int OUT>
__global__ __launch_bounds__(256, 2) void gemm_mma(const __half* __restrict__ A,
                                                   const __half* __restrict__ B,
                                                   const float* __restrict__ bias,
                                                   float* __restrict__ C,
                                                   __half* __restrict__ Ch,
                                                   int M, int N, int K, int cn,
                                                   size_t azs, size_t bzs,
                                                   size_t biaszs, size_t czs,
                                                   int ntiles)
{
    extern __shared__ __align__(128) char dynsm[];
    const uint32_t sb0 = smem_u32(dynsm);
    const int nx = N >> 7, ny = M >> 7;

    const int tid  = threadIdx.x;
    const int lane = tid & 31;
    const int wid  = tid >> 5;
    const int wm   = wid & 1;
    const int wn   = wid >> 1;

    const int lr  = tid >> 3;
    const int lcs = (tid & 7) * 8;
    const uint32_t so = (uint32_t)(lr * AS + lcs) * 2;
    const uint32_t SOSTEP = 32u * AS * 2;
    const size_t rstep = (size_t)32 * K;
    const int nch = K >> 6;

    int t = blockIdx.x;
    int bx = t % nx, rr = t / nx, by = rr % ny, bz = rr / ny;
    const __half* gA = A + (size_t)bz * azs + (size_t)(by * 128 + lr) * K + lcs;
    const __half* gB = B + (size_t)bz * bzs + (size_t)(bx * 128 + lr) * K + lcs;

#pragma unroll
    for (int tt = 0; tt < 4; tt++) {
        CP16(sb0 + 0*TILE_B + so + tt*SOSTEP, gA + tt*rstep);
        CP16(sb0 + 1*TILE_B + so + tt*SOSTEP, gB + tt*rstep);
    }
    CP_COMMIT();

    const uint32_t a_row = (uint32_t)(wm * 64 + (lane & 15));
    const uint32_t a_kb  = (uint32_t)((lane >> 4) * 16);
    const uint32_t b_row = (uint32_t)(wn * 32 + (lane & 7) + ((lane >> 4) << 3));
    const uint32_t b_kb  = (uint32_t)(((lane >> 3) & 1) * 16);

    while (true) {
        float acc[4][4][4];
#pragma unroll
        for (int i = 0; i < 4; i++)
#pragma unroll
            for (int n = 0; n < 4; n++)
#pragma unroll
                for (int j = 0; j < 4; j++) acc[i][n][j] = 0.f;

        const bool has_next = (t + (int)gridDim.x < ntiles);

        for (int c = 0; c < nch; c++) {
            if (c + 1 < nch) {
                const int k1 = (c + 1) << 6;
                uint32_t sb = sb0 + ((c + 1) & 1) * BUF_B;
#pragma unroll
                for (int tt = 0; tt < 4; tt++) {
                    CP16(sb + 0*TILE_B + so + tt*SOSTEP, gA + tt*rstep + k1);
                    CP16(sb + 1*TILE_B + so + tt*SOSTEP, gB + tt*rstep + k1);
                }
                CP_COMMIT();
                CP_WAIT1();
            } else if (has_next) {
                const int tn = t + gridDim.x;
                const int nbx = tn % nx; int r2 = tn / nx;
                const int nby = r2 % ny, nbz = r2 / ny;
                const __half* nA = A + (size_t)nbz * azs + (size_t)(nby * 128 + lr) * K + lcs;
                const __half* nB = B + (size_t)nbz * bzs + (size_t)(nbx * 128 + lr) * K + lcs;
#pragma unroll
                for (int tt = 0; tt < 4; tt++) {
                    CP16(sb0 + 0*TILE_B + so + tt*SOSTEP, nA + tt*rstep);
                    CP16(sb0 + 1*TILE_B + so + tt*SOSTEP, nB + tt*rstep);
                }
                CP_COMMIT();
                CP_WAIT1();
            } else {
                CP_WAIT0();
            }
            __syncthreads();

            const uint32_t sb = sb0 + (c & 1) * BUF_B;
            const uint32_t sA = sb + 0*TILE_B;
            const uint32_t sB = sb + 1*TILE_B;

#pragma unroll
            for (int ks = 0; ks < 4; ks++) {
                const uint32_t kb = (uint32_t)(ks * 32);
                uint32_t bh[2][4];
#pragma unroll
                for (int np = 0; np < 2; np++) {
                    uint32_t boff = (b_row + np * 16) * (AS * 2) + kb + b_kb;
                    LDSM_X4(bh[np][0], bh[np][1], bh[np][2], bh[np][3], sB + boff);
                }
#pragma unroll
                for (int i = 0; i < 4; i++) {
                    uint32_t a0, a1, a2, a3;
                    uint32_t aoff = (a_row + i * 16) * (AS * 2) + kb + a_kb;
                    LDSM_X4(a0, a1, a2, a3, sA + aoff);
                    MMA16816(acc[i][0], a0, a1, a2, a3, bh[0][0], bh[0][1]);
                    MMA16816(acc[i][1], a0, a1, a2, a3, bh[0][2], bh[0][3]);
                    MMA16816(acc[i][2], a0, a1, a2, a3, bh[1][0], bh[1][1]);
                    MMA16816(acc[i][3], a0, a1, a2, a3, bh[1][2], bh[1][3]);
                }
            }
            __syncthreads();
        }

        {
            const float* biasp = bias ? (bias + (size_t)bz * biaszs) : nullptr;
            float* Cp = C + (size_t)bz * czs;
            __half* Chp = (OUT >= 1) ? (Ch + (size_t)bz * czs) : nullptr;
            const int m0 = by * 128, n0 = bx * 128;
#pragma unroll
            for (int i = 0; i < 4; i++) {
                const int r0 = m0 + wm * 64 + i * 16 + (lane >> 2);
#pragma unroll
                for (int nt = 0; nt < 4; nt++) {
                    const int col = n0 + wn * 32 + nt * 8 + (lane & 3) * 2;
#pragma unroll
                    for (int half = 0; half < 2; half++) {
                        const int r = r0 + half * 8;
                        float v0 = acc[i][nt][half * 2 + 0];
                        float v1 = acc[i][nt][half * 2 + 1];
                        if (biasp) { v0 += biasp[col]; v1 += biasp[col + 1]; }
                        if (ACT == 1) {
                            v0 = 0.5f * v0 * (1.0f + erff(v0 * 0.70710678118654752f));
                            v1 = 0.5f * v1 * (1.0f + erff(v1 * 0.70710678118654752f));
                        }
                        if (OUT != 2) {
                            float2 o; o.x = v0; o.y = v1;
                            *(float2*)(Cp + (size_t)r * N + col) = o;
                        }
                        if (OUT >= 1)
                            *(uint32_t*)(Chp + (size_t)r * cn + col) = cvt2h(v0, v1);
                    }
                }
            }
        }

        if (!has_next) break;
        t += gridDim.x;
        bx = t % nx; rr = t / nx; by = rr % ny; bz = rr / ny;
        gA = A + (size_t)bz * azs + (size_t)(by * 128 + lr) * K + lcs;
        gB = B + (size_t)bz * bzs + (size_t)(bx * 128 + lr) * K + lcs;
    }
}

// ---------------- attention: 128 threads, 2 CTAs/(b,h), causal early-exit ---
__global__ __launch_bounds__(128) void attn_kernel(const float* __restrict__ Q,
                                                   const float* __restrict__ Kp,
                                                   const float* __restrict__ Vp,
                                                   const int* __restrict__ pm,
                                                   __half* __restrict__ Oh,
                                                   int NK, int qst, int kvst,
                                                   int rshift, int pmshift, float scale)
{
    __shared__ float Ks[64][64];
    __shared__ float Vs[64][64];
    __shared__ float bias_s[64];

    const int bh = blockIdx.x >> 1;
    const int hf = blockIdx.x & 1;
    const int b  = bh >> 4;
    const int h  = bh & 15;
    const float* qb = Q  + (size_t)b * NQ_ * qst  + h * 64;
    const float* kb = Kp + (size_t)b * NK  * kvst + h * 64;
    const float* vb = Vp + (size_t)b * NK  * kvst + h * 64;
    const int r = hf * 128 + threadIdx.x;

    float qr[64];
#pragma unroll
    for (int k4 = 0; k4 < 16; k4++) {
        float4 v = *(const float4*)(qb + (size_t)r * qst + k4 * 4);
        qr[k4*4+0] = v.x; qr[k4*4+1] = v.y; qr[k4*4+2] = v.z; qr[k4*4+3] = v.w;
    }

    float m = -1e30f, l = 0.f;
    float o[64];
#pragma unroll
    for (int k = 0; k < 64; k++) o[k] = 0.f;

    const int maxj = r >> rshift;
    int kend = ((hf * 128 + 127) >> rshift) + 1;
    if (kend > NK) kend = NK;

    for (int c0 = 0; c0 < kend; c0 += 64) {
        __syncthreads();
        for (int t = threadIdx.x; t < 1024; t += 128) {
            int j = t >> 4;
            int c = (t & 15) << 2;
            *(float4*)&Ks[j][c] = *(const float4*)(kb + (size_t)(c0 + j) * kvst + c);
            *(float4*)&Vs[j][c] = *(const float4*)(vb + (size_t)(c0 + j) * kvst + c);
        }
        if (threadIdx.x < 64)
            bias_s[threadIdx.x] =
                NEGV * (float)pm[b * SEQ + ((c0 + threadIdx.x) >> pmshift)];
        __syncthreads();

        int jend = maxj - c0;
        if (jend > 63) jend = 63;
        for (int j = 0; j <= jend; j++) {
            float d0 = 0.f, d1 = 0.f, d2 = 0.f, d3 = 0.f;
#pragma unroll
            for (int k = 0; k < 64; k += 4) {
                d0 += qr[k+0] * Ks[j][k+0];
                d1 += qr[k+1] * Ks[j][k+1];
                d2 += qr[k+2] * Ks[j][k+2];
                d3 += qr[k+3] * Ks[j][k+3];
            }
            float sc = ((d0 + d1) + (d2 + d3)) * scale + bias_s[j];
            if (sc > m) {
                float corr = expf(m - sc);
                l = l * corr + 1.f;
#pragma unroll
                for (int k = 0; k < 64; k++) o[k] = o[k] * corr + Vs[j][k];
                m = sc;
            } else {
                float p = expf(sc - m);
                l += p;
#pragma unroll
                for (int k = 0; k < 64; k++) o[k] += p * Vs[j][k];
            }
        }
    }

    float inv = 1.f / l;
    const size_t obase = ((size_t)b * NQ_ + r) * D_ + h * 64;
#pragma unroll
    for (int k2 = 0; k2 < 32; k2++)
        *(uint32_t*)(Oh + obase + k2*2) = cvt2h(o[k2*2] * inv, o[k2*2+1] * inv);
}

// ---------------- LN helpers ----------------
__device__ __forceinline__ void block_reduce2(float& a, float& b)
{
    __shared__ float sa[8], sb[8];
    const unsigned full = 0xffffffffu;
#pragma unroll
    for (int o = 16; o > 0; o >>= 1) {
        a += __shfl_down_sync(full, a, o);
        b += __shfl_down_sync(full, b, o);
    }
    int w = threadIdx.x >> 5, lane = threadIdx.x & 31;
    if (lane == 0) { sa[w] = a; sb[w] = b; }
    __syncthreads();
    float ta = 0.f, tb = 0.f;
#pragma unroll
    for (int i = 0; i < 8; i++) { ta += sa[i]; tb += sb[i]; }
    a = ta; b = tb;
}

__device__ __forceinline__ void block_reduce4(float& a, float& b, float& c, float& d)
{
    __shared__ float s4[8][4];
    const unsigned full = 0xffffffffu;
#pragma unroll
    for (int o = 16; o > 0; o >>= 1) {
        a += __shfl_down_sync(full, a, o);
        b += __shfl_down_sync(full, b, o);
        c += __shfl_down_sync(full, c, o);
        d += __shfl_down_sync(full, d, o);
    }
    int w = threadIdx.x >> 5, lane = threadIdx.x & 31;
    if (lane == 0) { s4[w][0] = a; s4[w][1] = b; s4[w][2] = c; s4[w][3] = d; }
    __syncthreads();
    float ta = 0.f, tb = 0.f, tc = 0.f, td = 0.f;
#pragma unroll
    for (int i = 0; i < 8; i++) {
        ta += s4[i][0]; tb += s4[i][1]; tc += s4[i][2]; td += s4[i][3];
    }
    a = ta; b = tb; c = tc; d = td;
}

// q = LN(q + add) * (1+s) + sh ; fp16 mirror (+ optional concat copy)
__global__ __launch_bounds__(256) void ln_mod_resid(float* __restrict__ q,
                                                    __half* __restrict__ qh,
                                                    __half* __restrict__ qcat,
                                                    const float* __restrict__ add,
                                                    const float* __restrict__ mod,
                                                    int off)
{
    const int row = blockIdx.x;
    const int b = row >> 8, n = row & 255;
    const float* mp = mod + ((size_t)(b * SEQ + (n >> 1))) * (6 * D_) + off;
    const size_t base = (size_t)row * D_;
    const int d = threadIdx.x * 4;

    float4 xv = *(const float4*)(q + base + d);
    float4 av = *(const float4*)(add + base + d);
    float x[4] = {xv.x + av.x, xv.y + av.y, xv.z + av.z, xv.w + av.w};

    float s  = x[0] + x[1] + x[2] + x[3];
    float ss = x[0]*x[0] + x[1]*x[1] + x[2]*x[2] + x[3]*x[3];
    block_reduce2(s, ss);
    float mean = s * (1.f / D_);
    float var  = ss * (1.f / D_) - mean * mean;
    float inv  = rsqrtf(var + 1e-6f);

    float4 sv  = *(const float4*)(mp + d);
    float4 shv = *(const float4*)(mp + D_ + d);
    float y0 = (x[0]-mean)*inv*(1.f+sv.x)+shv.x;
    float y1 = (x[1]-mean)*inv*(1.f+sv.y)+shv.y;
    float y2 = (x[2]-mean)*inv*(1.f+sv.z)+shv.z;
    float y3 = (x[3]-mean)*inv*(1.f+sv.w)+shv.w;
    float4 o; o.x = y0; o.y = y1; o.z = y2; o.w = y3;
    *(float4*)(q + base + d) = o;
    uint2 hh; hh.x = cvt2h(y0, y1); hh.y = cvt2h(y2, y3);
    *(uint2*)(qh + base + d) = hh;
    if (qcat)
        *(uint2*)(qcat + (size_t)row * (2*D_) + D_ + d) = hh;
}

// q = LN((1+al)*q2 + q) * (1+s) + sh ; fp16 mirror
__global__ __launch_bounds__(256) void alpha_ln_mod(float* __restrict__ q,
                                                    __half* __restrict__ qh,
                                                    const float* __restrict__ q2,
                                                    const float* __restrict__ al,
                                                    const float* __restrict__ mod,
                                                    int off)
{
    const int row = blockIdx.x;
    const int b = row >> 8, n = row & 255;
    const float* mp = mod + ((size_t)(b * SEQ + (n >> 1))) * (6 * D_) + off;
    const size_t base = (size_t)row * D_;
    const int d = threadIdx.x * 4;

    float4 qv  = *(const float4*)(q  + base + d);
    float4 q2v = *(const float4*)(q2 + base + d);
    float4 alv = *(const float4*)(al + base + d);
    float x[4];
    x[0] = (1.f+alv.x)*q2v.x + qv.x;
    x[1] = (1.f+alv.y)*q2v.y + qv.y;
    x[2] = (1.f+alv.z)*q2v.z + qv.z;
    x[3] = (1.f+alv.w)*q2v.w + qv.w;

    float s  = x[0] + x[1] + x[2] + x[3];
    float ss = x[0]*x[0] + x[1]*x[1] + x[2]*x[2] + x[3]*x[3];
    block_reduce2(s, ss);
    float mean = s * (1.f / D_);
    float var  = ss * (1.f / D_) - mean * mean;
    float inv  = rsqrtf(var + 1e-6f);

    float4 sv  = *(const float4*)(mp + d);
    float4 shv = *(const float4*)(mp + D_ + d);
    float y0 = (x[0]-mean)*inv*(1.f+sv.x)+shv.x;
    float y1 = (x[1]-mean)*inv*(1.f+sv.y)+shv.y;
    float y2 = (x[2]-mean)*inv*(1.f+sv.z)+shv.z;
    float y3 = (x[3]-mean)*inv*(1.f+sv.w)+shv.w;
    float4 o; o.x = y0; o.y = y1; o.z = y2; o.w = y3;
    *(float4*)(q + base + d) = o;
    uint2 hh; hh.x = cvt2h(y0, y1); hh.y = cvt2h(y2, y3);
    *(uint2*)(qh + base + d) = hh;
}

// all-layer fused CA input LNs: blockIdx.y = layer
__global__ __launch_bounds__(256) void ln_gamma2(__half* __restrict__ kv,
                                                 const float* __restrict__ c,
                                                 const float* __restrict__ pe,
                                                 const float* __restrict__ nk_g,
                                                 const float* __restrict__ nk_b,
                                                 const float* __restrict__ nv_g,
                                                 const float* __restrict__ nv_b)
{
    const int ly = blockIdx.y;
    const float* g1 = nk_g + (size_t)ly * D_;
    const float* b1 = nk_b + (size_t)ly * D_;
    const float* g2 = nv_g + (size_t)ly * D_;
    const float* b2 = nv_b + (size_t)ly * D_;
    __half* kin = kv + (size_t)ly * 2 * MCD_;
    __half* vin = kin + MCD_;

    const int row = blockIdx.x;
    const size_t base = (size_t)row * D_;
    const int d = threadIdx.x * 4;

    float4 cv = *(const float4*)(c  + base + d);
    float4 pv = *(const float4*)(pe + base + d);
    float xk[4] = {cv.x + pv.x, cv.y + pv.y, cv.z + pv.z, cv.w + pv.w};
    float xv[4] = {cv.x, cv.y, cv.z, cv.w};

    float sk = xk[0]+xk[1]+xk[2]+xk[3];
    float ssk = xk[0]*xk[0]+xk[1]*xk[1]+xk[2]*xk[2]+xk[3]*xk[3];
    float sv = xv[0]+xv[1]+xv[2]+xv[3];
    float ssv = xv[0]*xv[0]+xv[1]*xv[1]+xv[2]*xv[2]+xv[3]*xv[3];
    block_reduce4(sk, ssk, sv, ssv);

    float mk = sk * (1.f / D_);
    float ik = rsqrtf(ssk * (1.f / D_) - mk*mk + 1e-5f);
    float mv = sv * (1.f / D_);
    float iv = rsqrtf(ssv * (1.f / D_) - mv*mv + 1e-5f);

    float4 g1v = *(const float4*)(g1 + d);
    float4 b1v = *(const float4*)(b1 + d);
    float4 g2v = *(const float4*)(g2 + d);
    float4 b2v = *(const float4*)(b2 + d);

    float k0 = (xk[0]-mk)*ik*g1v.x+b1v.x;
    float k1 = (xk[1]-mk)*ik*g1v.y+b1v.y;
    float k2 = (xk[2]-mk)*ik*g1v.z+b1v.z;
    float k3 = (xk[3]-mk)*ik*g1v.w+b1v.w;
    uint2 hk; hk.x = cvt2h(k0, k1); hk.y = cvt2h(k2, k3);
    *(uint2*)(kin + base + d) = hk;

    float v0 = (xv[0]-mv)*iv*g2v.x+b2v.x;
    float v1 = (xv[1]-mv)*iv*g2v.y+b2v.y;
    float v2 = (xv[2]-mv)*iv*g2v.z+b2v.z;
    float v3 = (xv[3]-mv)*iv*g2v.w+b2v.w;
    uint2 hv; hv.x = cvt2h(v0, v1); hv.y = cvt2h(v2, v3);
    *(uint2*)(vin + base + d) = hv;
}

__global__ __launch_bounds__(256) void head_kernel(const float* __restrict__ X,
                                                   const float* __restrict__ W,
                                                   const float* __restrict__ bias,
                                                   float* __restrict__ out)
{
    __shared__ float xs[D_];
    const int row = blockIdx.x;
    const size_t base = (size_t)row * D_;
    for (int t = threadIdx.x; t < D_ / 4; t += 256)
        *(float4*)&xs[t * 4] = *(const float4*)(X + base + t * 4);
    __syncthreads();

    int w = threadIdx.x >> 5, lane = threadIdx.x & 31;
    for (int col = w; col < VOCAB; col += 8) {
        float s = 0.f;
        for (int k = lane; k < D_; k += 32) s += xs[k] * W[(size_t)k * VOCAB + col];
#pragma unroll
        for (int o = 16; o > 0; o >>= 1) s += __shfl_down_sync(0xffffffffu, s, o);
        if (lane == 0) out[(size_t)row * VOCAB + col] = s + bias[col];
    }
}

// ---------------- host orchestration ----------------
static float* symaddr_f(const void* s)
{
    void* p = nullptr;
    cudaGetSymbolAddress(&p, s);
    return (float*)p;
}
static __half* symaddr_h(const void* s)
{
    void* p = nullptr;
    cudaGetSymbolAddress(&p, s);
    return (__half*)p;
}
static inline int pgrid(int nt) { return nt < 296 ? nt : 296; }

extern "C" void kernel_launch(void* const* d_in, const int* in_sizes, int n_in,
                              void* d_out, int out_size)
{
    const float* q_in   = (const float*)d_in[0];
    const float* c_in   = (const float*)d_in[1];
    const float* pe_in  = (const float*)d_in[2];
    const float* mod_w  = (const float*)d_in[3];
    const float* mod_b  = (const float*)d_in[4];
    const float* sa_qw  = (const float*)d_in[5];
    const float* sa_kw  = (const float*)d_in[6];
    const float* sa_vw  = (const float*)d_in[7];
    const float* sa_pw  = (const float*)d_in[8];
    const float* sa_pb  = (const float*)d_in[9];
    const float* ca_qw  = (const float*)d_in[10];
    const float* ca_kw  = (const float*)d_in[11];
    const float* ca_vw  = (const float*)d_in[12];
    const float* ca_pw  = (const float*)d_in[13];
    const float* ca_pb  = (const float*)d_in[14];
    const float* nk_g   = (const float*)d_in[15];
    const float* nk_b   = (const float*)d_in[16];
    const float* nv_g   = (const float*)d_in[17];
    const float* nv_b   = (const float*)d_in[18];
    const float* al_w   = (const float*)d_in[19];
    const float* al_b   = (const float*)d_in[20];
    const float* fc1_w  = (const float*)d_in[21];
    const float* fc1_b  = (const float*)d_in[22];
    const float* fc2_w  = (const float*)d_in[23];
    const float* fc2_b  = (const float*)d_in[24];
    const float* head_w = (const float*)d_in[25];
    const float* head_b = (const float*)d_in[26];
    const int*   pm     = (const int*)  d_in[27];
    float* out = (float*)d_out;

    __half* wth   = symaddr_h(g_wth);
    __half* wkvh  = symaddr_h(g_wkvh);
    __half* sc16  = symaddr_h(g_sc16);
    __half* q16   = symaddr_h(g_q16);
    __half* ao16  = symaddr_h(g_ao16);
    __half* kv16  = symaddr_h(g_kv16);
    __half* cat16 = symaddr_h(g_cat16);
    __half* h16   = symaddr_h(g_h16);

    float* mod  = symaddr_f(g_mod);
    float* qbuf = symaddr_f(g_q);
    float* qkv  = symaddr_f(g_qkv);
    float* qp   = symaddr_f(g_qp);
    float* kvp  = symaddr_f(g_kvp);
    float* po   = symaddr_f(g_po);
    float* q2   = symaddr_f(g_q2);
    float* alf  = symaddr_f(g_alf);

    cudaFuncSetAttribute(gemm_mma<0,0>, cudaFuncAttributeMaxDynamicSharedMemorySize, GEMM_SMEM);
    cudaFuncSetAttribute(gemm_mma<0,1>, cudaFuncAttributeMaxDynamicSharedMemorySize, GEMM_SMEM);
    cudaFuncSetAttribute(gemm_mma<1,2>, cudaFuncAttributeMaxDynamicSharedMemorySize, GEMM_SMEM);

    const int MQ = BATCH * NQ_;   // 8192
    const int MC = BATCH * SEQ;   // 4096
    const float scale = 0.125f;
    const size_t MODL = (size_t)MC * 6 * D_;
    const size_t DD   = (size_t)D_ * D_;

    const int ntQ    = (D_/128) * (MQ/128);              // 512
    const int ntQKV  = (3*D_/128) * (MQ/128);            // 1536
    const int ntFc1  = (HID/128) * (MQ/128);             // 2048
    const int ntModA = (6*D_/128) * (MC/128) * NLAYER;   // 9216
    const int ntKVA  = (D_/128) * (MC/128) * 2 * NLAYER; // 3072

    // #1-#5: prerequisites; #6 is a GEMM (ncu -s 5 -c 1)
    silu_h<<<(MC * D_ / 4 + 255) / 256, 256>>>(c_in, sc16, MC * D_ / 4);               // 1
    copy_h<<<(MQ * D_ / 4 + 255) / 256, 256>>>(q_in, qbuf, q16, MQ * D_ / 4);          // 2
    transpose_h<<<dim3(6*D_/32, D_/32, NLAYER), 256>>>(mod_w, wth + OFF_MOD, D_, 6*D_, (size_t)D_*6*D_, WPL); // 3
    transpose_h<<<dim3(32, 32, NLAYER), 256>>>(ca_kw, wkvh,      D_, D_, DD, 2*DD);    // 4
    transpose_h<<<dim3(32, 32, NLAYER), 256>>>(ca_vw, wkvh + DD, D_, D_, DD, 2*DD);    // 5
    // 6: all-layer mod GEMM (single launch, z=6)
    gemm_mma<0,0><<<pgrid(ntModA), 256, GEMM_SMEM>>>(
        sc16, wth + OFF_MOD, mod_b, mod, nullptr,
        MC, 6*D_, D_, 6*D_, 0, WPL, (size_t)6*D_, MODL, ntModA);

    // all-layer CA input LNs + K/V projections (hoisted out of the loop)
    ln_gamma2<<<dim3(MC, NLAYER), 256>>>(kv16, c_in, pe_in, nk_g, nk_b, nv_g, nv_b);
    gemm_mma<0,0><<<pgrid(ntKVA), 256, GEMM_SMEM>>>(
        kv16, wkvh, nullptr, kvp, nullptr,
        MC, D_, D_, D_, MCD_, DD, 0, MCD_, ntKVA);

    // remaining weight transposes (z-batched over layers)
    transpose_h<<<dim3(32, 32, NLAYER), 256>>>(sa_qw, wth + OFF_SAQ,           D_, D_, DD, WPL);
    transpose_h<<<dim3(32, 32, NLAYER), 256>>>(sa_kw, wth + OFF_SAQ + 1048576, D_, D_, DD, WPL);
    transpose_h<<<dim3(32, 32, NLAYER), 256>>>(sa_vw, wth + OFF_SAQ + 2097152, D_, D_, DD, WPL);
    transpose_h<<<dim3(32, 32, NLAYER), 256>>>(sa_pw, wth + OFF_SAP, D_, D_, DD, WPL);
    transpose_h<<<dim3(32, 32, NLAYER), 256>>>(ca_qw, wth + OFF_CAQ, D_, D_, DD, WPL);
    transpose_h<<<dim3(32, 32, NLAYER), 256>>>(ca_pw, wth + OFF_CAP, D_, D_, DD, WPL);
    transpose_h<<<dim3(32, 64, NLAYER), 256>>>(al_w, wth + OFF_AL, 2*D_, D_, 2*DD, WPL);
    transpose_h<<<dim3(HID/32, 32, NLAYER), 256>>>(fc1_w, wth + OFF_FC1, D_, HID, (size_t)D_*HID, WPL);
    transpose_h<<<dim3(32, HID/32, NLAYER), 256>>>(fc2_w, wth + OFF_FC2, HID, D_, (size_t)HID*D_, WPL);

    for (int i = 0; i < NLAYER; i++) {
        size_t wb = (size_t)i * WPL;
        const float* modL = mod + (size_t)i * MODL;
        float* kvpL = kvp + (size_t)i * 2 * MCD_;
        const float* spb = sa_pb + (size_t)i * D_;
        const float* cpb = ca_pb + (size_t)i * D_;
        const float* alb = al_b  + (size_t)i * D_;
        const float* f1b = fc1_b + (size_t)i * HID;
        const float* f2b = fc2_b + (size_t)i * D_;

        // ---- self-attention (fused QKV) ----
        gemm_mma<0,0><<<pgrid(ntQKV), 256, GEMM_SMEM>>>(q16, wth + wb + OFF_SAQ, nullptr, qkv, nullptr, MQ, 3*D_, D_, 3*D_, 0, 0, 0, 0, ntQKV);
        attn_kernel<<<BATCH*NHEAD*2, 128>>>(qkv, qkv + D_, qkv + 2*D_, pm, ao16, NQ_, 3*D_, 3*D_, 0, 1, scale);
        gemm_mma<0,0><<<pgrid(ntQ), 256, GEMM_SMEM>>>(ao16, wth + wb + OFF_SAP, spb, po, nullptr, MQ, D_, D_, D_, 0, 0, 0, 0, ntQ);
        ln_mod_resid<<<MQ, 256>>>(qbuf, q16, cat16, po, modL, 0);

        // ---- cross attention (K/V precomputed) ----
        gemm_mma<0,0><<<pgrid(ntQ), 256, GEMM_SMEM>>>(q16, wth + wb + OFF_CAQ, nullptr, qp, nullptr, MQ, D_, D_, D_, 0, 0, 0, 0, ntQ);
        attn_kernel<<<BATCH*NHEAD*2, 128>>>(qp, kvpL, kvpL + MCD_, pm, ao16, SEQ, D_, D_, 1, 0, scale);
        gemm_mma<0,1><<<pgrid(ntQ), 256, GEMM_SMEM>>>(ao16, wth + wb + OFF_CAP, cpb, q2, cat16, MQ, D_, D_, 2*D_, 0, 0, 0, 0, ntQ);

        // alpha = [q2, q] @ al_w + al_b  (single K=2048 GEMM)
        gemm_mma<0,0><<<pgrid(ntQ), 256, GEMM_SMEM>>>(cat16, wth + wb + OFF_AL, alb, alf, nullptr, MQ, D_, 2*D_, D_, 0, 0, 0, 0, ntQ);
        alpha_ln_mod<<<MQ, 256>>>(qbuf, q16, q2, alf, modL, 2*D_);

        // ---- MLP ----
        gemm_mma<1,2><<<pgrid(ntFc1), 256, GEMM_SMEM>>>(q16, wth + wb + OFF_FC1, f1b, po, h16, MQ, HID, D_, HID, 0, 0, 0, 0, ntFc1);
        gemm_mma<0,0><<<pgrid(ntQ), 256, GEMM_SMEM>>>(h16, wth + wb + OFF_FC2, f2b, po, nullptr, MQ, D_, HID, D_, 0, 0, 0, 0, ntQ);
        ln_mod_resid<<<MQ, 256>>>(qbuf, q16, nullptr, po, modL, 4*D_);
    }

    head_kernel<<<MQ, 256>>>(qbuf, head_w, head_b, out);
}

// round 17
// speedup vs baseline: 1.7514x; 1.0221x over previous
#include <cuda_runtime.h>
#include <cuda_fp16.h>
#include <cstdint>
#include <cstddef>

#define D_    1024
#define BATCH 32
#define SEQ   128
#define NQ_   256
#define HID   4096
#define NHEAD 16
#define NEGV  (-10000.0f)
#define NLAYER 6
#define VOCAB 18

// ---------------- portable PTX helpers (compute_103-safe) -------------------
__device__ __forceinline__ uint32_t smem_u32(const void* p) {
    uint32_t a;
    asm("{ .reg .u64 t; cvta.to.shared.u64 t, %1; cvt.u32.u64 %0, t; }"
        : "=r"(a) : "l"(p));
    return a;
}

#define CP16(s, g) \
    asm volatile("cp.async.cg.shared.global [%0], [%1], 16;" :: "r"(s), "l"(g))
#define CP_COMMIT() asm volatile("cp.async.commit_group;" ::: "memory")
#define CP_WAIT2()  asm volatile("cp.async.wait_group 2;" ::: "memory")
#define CP_WAIT1()  asm volatile("cp.async.wait_group 1;" ::: "memory")
#define CP_WAIT0()  asm volatile("cp.async.wait_group 0;" ::: "memory")

#define LDSM_X4(r0, r1, r2, r3, addr) \
    asm volatile("ldmatrix.sync.aligned.m8n8.x4.shared.b16 {%0,%1,%2,%3}, [%4];" \
                 : "=r"(r0), "=r"(r1), "=r"(r2), "=r"(r3) : "r"(addr))

#define MMA16816(c, a0, a1, a2, a3, b0, b1) \
    asm volatile("mma.sync.aligned.m16n8k16.row.col.f32.f16.f16.f32 " \
                 "{%0,%1,%2,%3}, {%4,%5,%6,%7}, {%8,%9}, {%0,%1,%2,%3};" \
                 : "+f"((c)[0]), "+f"((c)[1]), "+f"((c)[2]), "+f"((c)[3]) \
                 : "r"(a0), "r"(a1), "r"(a2), "r"(a3), "r"(b0), "r"(b1))

__device__ __forceinline__ uint32_t cvt2h(float a, float b) {
    __half2 t = __floats2half2_rn(a, b);
    return *(uint32_t*)&t;
}
__device__ __forceinline__ void h8_to_f8(uint4 v, float* dst) {
    __half2* hp = (__half2*)&v;
#pragma unroll
    for (int i = 0; i < 4; i++) {
        float2 f = __half22float2(hp[i]);
        dst[2*i] = f.x; dst[2*i+1] = f.y;
    }
}

// ---------------- scratch (device globals; allocation-free) ----------------
#define WPL 25165824ULL
#define OFF_MOD 0ULL
#define OFF_SAQ 6291456ULL
#define OFF_SAP 9437184ULL
#define OFF_CAQ 10485760ULL
#define OFF_CAP 13631488ULL
#define OFF_AL  14680064ULL
#define OFF_FC1 16777216ULL
#define OFF_FC2 20971520ULL

#define MCD_ ((size_t)BATCH * SEQ * D_)

__device__ __half g_wth[NLAYER * WPL];
__device__ __half g_wkvh[NLAYER * 2 * D_ * D_];
__device__ __half g_sc16 [BATCH*SEQ*D_];
__device__ __half g_q16  [BATCH*NQ_*D_];
__device__ __half g_ao16 [BATCH*NQ_*D_];
__device__ __half g_kv16 [NLAYER*2*BATCH*SEQ*D_];
__device__ __half g_cat16[BATCH*NQ_*2*D_];
__device__ __half g_h16  [BATCH*NQ_*HID];
__device__ __half g_qkv16[BATCH*NQ_*3*D_];
__device__ __half g_qp16 [BATCH*NQ_*D_];
__device__ __half g_kvp16[NLAYER*2*BATCH*SEQ*D_];

__device__ float g_mod[NLAYER*BATCH*SEQ*6*D_];
__device__ float g_q  [BATCH*NQ_*D_];
__device__ float g_po [BATCH*NQ_*D_];
__device__ float g_q2 [BATCH*NQ_*D_];
__device__ float g_alf[BATCH*NQ_*D_];

// ---------------- weight transpose to fp16 (z-batched) ----------------------
__global__ __launch_bounds__(256) void transpose_h(const float* __restrict__ W,
                                                   __half* __restrict__ oh,
                                                   int K, int N,
                                                   size_t ils, size_t ols)
{
    __shared__ float t[32][33];
    const int z = blockIdx.z;
    W  += (size_t)z * ils;
    oh += (size_t)z * ols;
    const int n0 = blockIdx.x * 32, k0 = blockIdx.y * 32;
    const int tx = threadIdx.x & 31, ty = threadIdx.x >> 5;
#pragma unroll
    for (int r = 0; r < 4; r++)
        t[ty + 8*r][tx] = W[(size_t)(k0 + ty + 8*r) * N + n0 + tx];
    __syncthreads();
#pragma unroll
    for (int s = 0; s < 2; s++) {
        int id = threadIdx.x + s * 256;
        int n  = id >> 4;
        int kp = (id & 15) * 2;
        *(uint32_t*)(oh + (size_t)(n0 + n) * K + k0 + kp) =
            cvt2h(t[kp][n], t[kp + 1][n]);
    }
}

__global__ void silu_h(const float* __restrict__ x, __half* __restrict__ oh, int n4)
{
    int i = blockIdx.x * blockDim.x + threadIdx.x;
    if (i >= n4) return;
    float4 v = ((const float4*)x)[i];
    float f[4] = {v.x, v.y, v.z, v.w};
#pragma unroll
    for (int j = 0; j < 4; j++) f[j] = f[j] / (1.f + expf(-f[j]));
    uint2 hh; hh.x = cvt2h(f[0], f[1]); hh.y = cvt2h(f[2], f[3]);
    *(uint2*)(oh + 4*(size_t)i) = hh;
}

__global__ void copy_h(const float* __restrict__ x, float* __restrict__ o,
                       __half* __restrict__ oh, int n4)
{
    int i = blockIdx.x * blockDim.x + threadIdx.x;
    if (i >= n4) return;
    float4 v = ((const float4*)x)[i];
    ((float4*)o)[i] = v;
    uint2 hh; hh.x = cvt2h(v.x, v.y); hh.y = cvt2h(v.z, v.w);
    *(uint2*)(oh + 4*(size_t)i) = hh;
}

// ---------------- persistent HMMA GEMM (1-term fp16, BK=64, 3-stage) --------
// Warp tile 64Mx32N (warps 2x4). OUT: 0 fp32, 1 fp32+fp16, 2 fp16 only.
#define AS 72
#define TILE_B (128 * AS * 2)       // 18432 B
#define BUF_B  (2 * TILE_B)         // 36864 B (A, B)
#define GEMM_SMEM (3 * BUF_B)       // 110592 B (3 stages)

template<int ACT, int OUT>
__global__ __launch_bounds__(256, 2) void gemm_mma(const __half* __restrict__ A,
                                                   const __half* __restrict__ B,
                                                   const float* __restrict__ bias,
                                                   float* __restrict__ C,
                                                   __half* __restrict__ Ch,
                                                   int M, int N, int K, int cn,
                                                   size_t azs, size_t bzs,
                                                   size_t biaszs, size_t czs,
                                                   int ntiles)
{
    extern __shared__ __align__(128) char dynsm[];
    const uint32_t sb0 = smem_u32(dynsm);
    const int nx = N >> 7, ny = M >> 7;

    const int tid  = threadIdx.x;
    const int lane = tid & 31;
    const int wid  = tid >> 5;
    const int wm   = wid & 1;
    const int wn   = wid >> 1;

    const int lr  = tid >> 3;
    const int lcs = (tid & 7) * 8;
    const uint32_t so = (uint32_t)(lr * AS + lcs) * 2;
    const uint32_t SOSTEP = 32u * AS * 2;
    const size_t rstep = (size_t)32 * K;
    const int nch = K >> 6;

    int t = blockIdx.x;
    int bx = t % nx, rr = t / nx, by = rr % ny, bz = rr / ny;
    const __half* gA = A + (size_t)bz * azs + (size_t)(by * 128 + lr) * K + lcs;
    const __half* gB = B + (size_t)bz * bzs + (size_t)(bx * 128 + lr) * K + lcs;

    // prologue: chunks 0 and 1 into stages 0, 1
#pragma unroll
    for (int tt = 0; tt < 4; tt++) {
        CP16(sb0 + 0*BUF_B + 0*TILE_B + so + tt*SOSTEP, gA + tt*rstep);
        CP16(sb0 + 0*BUF_B + 1*TILE_B + so + tt*SOSTEP, gB + tt*rstep);
    }
    CP_COMMIT();
#pragma unroll
    for (int tt = 0; tt < 4; tt++) {
        CP16(sb0 + 1*BUF_B + 0*TILE_B + so + tt*SOSTEP, gA + tt*rstep + 64);
        CP16(sb0 + 1*BUF_B + 1*TILE_B + so + tt*SOSTEP, gB + tt*rstep + 64);
    }
    CP_COMMIT();
    int pend = 2;            // committed groups not yet waited
    int lb = 2;              // next load stage
    int cb = 0;              // next compute stage

    const uint32_t a_row = (uint32_t)(wm * 64 + (lane & 15));
    const uint32_t a_kb  = (uint32_t)((lane >> 4) * 16);
    const uint32_t b_row = (uint32_t)(wn * 32 + (lane & 7) + ((lane >> 4) << 3));
    const uint32_t b_kb  = (uint32_t)(((lane >> 3) & 1) * 16);

    while (true) {
        float acc[4][4][4];
#pragma unroll
        for (int i = 0; i < 4; i++)
#pragma unroll
            for (int n = 0; n < 4; n++)
#pragma unroll
                for (int j = 0; j < 4; j++) acc[i][n][j] = 0.f;

        const bool has_next = (t + (int)gridDim.x < ntiles);

        for (int c = 0; c < nch; c++) {
            const int cl = c + 2;
            if (cl < nch) {
                const int k1 = cl << 6;
                uint32_t sb = sb0 + lb * BUF_B;
#pragma unroll
                for (int tt = 0; tt < 4; tt++) {
                    CP16(sb + 0*TILE_B + so + tt*SOSTEP, gA + tt*rstep + k1);
                    CP16(sb + 1*TILE_B + so + tt*SOSTEP, gB + tt*rstep + k1);
                }
                CP_COMMIT();
                lb = (lb + 1 == 3) ? 0 : lb + 1;
                pend++;
            } else if (has_next) {
                const int tn = t + gridDim.x;
                const int nbx = tn % nx; int r2 = tn / nx;
                const int nby = r2 % ny, nbz = r2 / ny;
                const __half* nA = A + (size_t)nbz * azs + (size_t)(nby * 128 + lr) * K + lcs;
                const __half* nB = B + (size_t)nbz * bzs + (size_t)(nbx * 128 + lr) * K + lcs;
                const int k1 = (cl - nch) << 6;
                uint32_t sb = sb0 + lb * BUF_B;
#pragma unroll
                for (int tt = 0; tt < 4; tt++) {
                    CP16(sb + 0*TILE_B + so + tt*SOSTEP, nA + tt*rstep + k1);
                    CP16(sb + 1*TILE_B + so + tt*SOSTEP, nB + tt*rstep + k1);
                }
                CP_COMMIT();
                lb = (lb + 1 == 3) ? 0 : lb + 1;
                pend++;
            }
            if (pend == 3)      { CP_WAIT2(); }
            else if (pend == 2) { CP_WAIT1(); }
            else                { CP_WAIT0(); }
            pend--;
            __syncthreads();

            const uint32_t sb = sb0 + cb * BUF_B;
            const uint32_t sA = sb + 0*TILE_B;
            const uint32_t sB = sb + 1*TILE_B;

#pragma unroll
            for (int ks = 0; ks < 4; ks++) {
                const uint32_t kb = (uint32_t)(ks * 32);
                uint32_t bh[2][4];
#pragma unroll
                for (int np = 0; np < 2; np++) {
                    uint32_t boff = (b_row + np * 16) * (AS * 2) + kb + b_kb;
                    LDSM_X4(bh[np][0], bh[np][1], bh[np][2], bh[np][3], sB + boff);
                }
#pragma unroll
                for (int i = 0; i < 4; i++) {
                    uint32_t a0, a1, a2, a3;
                    uint32_t aoff = (a_row + i * 16) * (AS * 2) + kb + a_kb;
                    LDSM_X4(a0, a1, a2, a3, sA + aoff);
                    MMA16816(acc[i][0], a0, a1, a2, a3, bh[0][0], bh[0][1]);
                    MMA16816(acc[i][1], a0, a1, a2, a3, bh[0][2], bh[0][3]);
                    MMA16816(acc[i][2], a0, a1, a2, a3, bh[1][0], bh[1][1]);
                    MMA16816(acc[i][3], a0, a1, a2, a3, bh[1][2], bh[1][3]);
                }
            }
            cb = (cb + 1 == 3) ? 0 : cb + 1;
            __syncthreads();
        }

        // epilogue (next tile's chunks 0,1 already in flight)
        {
            const float* biasp = bias ? (bias + (size_t)bz * biaszs) : nullptr;
            float* Cp = (OUT != 2) ? (C + (size_t)bz * czs) : nullptr;
            __half* Chp = (OUT >= 1) ? (Ch + (size_t)bz * czs) : nullptr;
            const int m0 = by * 128, n0 = bx * 128;
#pragma unroll
            for (int i = 0; i < 4; i++) {
                const int r0 = m0 + wm * 64 + i * 16 + (lane >> 2);
#pragma unroll
                for (int nt = 0; nt < 4; nt++) {
                    const int col = n0 + wn * 32 + nt * 8 + (lane & 3) * 2;
#pragma unroll
                    for (int half = 0; half < 2; half++) {
                        const int r = r0 + half * 8;
                        float v0 = acc[i][nt][half * 2 + 0];
                        float v1 = acc[i][nt][half * 2 + 1];
                        if (biasp) { v0 += biasp[col]; v1 += biasp[col + 1]; }
                        if (ACT == 1) {
                            v0 = 0.5f * v0 * (1.0f + erff(v0 * 0.70710678118654752f));
                            v1 = 0.5f * v1 * (1.0f + erff(v1 * 0.70710678118654752f));
                        }
                        if (OUT != 2) {
                            float2 o; o.x = v0; o.y = v1;
                            *(float2*)(Cp + (size_t)r * N + col) = o;
                        }
                        if (OUT >= 1)
                            *(uint32_t*)(Chp + (size_t)r * cn + col) = cvt2h(v0, v1);
                    }
                }
            }
        }

        if (!has_next) break;
        t += gridDim.x;
        bx = t % nx; rr = t / nx; by = rr % ny; bz = rr / ny;
        gA = A + (size_t)bz * azs + (size_t)(by * 128 + lr) * K + lcs;
        gB = B + (size_t)bz * bzs + (size_t)(bx * 128 + lr) * K + lcs;
    }
}

// ---------------- attention: fp16 in, fp32 math, fp16 out -------------------
__global__ __launch_bounds__(128) void attn_kernel(const __half* __restrict__ Q,
                                                   const __half* __restrict__ Kp,
                                                   const __half* __restrict__ Vp,
                                                   const int* __restrict__ pm,
                                                   __half* __restrict__ Oh,
                                                   int NK, int qst, int kvst,
                                                   int rshift, int pmshift, float scale)
{
    __shared__ float Ks[64][64];
    __shared__ float Vs[64][64];
    __shared__ float bias_s[64];

    const int bh = blockIdx.x >> 1;
    const int hf = blockIdx.x & 1;
    const int b  = bh >> 4;
    const int h  = bh & 15;
    const __half* qb = Q  + (size_t)b * NQ_ * qst  + h * 64;
    const __half* kb = Kp + (size_t)b * NK  * kvst + h * 64;
    const __half* vb = Vp + (size_t)b * NK  * kvst + h * 64;
    const int r = hf * 128 + threadIdx.x;

    float qr[64];
#pragma unroll
    for (int k8 = 0; k8 < 8; k8++) {
        uint4 v = *(const uint4*)(qb + (size_t)r * qst + k8 * 8);
        h8_to_f8(v, qr + k8 * 8);
    }

    float m = -1e30f, l = 0.f;
    float o[64];
#pragma unroll
    for (int k = 0; k < 64; k++) o[k] = 0.f;

    const int maxj = r >> rshift;
    int kend = ((hf * 128 + 127) >> rshift) + 1;
    if (kend > NK) kend = NK;

    for (int c0 = 0; c0 < kend; c0 += 64) {
        __syncthreads();
        for (int t = threadIdx.x; t < 512; t += 128) {
            int j = t >> 3;
            int c = (t & 7) * 8;
            float f[8];
            uint4 kv = *(const uint4*)(kb + (size_t)(c0 + j) * kvst + c);
            h8_to_f8(kv, f);
            *(float4*)&Ks[j][c]     = *(float4*)&f[0];
            *(float4*)&Ks[j][c + 4] = *(float4*)&f[4];
            uint4 vv = *(const uint4*)(vb + (size_t)(c0 + j) * kvst + c);
            h8_to_f8(vv, f);
            *(float4*)&Vs[j][c]     = *(float4*)&f[0];
            *(float4*)&Vs[j][c + 4] = *(float4*)&f[4];
        }
        if (threadIdx.x < 64)
            bias_s[threadIdx.x] =
                NEGV * (float)pm[b * SEQ + ((c0 + threadIdx.x) >> pmshift)];
        __syncthreads();

        int jend = maxj - c0;
        if (jend > 63) jend = 63;
        for (int j = 0; j <= jend; j++) {
            float d0 = 0.f, d1 = 0.f, d2 = 0.f, d3 = 0.f;
#pragma unroll
            for (int k = 0; k < 64; k += 4) {
                d0 += qr[k+0] * Ks[j][k+0];
                d1 += qr[k+1] * Ks[j][k+1];
                d2 += qr[k+2] * Ks[j][k+2];
                d3 += qr[k+3] * Ks[j][k+3];
            }
            float sc = ((d0 + d1) + (d2 + d3)) * scale + bias_s[j];
            if (sc > m) {
                float corr = expf(m - sc);
                l = l * corr + 1.f;
#pragma unroll
                for (int k = 0; k < 64; k++) o[k] = o[k] * corr + Vs[j][k];
                m = sc;
            } else {
                float p = expf(sc - m);
                l += p;
#pragma unroll
                for (int k = 0; k < 64; k++) o[k] += p * Vs[j][k];
            }
        }
    }

    float inv = 1.f / l;
    const size_t obase = ((size_t)b * NQ_ + r) * D_ + h * 64;
#pragma unroll
    for (int k2 = 0; k2 < 32; k2++)
        *(uint32_t*)(Oh + obase + k2*2) = cvt2h(o[k2*2] * inv, o[k2*2+1] * inv);
}

// ---------------- LN helpers ----------------
__device__ __forceinline__ void block_reduce2(float& a, float& b)
{
    __shared__ float sa[8], sb[8];
    const unsigned full = 0xffffffffu;
#pragma unroll
    for (int o = 16; o > 0; o >>= 1) {
        a += __shfl_down_sync(full, a, o);
        b += __shfl_down_sync(full, b, o);
    }
    int w = threadIdx.x >> 5, lane = threadIdx.x & 31;
    if (lane == 0) { sa[w] = a; sb[w] = b; }
    __syncthreads();
    float ta = 0.f, tb = 0.f;
#pragma unroll
    for (int i = 0; i < 8; i++) { ta += sa[i]; tb += sb[i]; }
    a = ta; b = tb;
}

__device__ __forceinline__ void block_reduce4(float& a, float& b, float& c, float& d)
{
    __shared__ float s4[8][4];
    const unsigned full = 0xffffffffu;
#pragma unroll
    for (int o = 16; o > 0; o >>= 1) {
        a += __shfl_down_sync(full, a, o);
        b += __shfl_down_sync(full, b, o);
        c += __shfl_down_sync(full, c, o);
        d += __shfl_down_sync(full, d, o);
    }
    int w = threadIdx.x >> 5, lane = threadIdx.x & 31;
    if (lane == 0) { s4[w][0] = a; s4[w][1] = b; s4[w][2] = c; s4[w][3] = d; }
    __syncthreads();
    float ta = 0.f, tb = 0.f, tc = 0.f, td = 0.f;
#pragma unroll
    for (int i = 0; i < 8; i++) {
        ta += s4[i][0]; tb += s4[i][1]; tc += s4[i][2]; td += s4[i][3];
    }
    a = ta; b = tb; c = tc; d = td;
}

// q = LN(q + add) * (1+s) + sh ; fp16 mirror (+ optional concat copy)
__global__ __launch_bounds__(256) void ln_mod_resid(float* __restrict__ q,
                                                    __half* __restrict__ qh,
                                                    __half* __restrict__ qcat,
                                                    const float* __restrict__ add,
                                                    const float* __restrict__ mod,
                                                    int off)
{
    const int row = blockIdx.x;
    const int b = row >> 8, n = row & 255;
    const float* mp = mod + ((size_t)(b * SEQ + (n >> 1))) * (6 * D_) + off;
    const size_t base = (size_t)row * D_;
    const int d = threadIdx.x * 4;

    float4 xv = *(const float4*)(q + base + d);
    float4 av = *(const float4*)(add + base + d);
    float x[4] = {xv.x + av.x, xv.y + av.y, xv.z + av.z, xv.w + av.w};

    float s  = x[0] + x[1] + x[2] + x[3];
    float ss = x[0]*x[0] + x[1]*x[1] + x[2]*x[2] + x[3]*x[3];
    block_reduce2(s, ss);
    float mean = s * (1.f / D_);
    float var  = ss * (1.f / D_) - mean * mean;
    float inv  = rsqrtf(var + 1e-6f);

    float4 sv  = *(const float4*)(mp + d);
    float4 shv = *(const float4*)(mp + D_ + d);
    float y0 = (x[0]-mean)*inv*(1.f+sv.x)+shv.x;
    float y1 = (x[1]-mean)*inv*(1.f+sv.y)+shv.y;
    float y2 = (x[2]-mean)*inv*(1.f+sv.z)+shv.z;
    float y3 = (x[3]-mean)*inv*(1.f+sv.w)+shv.w;
    float4 o; o.x = y0; o.y = y1; o.z = y2; o.w = y3;
    *(float4*)(q + base + d) = o;
    uint2 hh; hh.x = cvt2h(y0, y1); hh.y = cvt2h(y2, y3);
    *(uint2*)(qh + base + d) = hh;
    if (qcat)
        *(uint2*)(qcat + (size_t)row * (2*D_) + D_ + d) = hh;
}

// q = LN((1+al)*q2 + q) * (1+s) + sh ; fp16 mirror
__global__ __launch_bounds__(256) void alpha_ln_mod(float* __restrict__ q,
                                                    __half* __restrict__ qh,
                                                    const float* __restrict__ q2,
                                                    const float* __restrict__ al,
                                                    const float* __restrict__ mod,
                                                    int off)
{
    const int row = blockIdx.x;
    const int b = row >> 8, n = row & 255;
    const float* mp = mod + ((size_t)(b * SEQ + (n >> 1))) * (6 * D_) + off;
    const size_t base = (size_t)row * D_;
    const int d = threadIdx.x * 4;

    float4 qv  = *(const float4*)(q  + base + d);
    float4 q2v = *(const float4*)(q2 + base + d);
    float4 alv = *(const float4*)(al + base + d);
    float x[4];
    x[0] = (1.f+alv.x)*q2v.x + qv.x;
    x[1] = (1.f+alv.y)*q2v.y + qv.y;
    x[2] = (1.f+alv.z)*q2v.z + qv.z;
    x[3] = (1.f+alv.w)*q2v.w + qv.w;

    float s  = x[0] + x[1] + x[2] + x[3];
    float ss = x[0]*x[0] + x[1]*x[1] + x[2]*x[2] + x[3]*x[3];
    block_reduce2(s, ss);
    float mean = s * (1.f / D_);
    float var  = ss * (1.f / D_) - mean * mean;
    float inv  = rsqrtf(var + 1e-6f);

    float4 sv  = *(const float4*)(mp + d);
    float4 shv = *(const float4*)(mp + D_ + d);
    float y0 = (x[0]-mean)*inv*(1.f+sv.x)+shv.x;
    float y1 = (x[1]-mean)*inv*(1.f+sv.y)+shv.y;
    float y2 = (x[2]-mean)*inv*(1.f+sv.z)+shv.z;
    float y3 = (x[3]-mean)*inv*(1.f+sv.w)+shv.w;
    float4 o; o.x = y0; o.y = y1; o.z = y2; o.w = y3;
    *(float4*)(q + base + d) = o;
    uint2 hh; hh.x = cvt2h(y0, y1); hh.y = cvt2h(y2, y3);
    *(uint2*)(qh + base + d) = hh;
}

// all-layer fused CA input LNs: blockIdx.y = layer
__global__ __launch_bounds__(256) void ln_gamma2(__half* __restrict__ kv,
                                                 const float* __restrict__ c,
                                                 const float* __restrict__ pe,
                                                 const float* __restrict__ nk_g,
                                                 const float* __restrict__ nk_b,
                                                 const float* __restrict__ nv_g,
                                                 const float* __restrict__ nv_b)
{
    const int ly = blockIdx.y;
    const float* g1 = nk_g + (size_t)ly * D_;
    const float* b1 = nk_b + (size_t)ly * D_;
    const float* g2 = nv_g + (size_t)ly * D_;
    const float* b2 = nv_b + (size_t)ly * D_;
    __half* kin = kv + (size_t)ly * 2 * MCD_;
    __half* vin = kin + MCD_;

    const int row = blockIdx.x;
    const size_t base = (size_t)row * D_;
    const int d = threadIdx.x * 4;

    float4 cv = *(const float4*)(c  + base + d);
    float4 pv = *(const float4*)(pe + base + d);
    float xk[4] = {cv.x + pv.x, cv.y + pv.y, cv.z + pv.z, cv.w + pv.w};
    float xv[4] = {cv.x, cv.y, cv.z, cv.w};

    float sk = xk[0]+xk[1]+xk[2]+xk[3];
    float ssk = xk[0]*xk[0]+xk[1]*xk[1]+xk[2]*xk[2]+xk[3]*xk[3];
    float sv = xv[0]+xv[1]+xv[2]+xv[3];
    float ssv = xv[0]*xv[0]+xv[1]*xv[1]+xv[2]*xv[2]+xv[3]*xv[3];
    block_reduce4(sk, ssk, sv, ssv);

    float mk = sk * (1.f / D_);
    float ik = rsqrtf(ssk * (1.f / D_) - mk*mk + 1e-5f);
    float mv = sv * (1.f / D_);
    float iv = rsqrtf(ssv * (1.f / D_) - mv*mv + 1e-5f);

    float4 g1v = *(const float4*)(g1 + d);
    float4 b1v = *(const float4*)(b1 + d);
    float4 g2v = *(const float4*)(g2 + d);
    float4 b2v = *(const float4*)(b2 + d);

    float k0 = (xk[0]-mk)*ik*g1v.x+b1v.x;
    float k1 = (xk[1]-mk)*ik*g1v.y+b1v.y;
    float k2 = (xk[2]-mk)*ik*g1v.z+b1v.z;
    float k3 = (xk[3]-mk)*ik*g1v.w+b1v.w;
    uint2 hk; hk.x = cvt2h(k0, k1); hk.y = cvt2h(k2, k3);
    *(uint2*)(kin + base + d) = hk;

    float v0 = (xv[0]-mv)*iv*g2v.x+b2v.x;
    float v1 = (xv[1]-mv)*iv*g2v.y+b2v.y;
    float v2 = (xv[2]-mv)*iv*g2v.z+b2v.z;
    float v3 = (xv[3]-mv)*iv*g2v.w+b2v.w;
    uint2 hv; hv.x = cvt2h(v0, v1); hv.y = cvt2h(v2, v3);
    *(uint2*)(vin + base + d) = hv;
}

__global__ __launch_bounds__(256) void head_kernel(const float* __restrict__ X,
                                                   const float* __restrict__ W,
                                                   const float* __restrict__ bias,
                                                   float* __restrict__ out)
{
    __shared__ float xs[D_];
    const int row = blockIdx.x;
    const size_t base = (size_t)row * D_;
    for (int t = threadIdx.x; t < D_ / 4; t += 256)
        *(float4*)&xs[t * 4] = *(const float4*)(X + base + t * 4);
    __syncthreads();

    int w = threadIdx.x >> 5, lane = threadIdx.x & 31;
    for (int col = w; col < VOCAB; col += 8) {
        float s = 0.f;
        for (int k = lane; k < D_; k += 32) s += xs[k] * W[(size_t)k * VOCAB + col];
#pragma unroll
        for (int o = 16; o > 0; o >>= 1) s += __shfl_down_sync(0xffffffffu, s, o);
        if (lane == 0) out[(size_t)row * VOCAB + col] = s + bias[col];
    }
}

// ---------------- host orchestration ----------------
static float* symaddr_f(const void* s)
{
    void* p = nullptr;
    cudaGetSymbolAddress(&p, s);
    return (float*)p;
}
static __half* symaddr_h(const void* s)
{
    void* p = nullptr;
    cudaGetSymbolAddress(&p, s);
    return (__half*)p;
}
static inline int pgrid(int nt) { return nt < 296 ? nt : 296; }

extern "C" void kernel_launch(void* const* d_in, const int* in_sizes, int n_in,
                              void* d_out, int out_size)
{
    const float* q_in   = (const float*)d_in[0];
    const float* c_in   = (const float*)d_in[1];
    const float* pe_in  = (const float*)d_in[2];
    const float* mod_w  = (const float*)d_in[3];
    const float* mod_b  = (const float*)d_in[4];
    const float* sa_qw  = (const float*)d_in[5];
    const float* sa_kw  = (const float*)d_in[6];
    const float* sa_vw  = (const float*)d_in[7];
    const float* sa_pw  = (const float*)d_in[8];
    const float* sa_pb  = (const float*)d_in[9];
    const float* ca_qw  = (const float*)d_in[10];
    const float* ca_kw  = (const float*)d_in[11];
    const float* ca_vw  = (const float*)d_in[12];
    const float* ca_pw  = (const float*)d_in[13];
    const float* ca_pb  = (const float*)d_in[14];
    const float* nk_g   = (const float*)d_in[15];
    const float* nk_b   = (const float*)d_in[16];
    const float* nv_g   = (const float*)d_in[17];
    const float* nv_b   = (const float*)d_in[18];
    const float* al_w   = (const float*)d_in[19];
    const float* al_b   = (const float*)d_in[20];
    const float* fc1_w  = (const float*)d_in[21];
    const float* fc1_b  = (const float*)d_in[22];
    const float* fc2_w  = (const float*)d_in[23];
    const float* fc2_b  = (const float*)d_in[24];
    const float* head_w = (const float*)d_in[25];
    const float* head_b = (const float*)d_in[26];
    const int*   pm     = (const int*)  d_in[27];
    float* out = (float*)d_out;

    __half* wth   = symaddr_h(g_wth);
    __half* wkvh  = symaddr_h(g_wkvh);
    __half* sc16  = symaddr_h(g_sc16);
    __half* q16   = symaddr_h(g_q16);
    __half* ao16  = symaddr_h(g_ao16);
    __half* kv16  = symaddr_h(g_kv16);
    __half* cat16 = symaddr_h(g_cat16);
    __half* h16   = symaddr_h(g_h16);
    __half* qkv16 = symaddr_h(g_qkv16);
    __half* qp16  = symaddr_h(g_qp16);
    __half* kvp16 = symaddr_h(g_kvp16);

    float* mod  = symaddr_f(g_mod);
    float* qbuf = symaddr_f(g_q);
    float* po   = symaddr_f(g_po);
    float* q2   = symaddr_f(g_q2);
    float* alf  = symaddr_f(g_alf);

    cudaFuncSetAttribute(gemm_mma<0,0>, cudaFuncAttributeMaxDynamicSharedMemorySize, GEMM_SMEM);
    cudaFuncSetAttribute(gemm_mma<0,1>, cudaFuncAttributeMaxDynamicSharedMemorySize, GEMM_SMEM);
    cudaFuncSetAttribute(gemm_mma<0,2>, cudaFuncAttributeMaxDynamicSharedMemorySize, GEMM_SMEM);
    cudaFuncSetAttribute(gemm_mma<1,2>, cudaFuncAttributeMaxDynamicSharedMemorySize, GEMM_SMEM);

    const int MQ = BATCH * NQ_;   // 8192
    const int MC = BATCH * SEQ;   // 4096
    const float scale = 0.125f;
    const size_t MODL = (size_t)MC * 6 * D_;
    const size_t DD   = (size_t)D_ * D_;

    const int ntQ    = (D_/128) * (MQ/128);              // 512
    const int ntQKV  = (3*D_/128) * (MQ/128);            // 1536
    const int ntFc1  = (HID/128) * (MQ/128);             // 2048
    const int ntModA = (6*D_/128) * (MC/128) * NLAYER;   // 9216
    const int ntKVA  = (D_/128) * (MC/128) * 2 * NLAYER; // 3072

    // #1-#5: prerequisites; #6 is the mod GEMM (ncu -s 5 -c 1)
    silu_h<<<(MC * D_ / 4 + 255) / 256, 256>>>(c_in, sc16, MC * D_ / 4);
    copy_h<<<(MQ * D_ / 4 + 255) / 256, 256>>>(q_in, qbuf, q16, MQ * D_ / 4);
    transpose_h<<<dim3(6*D_/32, D_/32, NLAYER), 256>>>(mod_w, wth + OFF_MOD, D_, 6*D_, (size_t)D_*6*D_, WPL);
    transpose_h<<<dim3(32, 32, NLAYER), 256>>>(ca_kw, wkvh,      D_, D_, DD, 2*DD);
    transpose_h<<<dim3(32, 32, NLAYER), 256>>>(ca_vw, wkvh + DD, D_, D_, DD, 2*DD);
    gemm_mma<0,0><<<pgrid(ntModA), 256, GEMM_SMEM>>>(
        sc16, wth + OFF_MOD, mod_b, mod, nullptr,
        MC, 6*D_, D_, 6*D_, 0, WPL, (size_t)6*D_, MODL, ntModA);

    // all-layer CA input LNs + K/V projections (fp16 out)
    ln_gamma2<<<dim3(MC, NLAYER), 256>>>(kv16, c_in, pe_in, nk_g, nk_b, nv_g, nv_b);
    gemm_mma<0,2><<<pgrid(ntKVA), 256, GEMM_SMEM>>>(
        kv16, wkvh, nullptr, nullptr, kvp16,
        MC, D_, D_, D_, MCD_, DD, 0, MCD_, ntKVA);

    // remaining weight transposes (z-batched over layers)
    transpose_h<<<dim3(32, 32, NLAYER), 256>>>(sa_qw, wth + OFF_SAQ,           D_, D_, DD, WPL);
    transpose_h<<<dim3(32, 32, NLAYER), 256>>>(sa_kw, wth + OFF_SAQ + 1048576, D_, D_, DD, WPL);
    transpose_h<<<dim3(32, 32, NLAYER), 256>>>(sa_vw, wth + OFF_SAQ + 2097152, D_, D_, DD, WPL);
    transpose_h<<<dim3(32, 32, NLAYER), 256>>>(sa_pw, wth + OFF_SAP, D_, D_, DD, WPL);
    transpose_h<<<dim3(32, 32, NLAYER), 256>>>(ca_qw, wth + OFF_CAQ, D_, D_, DD, WPL);
    transpose_h<<<dim3(32, 32, NLAYER), 256>>>(ca_pw, wth + OFF_CAP, D_, D_, DD, WPL);
    transpose_h<<<dim3(32, 64, NLAYER), 256>>>(al_w, wth + OFF_AL, 2*D_, D_, 2*DD, WPL);
    transpose_h<<<dim3(HID/32, 32, NLAYER), 256>>>(fc1_w, wth + OFF_FC1, D_, HID, (size_t)D_*HID, WPL);
    transpose_h<<<dim3(32, HID/32, NLAYER), 256>>>(fc2_w, wth + OFF_FC2, HID, D_, (size_t)HID*D_, WPL);

    for (int i = 0; i < NLAYER; i++) {
        size_t wb = (size_t)i * WPL;
        const float* modL = mod + (size_t)i * MODL;
        __half* kvpL = kvp16 + (size_t)i * 2 * MCD_;
        const float* spb = sa_pb + (size_t)i * D_;
        const float* cpb = ca_pb + (size_t)i * D_;
        const float* alb = al_b  + (size_t)i * D_;
        const float* f1b = fc1_b + (size_t)i * HID;
        const float* f2b = fc2_b + (size_t)i * D_;

        // ---- self-attention (fused QKV, fp16) ----
        gemm_mma<0,2><<<pgrid(ntQKV), 256, GEMM_SMEM>>>(q16, wth + wb + OFF_SAQ, nullptr, nullptr, qkv16, MQ, 3*D_, D_, 3*D_, 0, 0, 0, 0, ntQKV);
        attn_kernel<<<BATCH*NHEAD*2, 128>>>(qkv16, qkv16 + D_, qkv16 + 2*D_, pm, ao16, NQ_, 3*D_, 3*D_, 0, 1, scale);
        gemm_mma<0,0><<<pgrid(ntQ), 256, GEMM_SMEM>>>(ao16, wth + wb + OFF_SAP, spb, po, nullptr, MQ, D_, D_, D_, 0, 0, 0, 0, ntQ);
        ln_mod_resid<<<MQ, 256>>>(qbuf, q16, cat16, po, modL, 0);

        // ---- cross attention (K/V precomputed, fp16) ----
        gemm_mma<0,2><<<pgrid(ntQ), 256, GEMM_SMEM>>>(q16, wth + wb + OFF_CAQ, nullptr, nullptr, qp16, MQ, D_, D_, D_, 0, 0, 0, 0, ntQ);
        attn_kernel<<<BATCH*NHEAD*2, 128>>>(qp16, kvpL, kvpL + MCD_, pm, ao16, SEQ, D_, D_, 1, 0, scale);
        gemm_mma<0,1><<<pgrid(ntQ), 256, GEMM_SMEM>>>(ao16, wth + wb + OFF_CAP, cpb, q2, cat16, MQ, D_, D_, 2*D_, 0, 0, 0, 0, ntQ);

        // alpha = [q2, q] @ al_w + al_b  (single K=2048 GEMM)
        gemm_mma<0,0><<<pgrid(ntQ), 256, GEMM_SMEM>>>(cat16, wth + wb + OFF_AL, alb, alf, nullptr, MQ, D_, 2*D_, D_, 0, 0, 0, 0, ntQ);
        alpha_ln_mod<<<MQ, 256>>>(qbuf, q16, q2, alf, modL, 2*D_);

        // ---- MLP ----
        gemm_mma<1,2><<<pgrid(ntFc1), 256, GEMM_SMEM>>>(q16, wth + wb + OFF_FC1, f1b, nullptr, h16, MQ, HID, D_, HID, 0, 0, 0, 0, ntFc1);
        gemm_mma<0,0><<<pgrid(ntQ), 256, GEMM_SMEM>>>(h16, wth + wb + OFF_FC2, f2b, po, nullptr, MQ, D_, HID, D_, 0, 0, 0, 0, ntQ);
        ln_mod_resid<<<MQ, 256>>>(qbuf, q16, nullptr, po, modL, 4*D_);
    }

    head_kernel<<<MQ, 256>>>(qbuf, head_w, head_b, out);
}